// round 11
// baseline (speedup 1.0000x reference)
#include <cuda_runtime.h>
#include <cuda_bf16.h>
#include <cstdint>

// ---------------- problem constants ----------------
#define BDIM   16
#define CH     512
#define NTOK   1024
#define NT     (BDIM*NTOK)
#define NHEADS 8
#define HDIM   64
#define FFN    2048
#define EPSV   1e-6f

// ---------------- scratch ----------------
__device__ float g_ada [BDIM*6*CH];
__device__ float g_h   [NT*CH];
__device__ float g_stats[BDIM*32*2];
__device__ float g_b12p[2*FFN];
__device__ __nv_bfloat16 g_hnb [NT*CH];
__device__ __nv_bfloat16 g_qkvb[NT*3*CH];
__device__ __nv_bfloat16 g_qkb [NT*2*CH];
__device__ __nv_bfloat16 g_vtb [BDIM*NHEADS*HDIM*NTOK];
__device__ __nv_bfloat16 g_attb[NT*CH];
__device__ __nv_bfloat16 g_gateb[NT*FFN];
__device__ __nv_bfloat16 g_wqkv [3*CH*CH];
__device__ __nv_bfloat16 g_wproj[CH*CH];
__device__ __nv_bfloat16 g_w12c [2*FFN*CH];
__device__ __nv_bfloat16 g_woc  [CH*FFN];

// ---------------- helpers ----------------
__device__ __forceinline__ uint32_t pack2bf(float lo, float hi) {
    uint32_t r;
    asm("cvt.rn.bf16x2.f32 %0, %1, %2;" : "=r"(r) : "f"(hi), "f"(lo));
    return r;
}
__device__ __forceinline__ void cpa16(void* s, const void* g) {
    uint32_t sa = (uint32_t)__cvta_generic_to_shared(s);
    asm volatile("cp.async.cg.shared.global [%0], [%1], 16;\n" :: "r"(sa), "l"(g));
}
__device__ __forceinline__ void ldm4(uint32_t addr, uint32_t& r0, uint32_t& r1,
                                     uint32_t& r2, uint32_t& r3) {
    asm volatile("ldmatrix.sync.aligned.m8n8.x4.shared.b16 {%0,%1,%2,%3}, [%4];"
                 : "=r"(r0), "=r"(r1), "=r"(r2), "=r"(r3) : "r"(addr));
}
#define MMA_BF16(d, a, b) \
    asm volatile("mma.sync.aligned.m16n8k16.row.col.f32.bf16.bf16.f32 " \
                 "{%0,%1,%2,%3}, {%4,%5,%6,%7}, {%8,%9}, {%0,%1,%2,%3};" \
                 : "+f"(d[0]), "+f"(d[1]), "+f"(d[2]), "+f"(d[3]) \
                 : "r"(a[0]), "r"(a[1]), "r"(a[2]), "r"(a[3]), "r"(b[0]), "r"(b[1]))

// ---------------- merged weight conversion ----------------
__device__ __forceinline__ void cvt4(const float* __restrict__ s,
                                     __nv_bfloat16* __restrict__ d, int i) {
    float4 v = *(const float4*)(s + i);
    *(uint32_t*)(d + i)     = pack2bf(v.x, v.y);
    *(uint32_t*)(d + i + 2) = pack2bf(v.z, v.w);
}
__global__ void k_cvtall(const float* __restrict__ qkv_w, const float* __restrict__ proj_w,
                         const float* __restrict__ w_out, const float* __restrict__ w12,
                         const float* __restrict__ b12) {
    const int gi = blockIdx.x * blockDim.x + threadIdx.x;
    if (gi < 196608) {
        cvt4(qkv_w, g_wqkv, gi * 4);
    } else if (gi < 262144) {
        cvt4(proj_w, g_wproj, (gi - 196608) * 4);
    } else if (gi < 524288) {
        cvt4(w_out, g_woc, (gi - 262144) * 4);
    } else if (gi < 1048576) {
        const int i = (gi - 524288) * 4;
        const int r = i >> 9;
        const int k = i & (CH - 1);
        const int sr = (r & 1) ? (FFN + (r >> 1)) : (r >> 1);
        float4 v = *(const float4*)(w12 + (size_t)sr*CH + k);
        *(uint32_t*)(g_w12c + i)     = pack2bf(v.x, v.y);
        *(uint32_t*)(g_w12c + i + 2) = pack2bf(v.z, v.w);
    } else if (gi < 1048576 + FFN) {
        const int j = gi - 1048576;
        g_b12p[2*j]   = b12[j];
        g_b12p[2*j+1] = b12[FFN + j];
    }
}

// ---------------- merged adaLN + GroupNorm stats (one launch) ----------------
__global__ __launch_bounds__(256) void k_adagn(
    const float* __restrict__ temb, const float* __restrict__ ada_w,
    const float* __restrict__ ada_b, const float* __restrict__ x) {
    const int blk = blockIdx.x;
    __shared__ float sh[CH];
    if (blk < 192) {
        const int b = blk / 12;
        for (int i = threadIdx.x; i < CH; i += 256) {
            float v = temb[b*CH + i];
            sh[i] = v / (1.f + __expf(-v));
        }
        __syncthreads();
        const int n = (blk % 12) * 256 + threadIdx.x;
        const float* wr = ada_w + (size_t)n * CH;
        float acc = 0.f;
        #pragma unroll 8
        for (int k = 0; k < CH; k++) acc += wr[k] * sh[k];
        g_ada[b*6*CH + n] = acc + ada_b[n];
    } else {
        const int bg = blk - 192;
        const float* p = x + (size_t)bg * 16 * NTOK;
        float s = 0.f, s2 = 0.f;
        for (int i = threadIdx.x; i < 16*NTOK; i += 256) {
            float v = p[i]; s += v; s2 += v*v;
        }
        #pragma unroll
        for (int o = 16; o; o >>= 1) {
            s  += __shfl_xor_sync(0xffffffffu, s,  o);
            s2 += __shfl_xor_sync(0xffffffffu, s2, o);
        }
        const int w = threadIdx.x >> 5, l = threadIdx.x & 31;
        if (l == 0) { sh[w] = s; sh[32 + w] = s2; }
        __syncthreads();
        if (threadIdx.x < 32) {
            s  = (threadIdx.x < 8) ? sh[threadIdx.x]      : 0.f;
            s2 = (threadIdx.x < 8) ? sh[32 + threadIdx.x] : 0.f;
            #pragma unroll
            for (int o = 4; o; o >>= 1) {
                s  += __shfl_xor_sync(0xffffffffu, s,  o);
                s2 += __shfl_xor_sync(0xffffffffu, s2, o);
            }
            if (threadIdx.x == 0) {
                const float inv = 1.f / (16.f * NTOK);
                float mu  = s * inv;
                float var = s2 * inv - mu * mu;
                g_stats[bg*2]     = mu;
                g_stats[bg*2 + 1] = rsqrtf(var + EPSV);
            }
        }
    }
}

// ---------------- fused GroupNorm-apply + transpose + RMSNorm(n1) + mod ----------------
// one block = 16 tokens, 256 threads
#define HSTR 513
__global__ __launch_bounds__(256) void k_gnrms(
    const float* __restrict__ x, const float* __restrict__ gw, const float* __restrict__ gb,
    const float* __restrict__ n1w) {
    extern __shared__ float hb[];            // 16*HSTR + 16
    float* rms = hb + 16*HSTR;
    const int b  = blockIdx.y;
    const int n0 = blockIdx.x * 16;
    const int t  = threadIdx.x;
    #pragma unroll 8
    for (int i = 0; i < 32; i++) {
        const int lin = t + i*256;
        const int c  = lin >> 4;
        const int nl = lin & 15;
        const float mu = g_stats[(b*32 + (c >> 4))*2];
        const float rs = g_stats[(b*32 + (c >> 4))*2 + 1];
        const float v  = x[((size_t)b*CH + c)*NTOK + n0 + nl];
        hb[nl*HSTR + c] = (v - mu) * rs * gw[c] + gb[c];
    }
    __syncthreads();
    {
        const int tok = t >> 4, l16 = t & 15;
        float ss = 0.f;
        #pragma unroll 8
        for (int i = 0; i < 32; i++) {
            const float v = hb[tok*HSTR + l16 + i*16];
            ss += v*v;
        }
        #pragma unroll
        for (int o = 1; o <= 8; o <<= 1) ss += __shfl_xor_sync(0xffffffffu, ss, o);
        if (l16 == 0) rms[tok] = rsqrtf(ss / (float)CH + EPSV);
    }
    __syncthreads();
    const int rowb = b*NTOK + n0;
    const float* shf = g_ada + b*6*CH;
    const float* scl = g_ada + b*6*CH + CH;
    #pragma unroll 4
    for (int i = 0; i < 16; i++) {
        const int idx = (t + i*256) * 2;
        const int tk = idx >> 9, c = idx & 511;
        const float h0 = hb[tk*HSTR + c], h1 = hb[tk*HSTR + c + 1];
        const float r = rms[tk];
        *(float2*)(g_h + (size_t)(rowb + tk)*CH + c) = make_float2(h0, h1);
        const float o0 = h0 * r * n1w[c]   * (1.f + scl[c])   + shf[c];
        const float o1 = h1 * r * n1w[c+1] * (1.f + scl[c+1]) + shf[c+1];
        *(uint32_t*)(g_hnb + (size_t)(rowb + tk)*CH + c) = pack2bf(o0, o1);
    }
}

// ---------------- RMSNorm + modulation -> bf16 (n2 path) ----------------
__global__ void k_rmsmod(const float* __restrict__ w, int shift_ch, int scale_ch) {
    const int row = blockIdx.x;
    const int b = row >> 10;
    const float* hp = g_h + (size_t)row * CH;
    const int t = threadIdx.x;
    float4 v = *(const float4*)(hp + t*4);
    float ss = v.x*v.x + v.y*v.y + v.z*v.z + v.w*v.w;
    #pragma unroll
    for (int o = 16; o; o >>= 1) ss += __shfl_xor_sync(0xffffffffu, ss, o);
    __shared__ float sh[4];
    if ((t & 31) == 0) sh[t >> 5] = ss;
    __syncthreads();
    ss = sh[0] + sh[1] + sh[2] + sh[3];
    const float r = rsqrtf(ss / (float)CH + EPSV);
    const float* shf = g_ada + b*6*CH + shift_ch*CH;
    const float* scl = g_ada + b*6*CH + scale_ch*CH;
    const int c = t*4;
    float o0 = v.x * r * w[c+0] * (1.f + scl[c+0]) + shf[c+0];
    float o1 = v.y * r * w[c+1] * (1.f + scl[c+1]) + shf[c+1];
    float o2 = v.z * r * w[c+2] * (1.f + scl[c+2]) + shf[c+2];
    float o3 = v.w * r * w[c+3] * (1.f + scl[c+3]) + shf[c+3];
    uint32_t* dp = (uint32_t*)(g_hnb + (size_t)row*CH + c);
    dp[0] = pack2bf(o0, o1);
    dp[1] = pack2bf(o2, o3);
}

// ---------------- BF16 GEMM, ldmatrix, 4-stage cp.async ----------------
// modes: 1 = bf16 store; 2 = g_h += gate*(acc+bias); 3 = fused swiglu;
//        4 = final: out = x + (g_h + gate*(acc+bias))^T
#define WSTR 20
__global__ __launch_bounds__(256, 2) void k_gemm(
    const __nv_bfloat16* __restrict__ A, const __nv_bfloat16* __restrict__ W,
    const float* __restrict__ bias, float* __restrict__ Cf, uint32_t* __restrict__ Cb,
    __nv_bfloat16* __restrict__ Gb, const float* __restrict__ ada,
    const float* __restrict__ Xin, float* __restrict__ Oout,
    int gch, int mode, int M, int N, int K)
{
    extern __shared__ uint32_t sm[];
    const int tid  = threadIdx.x;
    const int lane = tid & 31;
    const int warp = tid >> 5;
    const int gid  = lane >> 2;
    const int tig  = lane & 3;
    const int row0 = (warp & 3) * 32;
    const int col0 = (warp >> 2) * 64;
    const int bm = blockIdx.y * 128, bn = blockIdx.x * 128;
    const int KT = K >> 5;
    const int lr   = lane & 7;
    const int sel8 = (lane >> 3) & 1;
    const int sel4 = (lane >> 4) & 1;

    const uint32_t sbase = (uint32_t)__cvta_generic_to_shared(sm);
    const uint32_t aoff  = ((row0 + sel8*8 + lr)*WSTR + sel4*4) * 4;
    const uint32_t boff  = ((col0 + sel8*8 + lr)*WSTR + sel4*4) * 4 + 2560*4;

    auto load_body = [&](int kt, int s) {
        uint32_t* As = sm + s * 5120;
        uint32_t* Ws = As + 2560;
        const int k0 = kt << 5;
        #pragma unroll
        for (int i = 0; i < 2; i++) {
            const int lin = tid + i*256;
            const int r = lin >> 2, c4 = lin & 3;
            cpa16(As + r*WSTR + c4*4, A + (size_t)(bm + r)*K + k0 + c4*8);
            cpa16(Ws + r*WSTR + c4*4, W + (size_t)(bn + r)*K + k0 + c4*8);
        }
    };

    load_body(0, 0);
    asm volatile("cp.async.commit_group;\n");
    load_body(1, 1);
    asm volatile("cp.async.commit_group;\n");
    load_body(2, 2);
    asm volatile("cp.async.commit_group;\n");

    float acc[2][8][4];
    #pragma unroll
    for (int i = 0; i < 2; i++)
        #pragma unroll
        for (int j = 0; j < 8; j++)
            #pragma unroll
            for (int c = 0; c < 4; c++) acc[i][j][c] = 0.f;

    for (int kt = 0; kt < KT; kt++) {
        asm volatile("cp.async.wait_group 2;\n");
        __syncthreads();
        if (kt + 3 < KT) load_body(kt + 3, (kt + 3) & 3);
        asm volatile("cp.async.commit_group;\n");

        const uint32_t stb = sbase + (uint32_t)((kt & 3) * 5120 * 4);
        #pragma unroll
        for (int kk = 0; kk < 2; kk++) {
            const uint32_t kb = kk * 32;
            uint32_t af[2][4], bf[8][2];
            const uint32_t aa = stb + aoff + kb;
            ldm4(aa,             af[0][0], af[0][1], af[0][2], af[0][3]);
            ldm4(aa + 16*WSTR*4, af[1][0], af[1][1], af[1][2], af[1][3]);
            const uint32_t bb = stb + boff + kb;
            #pragma unroll
            for (int nt2 = 0; nt2 < 4; nt2++) {
                ldm4(bb + nt2*16*WSTR*4,
                     bf[2*nt2][0], bf[2*nt2+1][0], bf[2*nt2][1], bf[2*nt2+1][1]);
            }
            #pragma unroll
            for (int mt = 0; mt < 2; mt++)
                #pragma unroll
                for (int nt = 0; nt < 8; nt++)
                    MMA_BF16(acc[mt][nt], af[mt], bf[nt]);
        }
    }

    if (mode == 4) {
        asm volatile("cp.async.wait_group 0;\n");
        __syncthreads();
        float* hs = (float*)sm;               // 128 x 132
        #pragma unroll
        for (int mt = 0; mt < 2; mt++) {
            const int rl = row0 + mt*16 + gid;
            const int row = bm + rl;
            const int b = row >> 10;
            const float* gp = ada + b*6*CH + gch*CH;
            #pragma unroll
            for (int nt = 0; nt < 8; nt++) {
                const int cl = col0 + nt*8 + tig*2;
                const int col = bn + cl;
                const float b0 = bias[col], b1 = bias[col+1];
                float2 h0 = *(float2*)(Cf + (size_t)row*N + col);
                float2 h1 = *(float2*)(Cf + (size_t)(row+8)*N + col);
                hs[rl*132 + cl]       = h0.x + gp[col]  *(acc[mt][nt][0] + b0);
                hs[rl*132 + cl+1]     = h0.y + gp[col+1]*(acc[mt][nt][1] + b1);
                hs[(rl+8)*132 + cl]   = h1.x + gp[col]  *(acc[mt][nt][2] + b0);
                hs[(rl+8)*132 + cl+1] = h1.y + gp[col+1]*(acc[mt][nt][3] + b1);
            }
        }
        __syncthreads();
        const int b = bm >> 10;
        const int nbase = bm & 1023;
        #pragma unroll
        for (int i = 0; i < 16; i++) {
            const int lin = tid + i*256;
            const int cr = lin >> 5, g = lin & 31;
            const size_t oidx = ((size_t)b*CH + bn + cr)*NTOK + nbase + g*4;
            float4 xs = *(const float4*)(Xin + oidx);
            xs.x += hs[(g*4+0)*132 + cr];
            xs.y += hs[(g*4+1)*132 + cr];
            xs.z += hs[(g*4+2)*132 + cr];
            xs.w += hs[(g*4+3)*132 + cr];
            *(float4*)(Oout + oidx) = xs;
        }
        return;
    }

    #pragma unroll
    for (int mt = 0; mt < 2; mt++) {
        const int row = bm + row0 + mt*16 + gid;
        const int b   = row >> 10;
        const float* gp = ada + b*6*CH + gch*CH;
        #pragma unroll
        for (int nt = 0; nt < 8; nt++) {
            const int col = bn + col0 + nt*8 + tig*2;
            const float b0 = bias[col], b1 = bias[col+1];
            float v00 = acc[mt][nt][0] + b0, v01 = acc[mt][nt][1] + b1;
            float v10 = acc[mt][nt][2] + b0, v11 = acc[mt][nt][3] + b1;
            if (mode == 1) {
                Cb[((size_t)row*N + col) >> 1]     = pack2bf(v00, v01);
                Cb[((size_t)(row+8)*N + col) >> 1] = pack2bf(v10, v11);
            } else if (mode == 2) {
                const float gg0 = gp[col], gg1 = gp[col+1];
                float2 h0 = *(float2*)(Cf + (size_t)row*N + col);
                float2 h1 = *(float2*)(Cf + (size_t)(row+8)*N + col);
                h0.x += gg0*v00; h0.y += gg1*v01;
                h1.x += gg0*v10; h1.y += gg1*v11;
                *(float2*)(Cf + (size_t)row*N + col)     = h0;
                *(float2*)(Cf + (size_t)(row+8)*N + col) = h1;
            } else {
                const int j = col >> 1;
                const float s0 = (v00 / (1.f + __expf(-v00))) * v01;
                const float s1 = (v10 / (1.f + __expf(-v10))) * v11;
                Gb[(size_t)row*(N>>1) + j]     = __float2bfloat16(s0);
                Gb[(size_t)(row+8)*(N>>1) + j] = __float2bfloat16(s1);
            }
        }
    }
}

// ---------------- merged q/k RMSNorm+RoPE  +  V transpose (one launch) ----------------
// rope: blocks 0..32767 (1 warp per (tok,head) = 131072 warps); vtrans: blocks 32768..34815
#define VSTR 72
__global__ __launch_bounds__(128) void k_qkv_post(
    const float* __restrict__ qn_w, const float* __restrict__ kn_w) {
    if (blockIdx.x < 32768) {
        // --- q/k rmsnorm + rope ---
        const int gw   = (blockIdx.x * 128 + threadIdx.x) >> 5;  // 0..131071
        const int lane = threadIdx.x & 31;
        const int head = gw & 7;
        const int tok  = gw >> 3;                                 // 0..16383
        const int n = tok & 1023;
        const int rrow = n >> 5, rcol = n & 31;
        const uint32_t* qkvw = (const uint32_t*)g_qkvb;
        const size_t base = (size_t)tok * 768;
        float2 qv = __bfloat1622float2(*(const __nv_bfloat162*)&qkvw[base + head*32 + lane]);
        float2 kv = __bfloat1622float2(*(const __nv_bfloat162*)&qkvw[base + 256 + head*32 + lane]);
        float q0 = qv.x, q1 = qv.y, k0 = kv.x, k1 = kv.y;
        const int j = lane * 2;
        float sq = q0*q0 + q1*q1, sk = k0*k0 + k1*k1;
        #pragma unroll
        for (int o = 16; o; o >>= 1) {
            sq += __shfl_xor_sync(0xffffffffu, sq, o);
            sk += __shfl_xor_sync(0xffffffffu, sk, o);
        }
        const float rq = rsqrtf(sq / 64.f + EPSV);
        const float rk = rsqrtf(sk / 64.f + EPSV);
        q0 *= rq * qn_w[j];  q1 *= rq * qn_w[j+1];
        k0 *= rk * kn_w[j];  k1 *= rk * kn_w[j+1];
        const int half = (j >= 32);
        const int idx  = (half ? (j - 32) : j) >> 1;
        const float freq = exp2f(-(float)idx * (13.287712379549449f / 16.f));
        const float f = (half ? (float)rcol : (float)rrow) * freq;
        const float cf = cosf(f), sf = sinf(f);
        const float qa = q0*cf - q1*sf, qb = q1*cf + q0*sf;
        const float ka = k0*cf - k1*sf, kb = k1*cf + k0*sf;
        const float qs = 0.125f;
        uint32_t* qkw = (uint32_t*)g_qkb;
        qkw[(size_t)tok*512 + head*32 + lane]       = pack2bf(qa*qs, qb*qs);
        qkw[(size_t)tok*512 + 256 + head*32 + lane] = pack2bf(ka, kb);
    } else {
        // --- V transpose, 64-token x 64-d tile ---
        __shared__ __nv_bfloat16 vt[64*VSTR];
        const int vb = blockIdx.x - 32768;   // 0..2047
        const int bh = vb >> 4;              // b*8 + head
        const int b = bh >> 3, hh = bh & 7;
        const int t0 = (vb & 15) * 64;
        const int t = threadIdx.x;
        const __nv_bfloat16* src = g_qkvb + (size_t)(b*NTOK + t0) * 1536 + 1024 + hh*64;
        #pragma unroll
        for (int i = 0; i < 4; i++) {
            const int lin = t + i*128;       // 512 uint4
            const int r = lin >> 3, c8 = lin & 7;
            *(uint4*)(vt + r*VSTR + c8*8) = *(const uint4*)(src + (size_t)r*1536 + c8*8);
        }
        __syncthreads();
        __nv_bfloat16* dst = g_vtb + (size_t)bh * 64 * NTOK + t0;
        #pragma unroll
        for (int i = 0; i < 4; i++) {
            const int lin = t + i*128;       // 512
            const int d = lin >> 3, t8 = (lin & 7) * 8;
            uint16_t v[8];
            #pragma unroll
            for (int jx = 0; jx < 8; jx++)
                v[jx] = *(const uint16_t*)(vt + (t8 + jx)*VSTR + d);
            uint4 o;
            o.x = (uint32_t)v[0] | ((uint32_t)v[1] << 16);
            o.y = (uint32_t)v[2] | ((uint32_t)v[3] << 16);
            o.z = (uint32_t)v[4] | ((uint32_t)v[5] << 16);
            o.w = (uint32_t)v[6] | ((uint32_t)v[7] << 16);
            *(uint4*)(dst + (size_t)d*NTOK + t8) = o;
        }
    }
}

// ---------------- flash attention: 3-stage K/V ring, one sync per chunk ----------------
#define QSTR 36
__global__ __launch_bounds__(256) void k_attn_mma() {
    extern __shared__ uint32_t smw[];        // 3 stages x 128 rows x QSTR
    const int bh = blockIdx.x;
    const int b = bh >> 3, hh = bh & 7;
    const int q0 = blockIdx.y * 128;
    const int tid = threadIdx.x, lane = tid & 31, warp = tid >> 5;
    const int lr = lane & 7, sel8 = (lane >> 3) & 1, sel4 = (lane >> 4) & 1;
    const int gid = lane >> 2, tig = lane & 3;
    const __nv_bfloat16* qk = g_qkb + (size_t)b * NTOK * 1024;
    const __nv_bfloat16* vt = g_vtb + (size_t)bh * 64 * NTOK;

    const uint32_t sbase = (uint32_t)__cvta_generic_to_shared(smw);
    const uint32_t qoff  = ((warp*16 + sel8*8 + lr)*QSTR + sel4*4) * 4;
    const uint32_t kvoff = ((sel8*8 + lr)*QSTR + sel4*4) * 4;

    #pragma unroll
    for (int i = 0; i < 4; i++) {
        const int lin = tid + i*256;
        const int r = lin >> 3, c4 = lin & 7;
        cpa16(smw + r*QSTR + c4*4, qk + (size_t)(q0 + r)*1024 + hh*64 + c4*8);
    }
    asm volatile("cp.async.commit_group;\n");
    asm volatile("cp.async.wait_group 0;\n");
    __syncthreads();
    uint32_t qf[4][4];
    #pragma unroll
    for (int kk = 0; kk < 4; kk++)
        ldm4(sbase + qoff + kk*32, qf[kk][0], qf[kk][1], qf[kk][2], qf[kk][3]);
    __syncthreads();

    auto load_kv = [&](int kc, int s) {
        uint32_t* Ks = smw + s*128*QSTR;
        uint32_t* Vs = Ks + 64*QSTR;
        #pragma unroll
        for (int i = 0; i < 2; i++) {
            const int lin = tid + i*256;
            const int r = lin >> 3, c4 = lin & 7;
            cpa16(Ks + r*QSTR + c4*4, qk + (size_t)(kc + r)*1024 + 512 + hh*64 + c4*8);
            cpa16(Vs + r*QSTR + c4*4, vt + (size_t)r*NTOK + kc + c4*8);
        }
    };

    float l0 = 0.f, l1 = 0.f;
    float oacc[8][4];
    #pragma unroll
    for (int nt = 0; nt < 8; nt++)
        #pragma unroll
        for (int c = 0; c < 4; c++) oacc[nt][c] = 0.f;

    load_kv(0, 0);
    asm volatile("cp.async.commit_group;\n");
    load_kv(64, 1);
    asm volatile("cp.async.commit_group;\n");

    int stg = 0;
    for (int it = 0; it < NTOK/64; it++) {
        if (it + 2 < NTOK/64) {
            asm volatile("cp.async.wait_group 1;\n");
        } else {
            asm volatile("cp.async.wait_group 0;\n");
        }
        __syncthreads();
        if (it + 2 < NTOK/64) {
            int ns = stg + 2; if (ns >= 3) ns -= 3;
            load_kv((it+2)*64, ns);
            asm volatile("cp.async.commit_group;\n");
        }
        const uint32_t kbase = sbase + (uint32_t)(stg*128*QSTR*4);
        const uint32_t vbase = kbase + 64*QSTR*4;

        float sacc[8][4];
        #pragma unroll
        for (int nt = 0; nt < 8; nt++)
            #pragma unroll
            for (int c = 0; c < 4; c++) sacc[nt][c] = 0.f;
        #pragma unroll
        for (int kk = 0; kk < 4; kk++) {
            uint32_t bf[8][2];
            const uint32_t kb = kbase + kvoff + kk*32;
            #pragma unroll
            for (int nt2 = 0; nt2 < 4; nt2++)
                ldm4(kb + nt2*16*QSTR*4,
                     bf[2*nt2][0], bf[2*nt2+1][0], bf[2*nt2][1], bf[2*nt2+1][1]);
            #pragma unroll
            for (int nt = 0; nt < 8; nt++)
                MMA_BF16(sacc[nt], qf[kk], bf[nt]);
        }

        uint32_t pa[8], pb[8];
        #pragma unroll
        for (int nt = 0; nt < 8; nt++) {
            const float p00 = __expf(sacc[nt][0] - 8.f);
            const float p01 = __expf(sacc[nt][1] - 8.f);
            const float p10 = __expf(sacc[nt][2] - 8.f);
            const float p11 = __expf(sacc[nt][3] - 8.f);
            l0 += p00 + p01;  l1 += p10 + p11;
            pa[nt] = pack2bf(p00, p01);
            pb[nt] = pack2bf(p10, p11);
        }

        #pragma unroll
        for (int kk = 0; kk < 4; kk++) {
            uint32_t af[4] = { pa[2*kk], pb[2*kk], pa[2*kk+1], pb[2*kk+1] };
            uint32_t bf[8][2];
            const uint32_t vb = vbase + kvoff + kk*32;
            #pragma unroll
            for (int nt2 = 0; nt2 < 4; nt2++)
                ldm4(vb + nt2*16*QSTR*4,
                     bf[2*nt2][0], bf[2*nt2+1][0], bf[2*nt2][1], bf[2*nt2+1][1]);
            #pragma unroll
            for (int nt = 0; nt < 8; nt++)
                MMA_BF16(oacc[nt], af, bf[nt]);
        }
        if (++stg == 3) stg = 0;
    }

    #pragma unroll
    for (int o = 1; o <= 2; o <<= 1) {
        l0 += __shfl_xor_sync(0xffffffffu, l0, o);
        l1 += __shfl_xor_sync(0xffffffffu, l1, o);
    }
    const float inv0 = 1.f / l0, inv1 = 1.f / l1;
    uint32_t* ow = (uint32_t*)g_attb;
    const size_t row = (size_t)b*NTOK + q0 + warp*16 + gid;
    #pragma unroll
    for (int nt = 0; nt < 8; nt++) {
        const int cw = hh*32 + nt*4 + tig;
        ow[row*256 + cw]     = pack2bf(oacc[nt][0]*inv0, oacc[nt][1]*inv0);
        ow[(row+8)*256 + cw] = pack2bf(oacc[nt][2]*inv1, oacc[nt][3]*inv1);
    }
}

// ---------------- launcher ----------------
extern "C" void kernel_launch(void* const* d_in, const int* in_sizes, int n_in,
                              void* d_out, int out_size) {
    const float* x      = (const float*)d_in[0];
    const float* temb   = (const float*)d_in[1];
    const float* gn_w   = (const float*)d_in[2];
    const float* gn_b   = (const float*)d_in[3];
    const float* ada_w  = (const float*)d_in[4];
    const float* ada_b  = (const float*)d_in[5];
    const float* n1_w   = (const float*)d_in[6];
    const float* n2_w   = (const float*)d_in[7];
    const float* qkv_w  = (const float*)d_in[8];
    const float* qkv_b  = (const float*)d_in[9];
    const float* qn_w   = (const float*)d_in[10];
    const float* kn_w   = (const float*)d_in[11];
    const float* proj_w = (const float*)d_in[12];
    const float* proj_b = (const float*)d_in[13];
    const float* w12    = (const float*)d_in[14];
    const float* b12    = (const float*)d_in[15];
    const float* w_out  = (const float*)d_in[16];
    const float* b_out  = (const float*)d_in[17];
    float* out = (float*)d_out;

    float *p_h, *p_ada, *p_b12p;
    __nv_bfloat16 *p_hnb, *p_qkvb, *p_attb, *p_gateb;
    __nv_bfloat16 *p_wqkv, *p_wproj, *p_w12c, *p_woc;
    cudaGetSymbolAddress((void**)&p_h,     g_h);
    cudaGetSymbolAddress((void**)&p_ada,   g_ada);
    cudaGetSymbolAddress((void**)&p_b12p,  g_b12p);
    cudaGetSymbolAddress((void**)&p_hnb,   g_hnb);
    cudaGetSymbolAddress((void**)&p_qkvb,  g_qkvb);
    cudaGetSymbolAddress((void**)&p_attb,  g_attb);
    cudaGetSymbolAddress((void**)&p_gateb, g_gateb);
    cudaGetSymbolAddress((void**)&p_wqkv,  g_wqkv);
    cudaGetSymbolAddress((void**)&p_wproj, g_wproj);
    cudaGetSymbolAddress((void**)&p_w12c,  g_w12c);
    cudaGetSymbolAddress((void**)&p_woc,   g_woc);

    const int gemm_smem  = 4*5120*4;          // 81920 B
    const int attn_smem  = 3*128*QSTR*4;      // 55296 B
    const int gnrms_smem = (16*HSTR + 16)*4;  // 32896 B
    cudaFuncSetAttribute(k_gemm,     cudaFuncAttributeMaxDynamicSharedMemorySize, gemm_smem);
    cudaFuncSetAttribute(k_attn_mma, cudaFuncAttributeMaxDynamicSharedMemorySize, attn_smem);
    cudaFuncSetAttribute(k_gnrms,    cudaFuncAttributeMaxDynamicSharedMemorySize, gnrms_smem);

    k_cvtall <<<(1048576 + FFN + 255)/256, 256>>>(qkv_w, proj_w, w_out, w12, b12);

    // adaLN + GroupNorm stats (merged) + fused gn-apply/rmsnorm/mod
    k_adagn  <<<192 + BDIM*32, 256>>>(temb, ada_w, ada_b, x);
    k_gnrms  <<<dim3(NTOK/16, BDIM), 256, gnrms_smem>>>(x, gn_w, gn_b, n1_w);

    // attention branch
    k_gemm   <<<dim3((3*CH)/128, NT/128), 256, gemm_smem>>>(
        p_hnb, p_wqkv, qkv_b, nullptr, (uint32_t*)p_qkvb, nullptr, p_ada,
        nullptr, nullptr, 0, 1, NT, 3*CH, CH);
    k_qkv_post<<<32768 + 2048, 128>>>(qn_w, kn_w);
    k_attn_mma<<<dim3(BDIM*NHEADS, NTOK/128), 256, attn_smem>>>();
    k_gemm   <<<dim3(CH/128, NT/128), 256, gemm_smem>>>(
        p_attb, p_wproj, proj_b, p_h, nullptr, nullptr, p_ada,
        nullptr, nullptr, 2, 2, NT, CH, CH);

    // FFN branch
    k_rmsmod <<<NT, 128>>>(n2_w, 3, 4);
    k_gemm   <<<dim3((2*FFN)/128, NT/128), 256, gemm_smem>>>(
        p_hnb, p_w12c, p_b12p, nullptr, nullptr, p_gateb, p_ada,
        nullptr, nullptr, 0, 3, NT, 2*FFN, CH);
    k_gemm   <<<dim3(CH/128, NT/128), 256, gemm_smem>>>(
        p_gateb, p_woc, b_out, p_h, nullptr, nullptr, p_ada,
        x, out, 5, 4, NT, CH, FFN);
}

// round 12
// speedup vs baseline: 1.0261x; 1.0261x over previous
#include <cuda_runtime.h>
#include <cuda_bf16.h>
#include <cstdint>

// ---------------- problem constants ----------------
#define BDIM   16
#define CH     512
#define NTOK   1024
#define NT     (BDIM*NTOK)
#define NHEADS 8
#define HDIM   64
#define FFN    2048
#define EPSV   1e-6f

// ---------------- scratch ----------------
__device__ float g_ada [BDIM*6*CH];
__device__ float g_h   [NT*CH];
__device__ float g_stats[BDIM*32*2];
__device__ float g_b12p[2*FFN];
__device__ __nv_bfloat16 g_hnb [NT*CH];
__device__ __nv_bfloat16 g_qkvb[NT*3*CH];
__device__ __nv_bfloat16 g_qkb [NT*2*CH];
__device__ __nv_bfloat16 g_vtb [BDIM*NHEADS*HDIM*NTOK];
__device__ __nv_bfloat16 g_attb[NT*CH];
__device__ __nv_bfloat16 g_gateb[NT*FFN];
__device__ __nv_bfloat16 g_wqkv [3*CH*CH];
__device__ __nv_bfloat16 g_wproj[CH*CH];
__device__ __nv_bfloat16 g_w12c [2*FFN*CH];
__device__ __nv_bfloat16 g_woc  [CH*FFN];

// ---------------- helpers ----------------
__device__ __forceinline__ uint32_t pack2bf(float lo, float hi) {
    uint32_t r;
    asm("cvt.rn.bf16x2.f32 %0, %1, %2;" : "=r"(r) : "f"(hi), "f"(lo));
    return r;
}
__device__ __forceinline__ void cpa16(void* s, const void* g) {
    uint32_t sa = (uint32_t)__cvta_generic_to_shared(s);
    asm volatile("cp.async.cg.shared.global [%0], [%1], 16;\n" :: "r"(sa), "l"(g));
}
__device__ __forceinline__ void ldm4(uint32_t addr, uint32_t& r0, uint32_t& r1,
                                     uint32_t& r2, uint32_t& r3) {
    asm volatile("ldmatrix.sync.aligned.m8n8.x4.shared.b16 {%0,%1,%2,%3}, [%4];"
                 : "=r"(r0), "=r"(r1), "=r"(r2), "=r"(r3) : "r"(addr));
}
#define MMA_BF16(d, a, b) \
    asm volatile("mma.sync.aligned.m16n8k16.row.col.f32.bf16.bf16.f32 " \
                 "{%0,%1,%2,%3}, {%4,%5,%6,%7}, {%8,%9}, {%0,%1,%2,%3};" \
                 : "+f"(d[0]), "+f"(d[1]), "+f"(d[2]), "+f"(d[3]) \
                 : "r"(a[0]), "r"(a[1]), "r"(a[2]), "r"(a[3]), "r"(b[0]), "r"(b[1]))

// ---------------- merged weight conversion ----------------
__device__ __forceinline__ void cvt4(const float* __restrict__ s,
                                     __nv_bfloat16* __restrict__ d, int i) {
    float4 v = *(const float4*)(s + i);
    *(uint32_t*)(d + i)     = pack2bf(v.x, v.y);
    *(uint32_t*)(d + i + 2) = pack2bf(v.z, v.w);
}
__global__ void k_cvtall(const float* __restrict__ qkv_w, const float* __restrict__ proj_w,
                         const float* __restrict__ w_out, const float* __restrict__ w12,
                         const float* __restrict__ b12) {
    const int gi = blockIdx.x * blockDim.x + threadIdx.x;
    if (gi < 196608) {
        cvt4(qkv_w, g_wqkv, gi * 4);
    } else if (gi < 262144) {
        cvt4(proj_w, g_wproj, (gi - 196608) * 4);
    } else if (gi < 524288) {
        cvt4(w_out, g_woc, (gi - 262144) * 4);
    } else if (gi < 1048576) {
        const int i = (gi - 524288) * 4;
        const int r = i >> 9;
        const int k = i & (CH - 1);
        const int sr = (r & 1) ? (FFN + (r >> 1)) : (r >> 1);
        float4 v = *(const float4*)(w12 + (size_t)sr*CH + k);
        *(uint32_t*)(g_w12c + i)     = pack2bf(v.x, v.y);
        *(uint32_t*)(g_w12c + i + 2) = pack2bf(v.z, v.w);
    } else if (gi < 1048576 + FFN) {
        const int j = gi - 1048576;
        g_b12p[2*j]   = b12[j];
        g_b12p[2*j+1] = b12[FFN + j];
    }
}

// ---------------- merged adaLN + GroupNorm stats ----------------
__global__ __launch_bounds__(256) void k_adagn(
    const float* __restrict__ temb, const float* __restrict__ ada_w,
    const float* __restrict__ ada_b, const float* __restrict__ x) {
    const int blk = blockIdx.x;
    __shared__ float sh[CH];
    if (blk < 192) {
        const int b = blk / 12;
        for (int i = threadIdx.x; i < CH; i += 256) {
            float v = temb[b*CH + i];
            sh[i] = v / (1.f + __expf(-v));
        }
        __syncthreads();
        const int n = (blk % 12) * 256 + threadIdx.x;
        const float* wr = ada_w + (size_t)n * CH;
        float acc = 0.f;
        #pragma unroll 8
        for (int k = 0; k < CH; k++) acc += wr[k] * sh[k];
        g_ada[b*6*CH + n] = acc + ada_b[n];
    } else {
        const int bg = blk - 192;
        const float* p = x + (size_t)bg * 16 * NTOK;
        float s = 0.f, s2 = 0.f;
        for (int i = threadIdx.x; i < 16*NTOK; i += 256) {
            float v = p[i]; s += v; s2 += v*v;
        }
        #pragma unroll
        for (int o = 16; o; o >>= 1) {
            s  += __shfl_xor_sync(0xffffffffu, s,  o);
            s2 += __shfl_xor_sync(0xffffffffu, s2, o);
        }
        const int w = threadIdx.x >> 5, l = threadIdx.x & 31;
        if (l == 0) { sh[w] = s; sh[32 + w] = s2; }
        __syncthreads();
        if (threadIdx.x < 32) {
            s  = (threadIdx.x < 8) ? sh[threadIdx.x]      : 0.f;
            s2 = (threadIdx.x < 8) ? sh[32 + threadIdx.x] : 0.f;
            #pragma unroll
            for (int o = 4; o; o >>= 1) {
                s  += __shfl_xor_sync(0xffffffffu, s,  o);
                s2 += __shfl_xor_sync(0xffffffffu, s2, o);
            }
            if (threadIdx.x == 0) {
                const float inv = 1.f / (16.f * NTOK);
                float mu  = s * inv;
                float var = s2 * inv - mu * mu;
                g_stats[bg*2]     = mu;
                g_stats[bg*2 + 1] = rsqrtf(var + EPSV);
            }
        }
    }
}

// ---------------- fused GroupNorm-apply + transpose + RMSNorm(n1) + mod ----------------
// one block = 32 tokens, 512 threads (R9 measured-best shape)
#define HSTR 513
__global__ __launch_bounds__(512) void k_gnrms(
    const float* __restrict__ x, const float* __restrict__ gw, const float* __restrict__ gb,
    const float* __restrict__ n1w) {
    extern __shared__ float hb[];            // 32*HSTR + 32
    float* rms = hb + 32*HSTR;
    const int b  = blockIdx.y;
    const int n0 = blockIdx.x * 32;
    const int t  = threadIdx.x;
    for (int c0 = 0; c0 < CH; c0 += 64) {
        #pragma unroll
        for (int i = 0; i < 4; i++) {
            const int cl = (t >> 5) + i*16;
            const int nl = t & 31;
            const int c  = c0 + cl;
            const float mu = g_stats[(b*32 + (c >> 4))*2];
            const float rs = g_stats[(b*32 + (c >> 4))*2 + 1];
            const float v  = x[((size_t)b*CH + c)*NTOK + n0 + nl];
            hb[nl*HSTR + c] = (v - mu) * rs * gw[c] + gb[c];
        }
    }
    __syncthreads();
    {
        const int tok = t >> 4, l16 = t & 15;
        float ss = 0.f;
        #pragma unroll 8
        for (int i = 0; i < 32; i++) {
            const float v = hb[tok*HSTR + l16 + i*16];
            ss += v*v;
        }
        #pragma unroll
        for (int o = 1; o <= 8; o <<= 1) ss += __shfl_xor_sync(0xffffffffu, ss, o);
        if (l16 == 0) rms[tok] = rsqrtf(ss / (float)CH + EPSV);
    }
    __syncthreads();
    const int rowb = b*NTOK + n0;
    const float* shf = g_ada + b*6*CH;
    const float* scl = g_ada + b*6*CH + CH;
    #pragma unroll 4
    for (int i = 0; i < 16; i++) {
        const int idx = (t + i*512) * 2;
        const int tk = idx >> 9, c = idx & 511;
        const float h0 = hb[tk*HSTR + c], h1 = hb[tk*HSTR + c + 1];
        const float r = rms[tk];
        *(float2*)(g_h + (size_t)(rowb + tk)*CH + c) = make_float2(h0, h1);
        const float o0 = h0 * r * n1w[c]   * (1.f + scl[c])   + shf[c];
        const float o1 = h1 * r * n1w[c+1] * (1.f + scl[c+1]) + shf[c+1];
        *(uint32_t*)(g_hnb + (size_t)(rowb + tk)*CH + c) = pack2bf(o0, o1);
    }
}

// ---------------- RMSNorm + modulation -> bf16 (n2 path) ----------------
__global__ void k_rmsmod(const float* __restrict__ w, int shift_ch, int scale_ch) {
    const int row = blockIdx.x;
    const int b = row >> 10;
    const float* hp = g_h + (size_t)row * CH;
    const int t = threadIdx.x;
    float4 v = *(const float4*)(hp + t*4);
    float ss = v.x*v.x + v.y*v.y + v.z*v.z + v.w*v.w;
    #pragma unroll
    for (int o = 16; o; o >>= 1) ss += __shfl_xor_sync(0xffffffffu, ss, o);
    __shared__ float sh[4];
    if ((t & 31) == 0) sh[t >> 5] = ss;
    __syncthreads();
    ss = sh[0] + sh[1] + sh[2] + sh[3];
    const float r = rsqrtf(ss / (float)CH + EPSV);
    const float* shf = g_ada + b*6*CH + shift_ch*CH;
    const float* scl = g_ada + b*6*CH + scale_ch*CH;
    const int c = t*4;
    float o0 = v.x * r * w[c+0] * (1.f + scl[c+0]) + shf[c+0];
    float o1 = v.y * r * w[c+1] * (1.f + scl[c+1]) + shf[c+1];
    float o2 = v.z * r * w[c+2] * (1.f + scl[c+2]) + shf[c+2];
    float o3 = v.w * r * w[c+3] * (1.f + scl[c+3]) + shf[c+3];
    uint32_t* dp = (uint32_t*)(g_hnb + (size_t)row*CH + c);
    dp[0] = pack2bf(o0, o1);
    dp[1] = pack2bf(o2, o3);
}

// ---------------- BF16 GEMM: K-chunk 64, 3-stage cp.async, 1 barrier/chunk ----------------
// modes: 1 = bf16 store; 2 = g_h += gate*(acc+bias); 3 = fused swiglu;
//        4 = final: out = x + (g_h + gate*(acc+bias))^T
#define WSTR 36
#define STG_W (128*WSTR*2)        // words per stage (A + B)
__global__ __launch_bounds__(256, 2) void k_gemm(
    const __nv_bfloat16* __restrict__ A, const __nv_bfloat16* __restrict__ W,
    const float* __restrict__ bias, float* __restrict__ Cf, uint32_t* __restrict__ Cb,
    __nv_bfloat16* __restrict__ Gb, const float* __restrict__ ada,
    const float* __restrict__ Xin, float* __restrict__ Oout,
    int gch, int mode, int M, int N, int K)
{
    extern __shared__ uint32_t sm[];      // 3 stages * STG_W words
    const int tid  = threadIdx.x;
    const int lane = tid & 31;
    const int warp = tid >> 5;
    const int gid  = lane >> 2;
    const int tig  = lane & 3;
    const int row0 = (warp & 3) * 32;
    const int col0 = (warp >> 2) * 64;
    const int bm = blockIdx.y * 128, bn = blockIdx.x * 128;
    const int KT = K >> 6;                // 64-K chunks
    const int lr   = lane & 7;
    const int sel8 = (lane >> 3) & 1;
    const int sel4 = (lane >> 4) & 1;

    const uint32_t sbase = (uint32_t)__cvta_generic_to_shared(sm);
    const uint32_t aoff  = ((row0 + sel8*8 + lr)*WSTR + sel4*4) * 4;
    const uint32_t boff  = ((col0 + sel8*8 + lr)*WSTR + sel4*4) * 4 + 128*WSTR*4;

    auto load_body = [&](int kt, int s) {
        uint32_t* As = sm + s * STG_W;
        uint32_t* Ws = As + 128*WSTR;
        const int k0 = kt << 6;
        #pragma unroll
        for (int i = 0; i < 4; i++) {
            const int lin = tid + i*256;              // 0..1023: A rows
            const int r = lin >> 3, c = lin & 7;
            cpa16(As + r*WSTR + c*4, A + (size_t)(bm + r)*K + k0 + c*8);
        }
        #pragma unroll
        for (int i = 0; i < 4; i++) {
            const int lin = tid + i*256;              // 0..1023: B rows
            const int r = lin >> 3, c = lin & 7;
            cpa16(Ws + r*WSTR + c*4, W + (size_t)(bn + r)*K + k0 + c*8);
        }
    };

    load_body(0, 0);
    asm volatile("cp.async.commit_group;\n");
    load_body(1, 1);
    asm volatile("cp.async.commit_group;\n");

    float acc[2][8][4];
    #pragma unroll
    for (int i = 0; i < 2; i++)
        #pragma unroll
        for (int j = 0; j < 8; j++)
            #pragma unroll
            for (int c = 0; c < 4; c++) acc[i][j][c] = 0.f;

    int stg = 0;
    for (int kt = 0; kt < KT; kt++) {
        if (kt + 1 < KT) {
            asm volatile("cp.async.wait_group 1;\n");
        } else {
            asm volatile("cp.async.wait_group 0;\n");
        }
        __syncthreads();                   // single barrier per 64-K chunk
        if (kt + 2 < KT) {
            int ns = stg + 2; if (ns >= 3) ns -= 3;
            load_body(kt + 2, ns);
            asm volatile("cp.async.commit_group;\n");
        }
        const uint32_t stb = sbase + (uint32_t)(stg * STG_W * 4);
        #pragma unroll
        for (int kk = 0; kk < 4; kk++) {
            const uint32_t kb = kk * 32;   // 8 words * 4B
            uint32_t af[2][4], bf[8][2];
            const uint32_t aa = stb + aoff + kb;
            ldm4(aa,             af[0][0], af[0][1], af[0][2], af[0][3]);
            ldm4(aa + 16*WSTR*4, af[1][0], af[1][1], af[1][2], af[1][3]);
            const uint32_t bb = stb + boff + kb;
            #pragma unroll
            for (int nt2 = 0; nt2 < 4; nt2++) {
                ldm4(bb + nt2*16*WSTR*4,
                     bf[2*nt2][0], bf[2*nt2+1][0], bf[2*nt2][1], bf[2*nt2+1][1]);
            }
            #pragma unroll
            for (int mt = 0; mt < 2; mt++)
                #pragma unroll
                for (int nt = 0; nt < 8; nt++)
                    MMA_BF16(acc[mt][nt], af[mt], bf[nt]);
        }
        if (++stg == 3) stg = 0;
    }

    if (mode == 4) {
        asm volatile("cp.async.wait_group 0;\n");
        __syncthreads();
        float* hs = (float*)sm;            // 128 x 132 floats (fits in stage mem)
        #pragma unroll
        for (int mt = 0; mt < 2; mt++) {
            const int rl = row0 + mt*16 + gid;
            const int row = bm + rl;
            const int b = row >> 10;
            const float* gp = ada + b*6*CH + gch*CH;
            #pragma unroll
            for (int nt = 0; nt < 8; nt++) {
                const int cl = col0 + nt*8 + tig*2;
                const int col = bn + cl;
                const float b0 = bias[col], b1 = bias[col+1];
                float2 h0 = *(float2*)(Cf + (size_t)row*N + col);
                float2 h1 = *(float2*)(Cf + (size_t)(row+8)*N + col);
                hs[rl*132 + cl]       = h0.x + gp[col]  *(acc[mt][nt][0] + b0);
                hs[rl*132 + cl+1]     = h0.y + gp[col+1]*(acc[mt][nt][1] + b1);
                hs[(rl+8)*132 + cl]   = h1.x + gp[col]  *(acc[mt][nt][2] + b0);
                hs[(rl+8)*132 + cl+1] = h1.y + gp[col+1]*(acc[mt][nt][3] + b1);
            }
        }
        __syncthreads();
        const int b = bm >> 10;
        const int nbase = bm & 1023;
        #pragma unroll
        for (int i = 0; i < 16; i++) {
            const int lin = tid + i*256;
            const int cr = lin >> 5, g = lin & 31;
            const size_t oidx = ((size_t)b*CH + bn + cr)*NTOK + nbase + g*4;
            float4 xs = *(const float4*)(Xin + oidx);
            xs.x += hs[(g*4+0)*132 + cr];
            xs.y += hs[(g*4+1)*132 + cr];
            xs.z += hs[(g*4+2)*132 + cr];
            xs.w += hs[(g*4+3)*132 + cr];
            *(float4*)(Oout + oidx) = xs;
        }
        return;
    }

    #pragma unroll
    for (int mt = 0; mt < 2; mt++) {
        const int row = bm + row0 + mt*16 + gid;
        const int b   = row >> 10;
        const float* gp = ada + b*6*CH + gch*CH;
        #pragma unroll
        for (int nt = 0; nt < 8; nt++) {
            const int col = bn + col0 + nt*8 + tig*2;
            const float b0 = bias[col], b1 = bias[col+1];
            float v00 = acc[mt][nt][0] + b0, v01 = acc[mt][nt][1] + b1;
            float v10 = acc[mt][nt][2] + b0, v11 = acc[mt][nt][3] + b1;
            if (mode == 1) {
                Cb[((size_t)row*N + col) >> 1]     = pack2bf(v00, v01);
                Cb[((size_t)(row+8)*N + col) >> 1] = pack2bf(v10, v11);
            } else if (mode == 2) {
                const float gg0 = gp[col], gg1 = gp[col+1];
                float2 h0 = *(float2*)(Cf + (size_t)row*N + col);
                float2 h1 = *(float2*)(Cf + (size_t)(row+8)*N + col);
                h0.x += gg0*v00; h0.y += gg1*v01;
                h1.x += gg0*v10; h1.y += gg1*v11;
                *(float2*)(Cf + (size_t)row*N + col)     = h0;
                *(float2*)(Cf + (size_t)(row+8)*N + col) = h1;
            } else {
                const int j = col >> 1;
                const float s0 = (v00 / (1.f + __expf(-v00))) * v01;
                const float s1 = (v10 / (1.f + __expf(-v10))) * v11;
                Gb[(size_t)row*(N>>1) + j]     = __float2bfloat16(s0);
                Gb[(size_t)(row+8)*(N>>1) + j] = __float2bfloat16(s1);
            }
        }
    }
}

// ---------------- q/k RMSNorm + RoPE (bf16 in) -> bf16 ----------------
__global__ void k_qkrope(const float* __restrict__ qn_w, const float* __restrict__ kn_w) {
    const int gw   = (blockIdx.x * blockDim.x + threadIdx.x) >> 5;
    const int lane = threadIdx.x & 31;
    const int head = gw & 7;
    const int tok  = gw >> 3;
    const int n = tok & 1023;
    const int rrow = n >> 5, rcol = n & 31;
    const uint32_t* qkvw = (const uint32_t*)g_qkvb;
    const size_t base = (size_t)tok * 768;
    float2 qv = __bfloat1622float2(*(const __nv_bfloat162*)&qkvw[base + head*32 + lane]);
    float2 kv = __bfloat1622float2(*(const __nv_bfloat162*)&qkvw[base + 256 + head*32 + lane]);
    float q0 = qv.x, q1 = qv.y, k0 = kv.x, k1 = kv.y;
    const int j = lane * 2;
    float sq = q0*q0 + q1*q1, sk = k0*k0 + k1*k1;
    #pragma unroll
    for (int o = 16; o; o >>= 1) {
        sq += __shfl_xor_sync(0xffffffffu, sq, o);
        sk += __shfl_xor_sync(0xffffffffu, sk, o);
    }
    const float rq = rsqrtf(sq / 64.f + EPSV);
    const float rk = rsqrtf(sk / 64.f + EPSV);
    q0 *= rq * qn_w[j];  q1 *= rq * qn_w[j+1];
    k0 *= rk * kn_w[j];  k1 *= rk * kn_w[j+1];
    const int half = (j >= 32);
    const int idx  = (half ? (j - 32) : j) >> 1;
    const float freq = exp2f(-(float)idx * (13.287712379549449f / 16.f));
    const float f = (half ? (float)rcol : (float)rrow) * freq;
    const float cf = cosf(f), sf = sinf(f);
    const float qa = q0*cf - q1*sf, qb = q1*cf + q0*sf;
    const float ka = k0*cf - k1*sf, kb = k1*cf + k0*sf;
    const float qs = 0.125f;
    uint32_t* qkw = (uint32_t*)g_qkb;
    qkw[(size_t)tok*512 + head*32 + lane]       = pack2bf(qa*qs, qb*qs);
    qkw[(size_t)tok*512 + 256 + head*32 + lane] = pack2bf(ka, kb);
}

// ---------------- V transpose: [tok][d] -> [b,h,d][tok], 128-token tiles ----------------
#define VSTR 72
__global__ __launch_bounds__(256) void k_vtrans() {
    __shared__ __nv_bfloat16 vt[128*VSTR];
    const int bh = blockIdx.x;
    const int b = bh >> 3, hh = bh & 7;
    const int t0 = blockIdx.y * 128;
    const int t = threadIdx.x;
    const __nv_bfloat16* src = g_qkvb + (size_t)(b*NTOK + t0) * 1536 + 1024 + hh*64;
    #pragma unroll
    for (int i = 0; i < 4; i++) {
        const int lin = t + i*256;
        const int r = lin >> 3, c8 = lin & 7;
        *(uint4*)(vt + r*VSTR + c8*8) = *(const uint4*)(src + (size_t)r*1536 + c8*8);
    }
    __syncthreads();
    __nv_bfloat16* dst = g_vtb + (size_t)bh * 64 * NTOK + t0;
    #pragma unroll
    for (int i = 0; i < 4; i++) {
        const int lin = t + i*256;
        const int d = lin >> 4, t8 = (lin & 15) * 8;
        uint16_t v[8];
        #pragma unroll
        for (int j = 0; j < 8; j++)
            v[j] = *(const uint16_t*)(vt + (t8 + j)*VSTR + d);
        uint4 o;
        o.x = (uint32_t)v[0] | ((uint32_t)v[1] << 16);
        o.y = (uint32_t)v[2] | ((uint32_t)v[3] << 16);
        o.z = (uint32_t)v[4] | ((uint32_t)v[5] << 16);
        o.w = (uint32_t)v[6] | ((uint32_t)v[7] << 16);
        *(uint4*)(dst + (size_t)d*NTOK + t8) = o;
    }
}

// ---------------- flash attention: 3-stage K/V ring, one sync per chunk ----------------
#define QSTR 36
__global__ __launch_bounds__(256) void k_attn_mma() {
    extern __shared__ uint32_t smw[];        // 3 stages x 128 rows x QSTR
    const int bh = blockIdx.x;
    const int b = bh >> 3, hh = bh & 7;
    const int q0 = blockIdx.y * 128;
    const int tid = threadIdx.x, lane = tid & 31, warp = tid >> 5;
    const int lr = lane & 7, sel8 = (lane >> 3) & 1, sel4 = (lane >> 4) & 1;
    const int gid = lane >> 2, tig = lane & 3;
    const __nv_bfloat16* qk = g_qkb + (size_t)b * NTOK * 1024;
    const __nv_bfloat16* vt = g_vtb + (size_t)bh * 64 * NTOK;

    const uint32_t sbase = (uint32_t)__cvta_generic_to_shared(smw);
    const uint32_t qoff  = ((warp*16 + sel8*8 + lr)*QSTR + sel4*4) * 4;
    const uint32_t kvoff = ((sel8*8 + lr)*QSTR + sel4*4) * 4;

    #pragma unroll
    for (int i = 0; i < 4; i++) {
        const int lin = tid + i*256;
        const int r = lin >> 3, c4 = lin & 7;
        cpa16(smw + r*QSTR + c4*4, qk + (size_t)(q0 + r)*1024 + hh*64 + c4*8);
    }
    asm volatile("cp.async.commit_group;\n");
    asm volatile("cp.async.wait_group 0;\n");
    __syncthreads();
    uint32_t qf[4][4];
    #pragma unroll
    for (int kk = 0; kk < 4; kk++)
        ldm4(sbase + qoff + kk*32, qf[kk][0], qf[kk][1], qf[kk][2], qf[kk][3]);
    __syncthreads();

    auto load_kv = [&](int kc, int s) {
        uint32_t* Ks = smw + s*128*QSTR;
        uint32_t* Vs = Ks + 64*QSTR;
        #pragma unroll
        for (int i = 0; i < 2; i++) {
            const int lin = tid + i*256;
            const int r = lin >> 3, c4 = lin & 7;
            cpa16(Ks + r*QSTR + c4*4, qk + (size_t)(kc + r)*1024 + 512 + hh*64 + c4*8);
            cpa16(Vs + r*QSTR + c4*4, vt + (size_t)r*NTOK + kc + c4*8);
        }
    };

    float l0 = 0.f, l1 = 0.f;
    float oacc[8][4];
    #pragma unroll
    for (int nt = 0; nt < 8; nt++)
        #pragma unroll
        for (int c = 0; c < 4; c++) oacc[nt][c] = 0.f;

    load_kv(0, 0);
    asm volatile("cp.async.commit_group;\n");
    load_kv(64, 1);
    asm volatile("cp.async.commit_group;\n");

    int stg = 0;
    for (int it = 0; it < NTOK/64; it++) {
        if (it + 2 < NTOK/64) {
            asm volatile("cp.async.wait_group 1;\n");
        } else {
            asm volatile("cp.async.wait_group 0;\n");
        }
        __syncthreads();
        if (it + 2 < NTOK/64) {
            int ns = stg + 2; if (ns >= 3) ns -= 3;
            load_kv((it+2)*64, ns);
            asm volatile("cp.async.commit_group;\n");
        }
        const uint32_t kbase = sbase + (uint32_t)(stg*128*QSTR*4);
        const uint32_t vbase = kbase + 64*QSTR*4;

        float sacc[8][4];
        #pragma unroll
        for (int nt = 0; nt < 8; nt++)
            #pragma unroll
            for (int c = 0; c < 4; c++) sacc[nt][c] = 0.f;
        #pragma unroll
        for (int kk = 0; kk < 4; kk++) {
            uint32_t bf[8][2];
            const uint32_t kb = kbase + kvoff + kk*32;
            #pragma unroll
            for (int nt2 = 0; nt2 < 4; nt2++)
                ldm4(kb + nt2*16*QSTR*4,
                     bf[2*nt2][0], bf[2*nt2+1][0], bf[2*nt2][1], bf[2*nt2+1][1]);
            #pragma unroll
            for (int nt = 0; nt < 8; nt++)
                MMA_BF16(sacc[nt], qf[kk], bf[nt]);
        }

        uint32_t pa[8], pb[8];
        #pragma unroll
        for (int nt = 0; nt < 8; nt++) {
            const float p00 = __expf(sacc[nt][0] - 8.f);
            const float p01 = __expf(sacc[nt][1] - 8.f);
            const float p10 = __expf(sacc[nt][2] - 8.f);
            const float p11 = __expf(sacc[nt][3] - 8.f);
            l0 += p00 + p01;  l1 += p10 + p11;
            pa[nt] = pack2bf(p00, p01);
            pb[nt] = pack2bf(p10, p11);
        }

        #pragma unroll
        for (int kk = 0; kk < 4; kk++) {
            uint32_t af[4] = { pa[2*kk], pb[2*kk], pa[2*kk+1], pb[2*kk+1] };
            uint32_t bf[8][2];
            const uint32_t vb = vbase + kvoff + kk*32;
            #pragma unroll
            for (int nt2 = 0; nt2 < 4; nt2++)
                ldm4(vb + nt2*16*QSTR*4,
                     bf[2*nt2][0], bf[2*nt2+1][0], bf[2*nt2][1], bf[2*nt2+1][1]);
            #pragma unroll
            for (int nt = 0; nt < 8; nt++)
                MMA_BF16(oacc[nt], af, bf[nt]);
        }
        if (++stg == 3) stg = 0;
    }

    #pragma unroll
    for (int o = 1; o <= 2; o <<= 1) {
        l0 += __shfl_xor_sync(0xffffffffu, l0, o);
        l1 += __shfl_xor_sync(0xffffffffu, l1, o);
    }
    const float inv0 = 1.f / l0, inv1 = 1.f / l1;
    uint32_t* ow = (uint32_t*)g_attb;
    const size_t row = (size_t)b*NTOK + q0 + warp*16 + gid;
    #pragma unroll
    for (int nt = 0; nt < 8; nt++) {
        const int cw = hh*32 + nt*4 + tig;
        ow[row*256 + cw]     = pack2bf(oacc[nt][0]*inv0, oacc[nt][1]*inv0);
        ow[(row+8)*256 + cw] = pack2bf(oacc[nt][2]*inv1, oacc[nt][3]*inv1);
    }
}

// ---------------- launcher ----------------
extern "C" void kernel_launch(void* const* d_in, const int* in_sizes, int n_in,
                              void* d_out, int out_size) {
    const float* x      = (const float*)d_in[0];
    const float* temb   = (const float*)d_in[1];
    const float* gn_w   = (const float*)d_in[2];
    const float* gn_b   = (const float*)d_in[3];
    const float* ada_w  = (const float*)d_in[4];
    const float* ada_b  = (const float*)d_in[5];
    const float* n1_w   = (const float*)d_in[6];
    const float* n2_w   = (const float*)d_in[7];
    const float* qkv_w  = (const float*)d_in[8];
    const float* qkv_b  = (const float*)d_in[9];
    const float* qn_w   = (const float*)d_in[10];
    const float* kn_w   = (const float*)d_in[11];
    const float* proj_w = (const float*)d_in[12];
    const float* proj_b = (const float*)d_in[13];
    const float* w12    = (const float*)d_in[14];
    const float* b12    = (const float*)d_in[15];
    const float* w_out  = (const float*)d_in[16];
    const float* b_out  = (const float*)d_in[17];
    float* out = (float*)d_out;

    float *p_h, *p_ada, *p_b12p;
    __nv_bfloat16 *p_hnb, *p_qkvb, *p_attb, *p_gateb;
    __nv_bfloat16 *p_wqkv, *p_wproj, *p_w12c, *p_woc;
    cudaGetSymbolAddress((void**)&p_h,     g_h);
    cudaGetSymbolAddress((void**)&p_ada,   g_ada);
    cudaGetSymbolAddress((void**)&p_b12p,  g_b12p);
    cudaGetSymbolAddress((void**)&p_hnb,   g_hnb);
    cudaGetSymbolAddress((void**)&p_qkvb,  g_qkvb);
    cudaGetSymbolAddress((void**)&p_attb,  g_attb);
    cudaGetSymbolAddress((void**)&p_gateb, g_gateb);
    cudaGetSymbolAddress((void**)&p_wqkv,  g_wqkv);
    cudaGetSymbolAddress((void**)&p_wproj, g_wproj);
    cudaGetSymbolAddress((void**)&p_w12c,  g_w12c);
    cudaGetSymbolAddress((void**)&p_woc,   g_woc);

    const int gemm_smem  = 3*STG_W*4;         // 110592 B
    const int attn_smem  = 3*128*QSTR*4;      // 55296 B
    const int gnrms_smem = (32*HSTR + 32)*4;  // 65792 B
    cudaFuncSetAttribute(k_gemm,     cudaFuncAttributeMaxDynamicSharedMemorySize, gemm_smem);
    cudaFuncSetAttribute(k_attn_mma, cudaFuncAttributeMaxDynamicSharedMemorySize, attn_smem);
    cudaFuncSetAttribute(k_gnrms,    cudaFuncAttributeMaxDynamicSharedMemorySize, gnrms_smem);

    k_cvtall <<<(1048576 + FFN + 255)/256, 256>>>(qkv_w, proj_w, w_out, w12, b12);

    // adaLN + GroupNorm stats (merged) + fused gn-apply/rmsnorm/mod
    k_adagn  <<<192 + BDIM*32, 256>>>(temb, ada_w, ada_b, x);
    k_gnrms  <<<dim3(NTOK/32, BDIM), 512, gnrms_smem>>>(x, gn_w, gn_b, n1_w);

    // attention branch
    k_gemm   <<<dim3((3*CH)/128, NT/128), 256, gemm_smem>>>(
        p_hnb, p_wqkv, qkv_b, nullptr, (uint32_t*)p_qkvb, nullptr, p_ada,
        nullptr, nullptr, 0, 1, NT, 3*CH, CH);
    k_qkrope <<<(NT*NHEADS*32)/128, 128>>>(qn_w, kn_w);
    k_vtrans <<<dim3(BDIM*NHEADS, NTOK/128), 256>>>();
    k_attn_mma<<<dim3(BDIM*NHEADS, NTOK/128), 256, attn_smem>>>();
    k_gemm   <<<dim3(CH/128, NT/128), 256, gemm_smem>>>(
        p_attb, p_wproj, proj_b, p_h, nullptr, nullptr, p_ada,
        nullptr, nullptr, 2, 2, NT, CH, CH);

    // FFN branch
    k_rmsmod <<<NT, 128>>>(n2_w, 3, 4);
    k_gemm   <<<dim3((2*FFN)/128, NT/128), 256, gemm_smem>>>(
        p_hnb, p_w12c, p_b12p, nullptr, nullptr, p_gateb, p_ada,
        nullptr, nullptr, 0, 3, NT, 2*FFN, CH);
    k_gemm   <<<dim3(CH/128, NT/128), 256, gemm_smem>>>(
        p_gateb, p_woc, b_out, p_h, nullptr, nullptr, p_ada,
        x, out, 5, 4, NT, CH, FFN);
}

// round 13
// speedup vs baseline: 1.0358x; 1.0095x over previous
#include <cuda_runtime.h>
#include <cuda_bf16.h>
#include <cstdint>

// ---------------- problem constants ----------------
#define BDIM   16
#define CH     512
#define NTOK   1024
#define NT     (BDIM*NTOK)
#define NHEADS 8
#define HDIM   64
#define FFN    2048
#define EPSV   1e-6f

// ---------------- scratch ----------------
__device__ float g_ada [BDIM*6*CH];
__device__ float g_h   [NT*CH];
__device__ float g_stats[BDIM*32*2];
__device__ float g_b12p[2*FFN];
__device__ __nv_bfloat16 g_hnb [NT*CH];
__device__ __nv_bfloat16 g_qkvb[NT*3*CH];
__device__ __nv_bfloat16 g_qkb [NT*2*CH];
__device__ __nv_bfloat16 g_vtb [BDIM*NHEADS*HDIM*NTOK];
__device__ __nv_bfloat16 g_attb[NT*CH];
__device__ __nv_bfloat16 g_gateb[NT*FFN];
__device__ __nv_bfloat16 g_wqkv [3*CH*CH];
__device__ __nv_bfloat16 g_wproj[CH*CH];
__device__ __nv_bfloat16 g_w12c [2*FFN*CH];
__device__ __nv_bfloat16 g_woc  [CH*FFN];

// ---------------- helpers ----------------
__device__ __forceinline__ uint32_t pack2bf(float lo, float hi) {
    uint32_t r;
    asm("cvt.rn.bf16x2.f32 %0, %1, %2;" : "=r"(r) : "f"(hi), "f"(lo));
    return r;
}
__device__ __forceinline__ void cpa16(void* s, const void* g) {
    uint32_t sa = (uint32_t)__cvta_generic_to_shared(s);
    asm volatile("cp.async.cg.shared.global [%0], [%1], 16;\n" :: "r"(sa), "l"(g));
}
__device__ __forceinline__ void ldm4(uint32_t addr, uint32_t& r0, uint32_t& r1,
                                     uint32_t& r2, uint32_t& r3) {
    asm volatile("ldmatrix.sync.aligned.m8n8.x4.shared.b16 {%0,%1,%2,%3}, [%4];"
                 : "=r"(r0), "=r"(r1), "=r"(r2), "=r"(r3) : "r"(addr));
}
#define MMA_BF16(d, a, b) \
    asm volatile("mma.sync.aligned.m16n8k16.row.col.f32.bf16.bf16.f32 " \
                 "{%0,%1,%2,%3}, {%4,%5,%6,%7}, {%8,%9}, {%0,%1,%2,%3};" \
                 : "+f"(d[0]), "+f"(d[1]), "+f"(d[2]), "+f"(d[3]) \
                 : "r"(a[0]), "r"(a[1]), "r"(a[2]), "r"(a[3]), "r"(b[0]), "r"(b[1]))

// ---------------- merged weight conversion ----------------
__device__ __forceinline__ void cvt4(const float* __restrict__ s,
                                     __nv_bfloat16* __restrict__ d, int i) {
    float4 v = *(const float4*)(s + i);
    *(uint32_t*)(d + i)     = pack2bf(v.x, v.y);
    *(uint32_t*)(d + i + 2) = pack2bf(v.z, v.w);
}
__global__ void k_cvtall(const float* __restrict__ qkv_w, const float* __restrict__ proj_w,
                         const float* __restrict__ w_out, const float* __restrict__ w12,
                         const float* __restrict__ b12) {
    const int gi = blockIdx.x * blockDim.x + threadIdx.x;
    if (gi < 196608) {
        cvt4(qkv_w, g_wqkv, gi * 4);
    } else if (gi < 262144) {
        cvt4(proj_w, g_wproj, (gi - 196608) * 4);
    } else if (gi < 524288) {
        cvt4(w_out, g_woc, (gi - 262144) * 4);
    } else if (gi < 1048576) {
        const int i = (gi - 524288) * 4;
        const int r = i >> 9;
        const int k = i & (CH - 1);
        const int sr = (r & 1) ? (FFN + (r >> 1)) : (r >> 1);
        float4 v = *(const float4*)(w12 + (size_t)sr*CH + k);
        *(uint32_t*)(g_w12c + i)     = pack2bf(v.x, v.y);
        *(uint32_t*)(g_w12c + i + 2) = pack2bf(v.z, v.w);
    } else if (gi < 1048576 + FFN) {
        const int j = gi - 1048576;
        g_b12p[2*j]   = b12[j];
        g_b12p[2*j+1] = b12[FFN + j];
    }
}

// ---------------- merged adaLN + GroupNorm stats ----------------
__global__ __launch_bounds__(256) void k_adagn(
    const float* __restrict__ temb, const float* __restrict__ ada_w,
    const float* __restrict__ ada_b, const float* __restrict__ x) {
    const int blk = blockIdx.x;
    __shared__ float sh[CH];
    if (blk < 192) {
        const int b = blk / 12;
        for (int i = threadIdx.x; i < CH; i += 256) {
            float v = temb[b*CH + i];
            sh[i] = v / (1.f + __expf(-v));
        }
        __syncthreads();
        const int n = (blk % 12) * 256 + threadIdx.x;
        const float* wr = ada_w + (size_t)n * CH;
        float acc = 0.f;
        #pragma unroll 8
        for (int k = 0; k < CH; k++) acc += wr[k] * sh[k];
        g_ada[b*6*CH + n] = acc + ada_b[n];
    } else {
        const int bg = blk - 192;
        const float* p = x + (size_t)bg * 16 * NTOK;
        float s = 0.f, s2 = 0.f;
        for (int i = threadIdx.x; i < 16*NTOK; i += 256) {
            float v = p[i]; s += v; s2 += v*v;
        }
        #pragma unroll
        for (int o = 16; o; o >>= 1) {
            s  += __shfl_xor_sync(0xffffffffu, s,  o);
            s2 += __shfl_xor_sync(0xffffffffu, s2, o);
        }
        const int w = threadIdx.x >> 5, l = threadIdx.x & 31;
        if (l == 0) { sh[w] = s; sh[32 + w] = s2; }
        __syncthreads();
        if (threadIdx.x < 32) {
            s  = (threadIdx.x < 8) ? sh[threadIdx.x]      : 0.f;
            s2 = (threadIdx.x < 8) ? sh[32 + threadIdx.x] : 0.f;
            #pragma unroll
            for (int o = 4; o; o >>= 1) {
                s  += __shfl_xor_sync(0xffffffffu, s,  o);
                s2 += __shfl_xor_sync(0xffffffffu, s2, o);
            }
            if (threadIdx.x == 0) {
                const float inv = 1.f / (16.f * NTOK);
                float mu  = s * inv;
                float var = s2 * inv - mu * mu;
                g_stats[bg*2]     = mu;
                g_stats[bg*2 + 1] = rsqrtf(var + EPSV);
            }
        }
    }
}

// ---------------- fused GroupNorm-apply + transpose + RMSNorm(n1) + mod ----------------
#define HSTR 513
__global__ __launch_bounds__(512) void k_gnrms(
    const float* __restrict__ x, const float* __restrict__ gw, const float* __restrict__ gb,
    const float* __restrict__ n1w) {
    extern __shared__ float hb[];
    float* rms = hb + 32*HSTR;
    const int b  = blockIdx.y;
    const int n0 = blockIdx.x * 32;
    const int t  = threadIdx.x;
    for (int c0 = 0; c0 < CH; c0 += 64) {
        #pragma unroll
        for (int i = 0; i < 4; i++) {
            const int cl = (t >> 5) + i*16;
            const int nl = t & 31;
            const int c  = c0 + cl;
            const float mu = g_stats[(b*32 + (c >> 4))*2];
            const float rs = g_stats[(b*32 + (c >> 4))*2 + 1];
            const float v  = x[((size_t)b*CH + c)*NTOK + n0 + nl];
            hb[nl*HSTR + c] = (v - mu) * rs * gw[c] + gb[c];
        }
    }
    __syncthreads();
    {
        const int tok = t >> 4, l16 = t & 15;
        float ss = 0.f;
        #pragma unroll 8
        for (int i = 0; i < 32; i++) {
            const float v = hb[tok*HSTR + l16 + i*16];
            ss += v*v;
        }
        #pragma unroll
        for (int o = 1; o <= 8; o <<= 1) ss += __shfl_xor_sync(0xffffffffu, ss, o);
        if (l16 == 0) rms[tok] = rsqrtf(ss / (float)CH + EPSV);
    }
    __syncthreads();
    const int rowb = b*NTOK + n0;
    const float* shf = g_ada + b*6*CH;
    const float* scl = g_ada + b*6*CH + CH;
    #pragma unroll 4
    for (int i = 0; i < 16; i++) {
        const int idx = (t + i*512) * 2;
        const int tk = idx >> 9, c = idx & 511;
        const float h0 = hb[tk*HSTR + c], h1 = hb[tk*HSTR + c + 1];
        const float r = rms[tk];
        *(float2*)(g_h + (size_t)(rowb + tk)*CH + c) = make_float2(h0, h1);
        const float o0 = h0 * r * n1w[c]   * (1.f + scl[c])   + shf[c];
        const float o1 = h1 * r * n1w[c+1] * (1.f + scl[c+1]) + shf[c+1];
        *(uint32_t*)(g_hnb + (size_t)(rowb + tk)*CH + c) = pack2bf(o0, o1);
    }
}

// ---------------- RMSNorm + modulation -> bf16 (n2 path) ----------------
__global__ void k_rmsmod(const float* __restrict__ w, int shift_ch, int scale_ch) {
    const int row = blockIdx.x;
    const int b = row >> 10;
    const float* hp = g_h + (size_t)row * CH;
    const int t = threadIdx.x;
    float4 v = *(const float4*)(hp + t*4);
    float ss = v.x*v.x + v.y*v.y + v.z*v.z + v.w*v.w;
    #pragma unroll
    for (int o = 16; o; o >>= 1) ss += __shfl_xor_sync(0xffffffffu, ss, o);
    __shared__ float sh[4];
    if ((t & 31) == 0) sh[t >> 5] = ss;
    __syncthreads();
    ss = sh[0] + sh[1] + sh[2] + sh[3];
    const float r = rsqrtf(ss / (float)CH + EPSV);
    const float* shf = g_ada + b*6*CH + shift_ch*CH;
    const float* scl = g_ada + b*6*CH + scale_ch*CH;
    const int c = t*4;
    float o0 = v.x * r * w[c+0] * (1.f + scl[c+0]) + shf[c+0];
    float o1 = v.y * r * w[c+1] * (1.f + scl[c+1]) + shf[c+1];
    float o2 = v.z * r * w[c+2] * (1.f + scl[c+2]) + shf[c+2];
    float o3 = v.w * r * w[c+3] * (1.f + scl[c+3]) + shf[c+3];
    uint32_t* dp = (uint32_t*)(g_hnb + (size_t)row*CH + c);
    dp[0] = pack2bf(o0, o1);
    dp[1] = pack2bf(o2, o3);
}

// ---------------- BF16 GEMM (templated shapes): K-chunk 64, 3-stage, 1 barrier/chunk ----------------
// MODE: 1 = bf16 store; 2 = g_h += gate*(acc+bias); 3 = fused swiglu;
//       4 = final: out = x + (g_h + gate*(acc+bias))^T
#define WSTR 36
#define STG_W (128*WSTR*2)
template<int MODE, int NN, int KK>
__global__ __launch_bounds__(256, 2) void k_gemm(
    const __nv_bfloat16* __restrict__ A, const __nv_bfloat16* __restrict__ W,
    const float* __restrict__ bias, float* __restrict__ Cf, uint32_t* __restrict__ Cb,
    __nv_bfloat16* __restrict__ Gb, const float* __restrict__ ada,
    const float* __restrict__ Xin, float* __restrict__ Oout, int gch)
{
    extern __shared__ uint32_t sm[];
    const int tid  = threadIdx.x;
    const int lane = tid & 31;
    const int warp = tid >> 5;
    const int gid  = lane >> 2;
    const int tig  = lane & 3;
    const int row0 = (warp & 3) * 32;
    const int col0 = (warp >> 2) * 64;
    const int bm = blockIdx.y * 128, bn = blockIdx.x * 128;
    constexpr int KT = KK >> 6;
    const int lr   = lane & 7;
    const int sel8 = (lane >> 3) & 1;
    const int sel4 = (lane >> 4) & 1;

    const uint32_t sbase = (uint32_t)__cvta_generic_to_shared(sm);
    const uint32_t aoff  = ((row0 + sel8*8 + lr)*WSTR + sel4*4) * 4;
    const uint32_t boff  = ((col0 + sel8*8 + lr)*WSTR + sel4*4) * 4 + 128*WSTR*4;

    auto load_body = [&](int kt, int s) {
        uint32_t* As = sm + s * STG_W;
        uint32_t* Ws = As + 128*WSTR;
        const int k0 = kt << 6;
        #pragma unroll
        for (int i = 0; i < 4; i++) {
            const int lin = tid + i*256;
            const int r = lin >> 3, c = lin & 7;
            cpa16(As + r*WSTR + c*4, A + (size_t)(bm + r)*KK + k0 + c*8);
        }
        #pragma unroll
        for (int i = 0; i < 4; i++) {
            const int lin = tid + i*256;
            const int r = lin >> 3, c = lin & 7;
            cpa16(Ws + r*WSTR + c*4, W + (size_t)(bn + r)*KK + k0 + c*8);
        }
    };

    load_body(0, 0);
    asm volatile("cp.async.commit_group;\n");
    load_body(1, 1);
    asm volatile("cp.async.commit_group;\n");

    float acc[2][8][4];
    #pragma unroll
    for (int i = 0; i < 2; i++)
        #pragma unroll
        for (int j = 0; j < 8; j++)
            #pragma unroll
            for (int c = 0; c < 4; c++) acc[i][j][c] = 0.f;

    int stg = 0;
    #pragma unroll 2
    for (int kt = 0; kt < KT; kt++) {
        if (kt + 1 < KT) {
            asm volatile("cp.async.wait_group 1;\n");
        } else {
            asm volatile("cp.async.wait_group 0;\n");
        }
        __syncthreads();
        if (kt + 2 < KT) {
            int ns = stg + 2; if (ns >= 3) ns -= 3;
            load_body(kt + 2, ns);
            asm volatile("cp.async.commit_group;\n");
        }
        const uint32_t stb = sbase + (uint32_t)(stg * STG_W * 4);
        #pragma unroll
        for (int kk = 0; kk < 4; kk++) {
            const uint32_t kb = kk * 32;
            uint32_t af[2][4], bf[8][2];
            const uint32_t aa = stb + aoff + kb;
            ldm4(aa,             af[0][0], af[0][1], af[0][2], af[0][3]);
            ldm4(aa + 16*WSTR*4, af[1][0], af[1][1], af[1][2], af[1][3]);
            const uint32_t bb = stb + boff + kb;
            #pragma unroll
            for (int nt2 = 0; nt2 < 4; nt2++) {
                ldm4(bb + nt2*16*WSTR*4,
                     bf[2*nt2][0], bf[2*nt2+1][0], bf[2*nt2][1], bf[2*nt2+1][1]);
            }
            #pragma unroll
            for (int mt = 0; mt < 2; mt++)
                #pragma unroll
                for (int nt = 0; nt < 8; nt++)
                    MMA_BF16(acc[mt][nt], af[mt], bf[nt]);
        }
        if (++stg == 3) stg = 0;
    }

    if (MODE == 4) {
        asm volatile("cp.async.wait_group 0;\n");
        __syncthreads();
        float* hs = (float*)sm;
        #pragma unroll
        for (int mt = 0; mt < 2; mt++) {
            const int rl = row0 + mt*16 + gid;
            const int row = bm + rl;
            const int b = row >> 10;
            const float* gp = ada + b*6*CH + gch*CH;
            #pragma unroll
            for (int nt = 0; nt < 8; nt++) {
                const int cl = col0 + nt*8 + tig*2;
                const int col = bn + cl;
                const float b0 = bias[col], b1 = bias[col+1];
                float2 h0 = *(float2*)(Cf + (size_t)row*NN + col);
                float2 h1 = *(float2*)(Cf + (size_t)(row+8)*NN + col);
                hs[rl*132 + cl]       = h0.x + gp[col]  *(acc[mt][nt][0] + b0);
                hs[rl*132 + cl+1]     = h0.y + gp[col+1]*(acc[mt][nt][1] + b1);
                hs[(rl+8)*132 + cl]   = h1.x + gp[col]  *(acc[mt][nt][2] + b0);
                hs[(rl+8)*132 + cl+1] = h1.y + gp[col+1]*(acc[mt][nt][3] + b1);
            }
        }
        __syncthreads();
        const int b = bm >> 10;
        const int nbase = bm & 1023;
        #pragma unroll
        for (int i = 0; i < 16; i++) {
            const int lin = tid + i*256;
            const int cr = lin >> 5, g = lin & 31;
            const size_t oidx = ((size_t)b*CH + bn + cr)*NTOK + nbase + g*4;
            float4 xs = *(const float4*)(Xin + oidx);
            xs.x += hs[(g*4+0)*132 + cr];
            xs.y += hs[(g*4+1)*132 + cr];
            xs.z += hs[(g*4+2)*132 + cr];
            xs.w += hs[(g*4+3)*132 + cr];
            *(float4*)(Oout + oidx) = xs;
        }
        return;
    }

    #pragma unroll
    for (int mt = 0; mt < 2; mt++) {
        const int row = bm + row0 + mt*16 + gid;
        const int b   = row >> 10;
        const float* gp = ada + b*6*CH + gch*CH;
        #pragma unroll
        for (int nt = 0; nt < 8; nt++) {
            const int col = bn + col0 + nt*8 + tig*2;
            const float b0 = bias[col], b1 = bias[col+1];
            float v00 = acc[mt][nt][0] + b0, v01 = acc[mt][nt][1] + b1;
            float v10 = acc[mt][nt][2] + b0, v11 = acc[mt][nt][3] + b1;
            if (MODE == 1) {
                Cb[((size_t)row*NN + col) >> 1]     = pack2bf(v00, v01);
                Cb[((size_t)(row+8)*NN + col) >> 1] = pack2bf(v10, v11);
            } else if (MODE == 2) {
                const float gg0 = gp[col], gg1 = gp[col+1];
                float2 h0 = *(float2*)(Cf + (size_t)row*NN + col);
                float2 h1 = *(float2*)(Cf + (size_t)(row+8)*NN + col);
                h0.x += gg0*v00; h0.y += gg1*v01;
                h1.x += gg0*v10; h1.y += gg1*v11;
                *(float2*)(Cf + (size_t)row*NN + col)     = h0;
                *(float2*)(Cf + (size_t)(row+8)*NN + col) = h1;
            } else {
                const int j = col >> 1;
                const float s0 = (v00 / (1.f + __expf(-v00))) * v01;
                const float s1 = (v10 / (1.f + __expf(-v10))) * v11;
                Gb[(size_t)row*(NN>>1) + j]     = __float2bfloat16(s0);
                Gb[(size_t)(row+8)*(NN>>1) + j] = __float2bfloat16(s1);
            }
        }
    }
}

// ---------------- q/k RMSNorm + RoPE (bf16 in) -> bf16 ----------------
__global__ void k_qkrope(const float* __restrict__ qn_w, const float* __restrict__ kn_w) {
    const int gw   = (blockIdx.x * blockDim.x + threadIdx.x) >> 5;
    const int lane = threadIdx.x & 31;
    const int head = gw & 7;
    const int tok  = gw >> 3;
    const int n = tok & 1023;
    const int rrow = n >> 5, rcol = n & 31;
    const uint32_t* qkvw = (const uint32_t*)g_qkvb;
    const size_t base = (size_t)tok * 768;
    float2 qv = __bfloat1622float2(*(const __nv_bfloat162*)&qkvw[base + head*32 + lane]);
    float2 kv = __bfloat1622float2(*(const __nv_bfloat162*)&qkvw[base + 256 + head*32 + lane]);
    float q0 = qv.x, q1 = qv.y, k0 = kv.x, k1 = kv.y;
    const int j = lane * 2;
    float sq = q0*q0 + q1*q1, sk = k0*k0 + k1*k1;
    #pragma unroll
    for (int o = 16; o; o >>= 1) {
        sq += __shfl_xor_sync(0xffffffffu, sq, o);
        sk += __shfl_xor_sync(0xffffffffu, sk, o);
    }
    const float rq = rsqrtf(sq / 64.f + EPSV);
    const float rk = rsqrtf(sk / 64.f + EPSV);
    q0 *= rq * qn_w[j];  q1 *= rq * qn_w[j+1];
    k0 *= rk * kn_w[j];  k1 *= rk * kn_w[j+1];
    const int half = (j >= 32);
    const int idx  = (half ? (j - 32) : j) >> 1;
    const float freq = exp2f(-(float)idx * (13.287712379549449f / 16.f));
    const float f = (half ? (float)rcol : (float)rrow) * freq;
    const float cf = cosf(f), sf = sinf(f);
    const float qa = q0*cf - q1*sf, qb = q1*cf + q0*sf;
    const float ka = k0*cf - k1*sf, kb = k1*cf + k0*sf;
    const float qs = 0.125f;
    uint32_t* qkw = (uint32_t*)g_qkb;
    qkw[(size_t)tok*512 + head*32 + lane]       = pack2bf(qa*qs, qb*qs);
    qkw[(size_t)tok*512 + 256 + head*32 + lane] = pack2bf(ka, kb);
}

// ---------------- V transpose: [tok][d] -> [b,h,d][tok], 128-token tiles ----------------
#define VSTR 72
__global__ __launch_bounds__(256) void k_vtrans() {
    __shared__ __nv_bfloat16 vt[128*VSTR];
    const int bh = blockIdx.x;
    const int b = bh >> 3, hh = bh & 7;
    const int t0 = blockIdx.y * 128;
    const int t = threadIdx.x;
    const __nv_bfloat16* src = g_qkvb + (size_t)(b*NTOK + t0) * 1536 + 1024 + hh*64;
    #pragma unroll
    for (int i = 0; i < 4; i++) {
        const int lin = t + i*256;
        const int r = lin >> 3, c8 = lin & 7;
        *(uint4*)(vt + r*VSTR + c8*8) = *(const uint4*)(src + (size_t)r*1536 + c8*8);
    }
    __syncthreads();
    __nv_bfloat16* dst = g_vtb + (size_t)bh * 64 * NTOK + t0;
    #pragma unroll
    for (int i = 0; i < 4; i++) {
        const int lin = t + i*256;
        const int d = lin >> 4, t8 = (lin & 15) * 8;
        uint16_t v[8];
        #pragma unroll
        for (int j = 0; j < 8; j++)
            v[j] = *(const uint16_t*)(vt + (t8 + j)*VSTR + d);
        uint4 o;
        o.x = (uint32_t)v[0] | ((uint32_t)v[1] << 16);
        o.y = (uint32_t)v[2] | ((uint32_t)v[3] << 16);
        o.z = (uint32_t)v[4] | ((uint32_t)v[5] << 16);
        o.w = (uint32_t)v[6] | ((uint32_t)v[7] << 16);
        *(uint4*)(dst + (size_t)d*NTOK + t8) = o;
    }
}

// ---------------- flash attention: 3-stage K/V ring, one sync per chunk ----------------
#define QSTR 36
__global__ __launch_bounds__(256) void k_attn_mma() {
    extern __shared__ uint32_t smw[];
    const int bh = blockIdx.x;
    const int b = bh >> 3, hh = bh & 7;
    const int q0 = blockIdx.y * 128;
    const int tid = threadIdx.x, lane = tid & 31, warp = tid >> 5;
    const int lr = lane & 7, sel8 = (lane >> 3) & 1, sel4 = (lane >> 4) & 1;
    const int gid = lane >> 2, tig = lane & 3;
    const __nv_bfloat16* qk = g_qkb + (size_t)b * NTOK * 1024;
    const __nv_bfloat16* vt = g_vtb + (size_t)bh * 64 * NTOK;

    const uint32_t sbase = (uint32_t)__cvta_generic_to_shared(smw);
    const uint32_t qoff  = ((warp*16 + sel8*8 + lr)*QSTR + sel4*4) * 4;
    const uint32_t kvoff = ((sel8*8 + lr)*QSTR + sel4*4) * 4;

    #pragma unroll
    for (int i = 0; i < 4; i++) {
        const int lin = tid + i*256;
        const int r = lin >> 3, c4 = lin & 7;
        cpa16(smw + r*QSTR + c4*4, qk + (size_t)(q0 + r)*1024 + hh*64 + c4*8);
    }
    asm volatile("cp.async.commit_group;\n");
    asm volatile("cp.async.wait_group 0;\n");
    __syncthreads();
    uint32_t qf[4][4];
    #pragma unroll
    for (int kk = 0; kk < 4; kk++)
        ldm4(sbase + qoff + kk*32, qf[kk][0], qf[kk][1], qf[kk][2], qf[kk][3]);
    __syncthreads();

    auto load_kv = [&](int kc, int s) {
        uint32_t* Ks = smw + s*128*QSTR;
        uint32_t* Vs = Ks + 64*QSTR;
        #pragma unroll
        for (int i = 0; i < 2; i++) {
            const int lin = tid + i*256;
            const int r = lin >> 3, c4 = lin & 7;
            cpa16(Ks + r*QSTR + c4*4, qk + (size_t)(kc + r)*1024 + 512 + hh*64 + c4*8);
            cpa16(Vs + r*QSTR + c4*4, vt + (size_t)r*NTOK + kc + c4*8);
        }
    };

    float l0 = 0.f, l1 = 0.f;
    float oacc[8][4];
    #pragma unroll
    for (int nt = 0; nt < 8; nt++)
        #pragma unroll
        for (int c = 0; c < 4; c++) oacc[nt][c] = 0.f;

    load_kv(0, 0);
    asm volatile("cp.async.commit_group;\n");
    load_kv(64, 1);
    asm volatile("cp.async.commit_group;\n");

    int stg = 0;
    for (int it = 0; it < NTOK/64; it++) {
        if (it + 2 < NTOK/64) {
            asm volatile("cp.async.wait_group 1;\n");
        } else {
            asm volatile("cp.async.wait_group 0;\n");
        }
        __syncthreads();
        if (it + 2 < NTOK/64) {
            int ns = stg + 2; if (ns >= 3) ns -= 3;
            load_kv((it+2)*64, ns);
            asm volatile("cp.async.commit_group;\n");
        }
        const uint32_t kbase = sbase + (uint32_t)(stg*128*QSTR*4);
        const uint32_t vbase = kbase + 64*QSTR*4;

        float sacc[8][4];
        #pragma unroll
        for (int nt = 0; nt < 8; nt++)
            #pragma unroll
            for (int c = 0; c < 4; c++) sacc[nt][c] = 0.f;
        #pragma unroll
        for (int kk = 0; kk < 4; kk++) {
            uint32_t bf[8][2];
            const uint32_t kb = kbase + kvoff + kk*32;
            #pragma unroll
            for (int nt2 = 0; nt2 < 4; nt2++)
                ldm4(kb + nt2*16*QSTR*4,
                     bf[2*nt2][0], bf[2*nt2+1][0], bf[2*nt2][1], bf[2*nt2+1][1]);
            #pragma unroll
            for (int nt = 0; nt < 8; nt++)
                MMA_BF16(sacc[nt], qf[kk], bf[nt]);
        }

        uint32_t pa[8], pb[8];
        #pragma unroll
        for (int nt = 0; nt < 8; nt++) {
            const float p00 = __expf(sacc[nt][0] - 8.f);
            const float p01 = __expf(sacc[nt][1] - 8.f);
            const float p10 = __expf(sacc[nt][2] - 8.f);
            const float p11 = __expf(sacc[nt][3] - 8.f);
            l0 += p00 + p01;  l1 += p10 + p11;
            pa[nt] = pack2bf(p00, p01);
            pb[nt] = pack2bf(p10, p11);
        }

        #pragma unroll
        for (int kk = 0; kk < 4; kk++) {
            uint32_t af[4] = { pa[2*kk], pb[2*kk], pa[2*kk+1], pb[2*kk+1] };
            uint32_t bf[8][2];
            const uint32_t vb = vbase + kvoff + kk*32;
            #pragma unroll
            for (int nt2 = 0; nt2 < 4; nt2++)
                ldm4(vb + nt2*16*QSTR*4,
                     bf[2*nt2][0], bf[2*nt2+1][0], bf[2*nt2][1], bf[2*nt2+1][1]);
            #pragma unroll
            for (int nt = 0; nt < 8; nt++)
                MMA_BF16(oacc[nt], af, bf[nt]);
        }
        if (++stg == 3) stg = 0;
    }

    #pragma unroll
    for (int o = 1; o <= 2; o <<= 1) {
        l0 += __shfl_xor_sync(0xffffffffu, l0, o);
        l1 += __shfl_xor_sync(0xffffffffu, l1, o);
    }
    const float inv0 = 1.f / l0, inv1 = 1.f / l1;
    uint32_t* ow = (uint32_t*)g_attb;
    const size_t row = (size_t)b*NTOK + q0 + warp*16 + gid;
    #pragma unroll
    for (int nt = 0; nt < 8; nt++) {
        const int cw = hh*32 + nt*4 + tig;
        ow[row*256 + cw]     = pack2bf(oacc[nt][0]*inv0, oacc[nt][1]*inv0);
        ow[(row+8)*256 + cw] = pack2bf(oacc[nt][2]*inv1, oacc[nt][3]*inv1);
    }
}

// ---------------- launcher ----------------
extern "C" void kernel_launch(void* const* d_in, const int* in_sizes, int n_in,
                              void* d_out, int out_size) {
    const float* x      = (const float*)d_in[0];
    const float* temb   = (const float*)d_in[1];
    const float* gn_w   = (const float*)d_in[2];
    const float* gn_b   = (const float*)d_in[3];
    const float* ada_w  = (const float*)d_in[4];
    const float* ada_b  = (const float*)d_in[5];
    const float* n1_w   = (const float*)d_in[6];
    const float* n2_w   = (const float*)d_in[7];
    const float* qkv_w  = (const float*)d_in[8];
    const float* qkv_b  = (const float*)d_in[9];
    const float* qn_w   = (const float*)d_in[10];
    const float* kn_w   = (const float*)d_in[11];
    const float* proj_w = (const float*)d_in[12];
    const float* proj_b = (const float*)d_in[13];
    const float* w12    = (const float*)d_in[14];
    const float* b12    = (const float*)d_in[15];
    const float* w_out  = (const float*)d_in[16];
    const float* b_out  = (const float*)d_in[17];
    float* out = (float*)d_out;

    float *p_h, *p_ada, *p_b12p;
    __nv_bfloat16 *p_hnb, *p_qkvb, *p_attb, *p_gateb;
    __nv_bfloat16 *p_wqkv, *p_wproj, *p_w12c, *p_woc;
    cudaGetSymbolAddress((void**)&p_h,     g_h);
    cudaGetSymbolAddress((void**)&p_ada,   g_ada);
    cudaGetSymbolAddress((void**)&p_b12p,  g_b12p);
    cudaGetSymbolAddress((void**)&p_hnb,   g_hnb);
    cudaGetSymbolAddress((void**)&p_qkvb,  g_qkvb);
    cudaGetSymbolAddress((void**)&p_attb,  g_attb);
    cudaGetSymbolAddress((void**)&p_gateb, g_gateb);
    cudaGetSymbolAddress((void**)&p_wqkv,  g_wqkv);
    cudaGetSymbolAddress((void**)&p_wproj, g_wproj);
    cudaGetSymbolAddress((void**)&p_w12c,  g_w12c);
    cudaGetSymbolAddress((void**)&p_woc,   g_woc);

    const int gemm_smem  = 3*STG_W*4;         // 110592 B
    const int attn_smem  = 3*128*QSTR*4;      // 55296 B
    const int gnrms_smem = (32*HSTR + 32)*4;  // 65792 B
    cudaFuncSetAttribute(k_gemm<1,1536,512>, cudaFuncAttributeMaxDynamicSharedMemorySize, gemm_smem);
    cudaFuncSetAttribute(k_gemm<2,512,512>,  cudaFuncAttributeMaxDynamicSharedMemorySize, gemm_smem);
    cudaFuncSetAttribute(k_gemm<3,4096,512>, cudaFuncAttributeMaxDynamicSharedMemorySize, gemm_smem);
    cudaFuncSetAttribute(k_gemm<4,512,2048>, cudaFuncAttributeMaxDynamicSharedMemorySize, gemm_smem);
    cudaFuncSetAttribute(k_attn_mma, cudaFuncAttributeMaxDynamicSharedMemorySize, attn_smem);
    cudaFuncSetAttribute(k_gnrms,    cudaFuncAttributeMaxDynamicSharedMemorySize, gnrms_smem);

    k_cvtall <<<(1048576 + FFN + 255)/256, 256>>>(qkv_w, proj_w, w_out, w12, b12);

    // adaLN + GroupNorm stats (merged) + fused gn-apply/rmsnorm/mod
    k_adagn  <<<192 + BDIM*32, 256>>>(temb, ada_w, ada_b, x);
    k_gnrms  <<<dim3(NTOK/32, BDIM), 512, gnrms_smem>>>(x, gn_w, gn_b, n1_w);

    // attention branch
    k_gemm<1,1536,512><<<dim3(1536/128, NT/128), 256, gemm_smem>>>(
        p_hnb, p_wqkv, qkv_b, nullptr, (uint32_t*)p_qkvb, nullptr, p_ada,
        nullptr, nullptr, 0);
    k_qkrope <<<(NT*NHEADS*32)/128, 128>>>(qn_w, kn_w);
    k_vtrans <<<dim3(BDIM*NHEADS, NTOK/128), 256>>>();
    k_attn_mma<<<dim3(BDIM*NHEADS, NTOK/128), 256, attn_smem>>>();
    k_gemm<2,512,512><<<dim3(512/128, NT/128), 256, gemm_smem>>>(
        p_attb, p_wproj, proj_b, p_h, nullptr, nullptr, p_ada,
        nullptr, nullptr, 2);

    // FFN branch
    k_rmsmod <<<NT, 128>>>(n2_w, 3, 4);
    k_gemm<3,4096,512><<<dim3(4096/128, NT/128), 256, gemm_smem>>>(
        p_hnb, p_w12c, p_b12p, nullptr, nullptr, p_gateb, p_ada,
        nullptr, nullptr, 0);
    k_gemm<4,512,2048><<<dim3(512/128, NT/128), 256, gemm_smem>>>(
        p_gateb, p_woc, b_out, p_h, nullptr, nullptr, p_ada,
        x, out, 5);
}

// round 14
// speedup vs baseline: 1.0476x; 1.0114x over previous
#include <cuda_runtime.h>
#include <cuda_bf16.h>
#include <cstdint>

// ---------------- problem constants ----------------
#define BDIM   16
#define CH     512
#define NTOK   1024
#define NT     (BDIM*NTOK)
#define NHEADS 8
#define HDIM   64
#define FFN    2048
#define EPSV   1e-6f

// ---------------- scratch ----------------
__device__ float g_ada [BDIM*6*CH];
__device__ float g_h   [NT*CH];
__device__ float g_stats[BDIM*32*2];
__device__ float g_b12p[2*FFN];
__device__ __nv_bfloat16 g_hnb [NT*CH];
__device__ __nv_bfloat16 g_qkb [NT*2*CH];
__device__ __nv_bfloat16 g_vtb [BDIM*NHEADS*HDIM*NTOK];
__device__ __nv_bfloat16 g_attb[NT*CH];
__device__ __nv_bfloat16 g_gateb[NT*FFN];
__device__ __nv_bfloat16 g_wqkv [3*CH*CH];
__device__ __nv_bfloat16 g_wproj[CH*CH];
__device__ __nv_bfloat16 g_w12c [2*FFN*CH];
__device__ __nv_bfloat16 g_woc  [CH*FFN];

// ---------------- helpers ----------------
__device__ __forceinline__ uint32_t pack2bf(float lo, float hi) {
    uint32_t r;
    asm("cvt.rn.bf16x2.f32 %0, %1, %2;" : "=r"(r) : "f"(hi), "f"(lo));
    return r;
}
__device__ __forceinline__ void cpa16(void* s, const void* g) {
    uint32_t sa = (uint32_t)__cvta_generic_to_shared(s);
    asm volatile("cp.async.cg.shared.global [%0], [%1], 16;\n" :: "r"(sa), "l"(g));
}
__device__ __forceinline__ void ldm4(uint32_t addr, uint32_t& r0, uint32_t& r1,
                                     uint32_t& r2, uint32_t& r3) {
    asm volatile("ldmatrix.sync.aligned.m8n8.x4.shared.b16 {%0,%1,%2,%3}, [%4];"
                 : "=r"(r0), "=r"(r1), "=r"(r2), "=r"(r3) : "r"(addr));
}
#define MMA_BF16(d, a, b) \
    asm volatile("mma.sync.aligned.m16n8k16.row.col.f32.bf16.bf16.f32 " \
                 "{%0,%1,%2,%3}, {%4,%5,%6,%7}, {%8,%9}, {%0,%1,%2,%3};" \
                 : "+f"(d[0]), "+f"(d[1]), "+f"(d[2]), "+f"(d[3]) \
                 : "r"(a[0]), "r"(a[1]), "r"(a[2]), "r"(a[3]), "r"(b[0]), "r"(b[1]))

// ---------------- merged weight conversion ----------------
__device__ __forceinline__ void cvt4(const float* __restrict__ s,
                                     __nv_bfloat16* __restrict__ d, int i) {
    float4 v = *(const float4*)(s + i);
    *(uint32_t*)(d + i)     = pack2bf(v.x, v.y);
    *(uint32_t*)(d + i + 2) = pack2bf(v.z, v.w);
}
__global__ void k_cvtall(const float* __restrict__ qkv_w, const float* __restrict__ proj_w,
                         const float* __restrict__ w_out, const float* __restrict__ w12,
                         const float* __restrict__ b12) {
    const int gi = blockIdx.x * blockDim.x + threadIdx.x;
    if (gi < 196608) {
        cvt4(qkv_w, g_wqkv, gi * 4);
    } else if (gi < 262144) {
        cvt4(proj_w, g_wproj, (gi - 196608) * 4);
    } else if (gi < 524288) {
        cvt4(w_out, g_woc, (gi - 262144) * 4);
    } else if (gi < 1048576) {
        const int i = (gi - 524288) * 4;
        const int r = i >> 9;
        const int k = i & (CH - 1);
        const int sr = (r & 1) ? (FFN + (r >> 1)) : (r >> 1);
        float4 v = *(const float4*)(w12 + (size_t)sr*CH + k);
        *(uint32_t*)(g_w12c + i)     = pack2bf(v.x, v.y);
        *(uint32_t*)(g_w12c + i + 2) = pack2bf(v.z, v.w);
    } else if (gi < 1048576 + FFN) {
        const int j = gi - 1048576;
        g_b12p[2*j]   = b12[j];
        g_b12p[2*j+1] = b12[FFN + j];
    }
}

// ---------------- merged adaLN + GroupNorm stats ----------------
__global__ __launch_bounds__(256) void k_adagn(
    const float* __restrict__ temb, const float* __restrict__ ada_w,
    const float* __restrict__ ada_b, const float* __restrict__ x) {
    const int blk = blockIdx.x;
    __shared__ float sh[CH];
    if (blk < 192) {
        const int b = blk / 12;
        for (int i = threadIdx.x; i < CH; i += 256) {
            float v = temb[b*CH + i];
            sh[i] = v / (1.f + __expf(-v));
        }
        __syncthreads();
        const int n = (blk % 12) * 256 + threadIdx.x;
        const float* wr = ada_w + (size_t)n * CH;
        float acc = 0.f;
        #pragma unroll 8
        for (int k = 0; k < CH; k++) acc += wr[k] * sh[k];
        g_ada[b*6*CH + n] = acc + ada_b[n];
    } else {
        const int bg = blk - 192;
        const float* p = x + (size_t)bg * 16 * NTOK;
        float s = 0.f, s2 = 0.f;
        for (int i = threadIdx.x; i < 16*NTOK; i += 256) {
            float v = p[i]; s += v; s2 += v*v;
        }
        #pragma unroll
        for (int o = 16; o; o >>= 1) {
            s  += __shfl_xor_sync(0xffffffffu, s,  o);
            s2 += __shfl_xor_sync(0xffffffffu, s2, o);
        }
        const int w = threadIdx.x >> 5, l = threadIdx.x & 31;
        if (l == 0) { sh[w] = s; sh[32 + w] = s2; }
        __syncthreads();
        if (threadIdx.x < 32) {
            s  = (threadIdx.x < 8) ? sh[threadIdx.x]      : 0.f;
            s2 = (threadIdx.x < 8) ? sh[32 + threadIdx.x] : 0.f;
            #pragma unroll
            for (int o = 4; o; o >>= 1) {
                s  += __shfl_xor_sync(0xffffffffu, s,  o);
                s2 += __shfl_xor_sync(0xffffffffu, s2, o);
            }
            if (threadIdx.x == 0) {
                const float inv = 1.f / (16.f * NTOK);
                float mu  = s * inv;
                float var = s2 * inv - mu * mu;
                g_stats[bg*2]     = mu;
                g_stats[bg*2 + 1] = rsqrtf(var + EPSV);
            }
        }
    }
}

// ---------------- fused GroupNorm-apply + transpose + RMSNorm(n1) + mod ----------------
#define HSTR 513
__global__ __launch_bounds__(512) void k_gnrms(
    const float* __restrict__ x, const float* __restrict__ gw, const float* __restrict__ gb,
    const float* __restrict__ n1w) {
    extern __shared__ float hb[];
    float* rms = hb + 32*HSTR;
    const int b  = blockIdx.y;
    const int n0 = blockIdx.x * 32;
    const int t  = threadIdx.x;
    for (int c0 = 0; c0 < CH; c0 += 64) {
        #pragma unroll
        for (int i = 0; i < 4; i++) {
            const int cl = (t >> 5) + i*16;
            const int nl = t & 31;
            const int c  = c0 + cl;
            const float mu = g_stats[(b*32 + (c >> 4))*2];
            const float rs = g_stats[(b*32 + (c >> 4))*2 + 1];
            const float v  = x[((size_t)b*CH + c)*NTOK + n0 + nl];
            hb[nl*HSTR + c] = (v - mu) * rs * gw[c] + gb[c];
        }
    }
    __syncthreads();
    {
        const int tok = t >> 4, l16 = t & 15;
        float ss = 0.f;
        #pragma unroll 8
        for (int i = 0; i < 32; i++) {
            const float v = hb[tok*HSTR + l16 + i*16];
            ss += v*v;
        }
        #pragma unroll
        for (int o = 1; o <= 8; o <<= 1) ss += __shfl_xor_sync(0xffffffffu, ss, o);
        if (l16 == 0) rms[tok] = rsqrtf(ss / (float)CH + EPSV);
    }
    __syncthreads();
    const int rowb = b*NTOK + n0;
    const float* shf = g_ada + b*6*CH;
    const float* scl = g_ada + b*6*CH + CH;
    #pragma unroll 4
    for (int i = 0; i < 16; i++) {
        const int idx = (t + i*512) * 2;
        const int tk = idx >> 9, c = idx & 511;
        const float h0 = hb[tk*HSTR + c], h1 = hb[tk*HSTR + c + 1];
        const float r = rms[tk];
        *(float2*)(g_h + (size_t)(rowb + tk)*CH + c) = make_float2(h0, h1);
        const float o0 = h0 * r * n1w[c]   * (1.f + scl[c])   + shf[c];
        const float o1 = h1 * r * n1w[c+1] * (1.f + scl[c+1]) + shf[c+1];
        *(uint32_t*)(g_hnb + (size_t)(rowb + tk)*CH + c) = pack2bf(o0, o1);
    }
}

// ---------------- RMSNorm + modulation -> bf16 (n2 path) ----------------
__global__ void k_rmsmod(const float* __restrict__ w, int shift_ch, int scale_ch) {
    const int row = blockIdx.x;
    const int b = row >> 10;
    const float* hp = g_h + (size_t)row * CH;
    const int t = threadIdx.x;
    float4 v = *(const float4*)(hp + t*4);
    float ss = v.x*v.x + v.y*v.y + v.z*v.z + v.w*v.w;
    #pragma unroll
    for (int o = 16; o; o >>= 1) ss += __shfl_xor_sync(0xffffffffu, ss, o);
    __shared__ float sh[4];
    if ((t & 31) == 0) sh[t >> 5] = ss;
    __syncthreads();
    ss = sh[0] + sh[1] + sh[2] + sh[3];
    const float r = rsqrtf(ss / (float)CH + EPSV);
    const float* shf = g_ada + b*6*CH + shift_ch*CH;
    const float* scl = g_ada + b*6*CH + scale_ch*CH;
    const int c = t*4;
    float o0 = v.x * r * w[c+0] * (1.f + scl[c+0]) + shf[c+0];
    float o1 = v.y * r * w[c+1] * (1.f + scl[c+1]) + shf[c+1];
    float o2 = v.z * r * w[c+2] * (1.f + scl[c+2]) + shf[c+2];
    float o3 = v.w * r * w[c+3] * (1.f + scl[c+3]) + shf[c+3];
    uint32_t* dp = (uint32_t*)(g_hnb + (size_t)row*CH + c);
    dp[0] = pack2bf(o0, o1);
    dp[1] = pack2bf(o2, o3);
}

// ---------------- BF16 GEMM (templated): K-chunk 64, 3-stage, 1 barrier/chunk ----------------
// MODE: 2 = g_h += gate*(acc+bias); 3 = fused swiglu; 4 = final out = x + h^T;
//       5 = fused QKV post: q/k rmsnorm+rope -> g_qkb, v -> transposed g_vtb
#define WSTR 36
#define STG_W (128*WSTR*2)
template<int MODE, int NN, int KK>
__global__ __launch_bounds__(256, 2) void k_gemm(
    const __nv_bfloat16* __restrict__ A, const __nv_bfloat16* __restrict__ W,
    const float* __restrict__ bias, float* __restrict__ Cf, uint32_t* __restrict__ Cb,
    __nv_bfloat16* __restrict__ Gb, const float* __restrict__ ada,
    const float* __restrict__ Xin, float* __restrict__ Oout,
    const float* __restrict__ qnw, const float* __restrict__ knw, int gch)
{
    extern __shared__ uint32_t sm[];
    const int tid  = threadIdx.x;
    const int lane = tid & 31;
    const int warp = tid >> 5;
    const int gid  = lane >> 2;
    const int tig  = lane & 3;
    const int row0 = (warp & 3) * 32;
    const int col0 = (warp >> 2) * 64;
    const int bm = blockIdx.y * 128, bn = blockIdx.x * 128;
    constexpr int KT = KK >> 6;
    const int lr   = lane & 7;
    const int sel8 = (lane >> 3) & 1;
    const int sel4 = (lane >> 4) & 1;

    const uint32_t sbase = (uint32_t)__cvta_generic_to_shared(sm);
    const uint32_t aoff  = ((row0 + sel8*8 + lr)*WSTR + sel4*4) * 4;
    const uint32_t boff  = ((col0 + sel8*8 + lr)*WSTR + sel4*4) * 4 + 128*WSTR*4;

    auto load_body = [&](int kt, int s) {
        uint32_t* As = sm + s * STG_W;
        uint32_t* Ws = As + 128*WSTR;
        const int k0 = kt << 6;
        #pragma unroll
        for (int i = 0; i < 4; i++) {
            const int lin = tid + i*256;
            const int r = lin >> 3, c = lin & 7;
            cpa16(As + r*WSTR + c*4, A + (size_t)(bm + r)*KK + k0 + c*8);
        }
        #pragma unroll
        for (int i = 0; i < 4; i++) {
            const int lin = tid + i*256;
            const int r = lin >> 3, c = lin & 7;
            cpa16(Ws + r*WSTR + c*4, W + (size_t)(bn + r)*KK + k0 + c*8);
        }
    };

    load_body(0, 0);
    asm volatile("cp.async.commit_group;\n");
    load_body(1, 1);
    asm volatile("cp.async.commit_group;\n");

    float acc[2][8][4];
    #pragma unroll
    for (int i = 0; i < 2; i++)
        #pragma unroll
        for (int j = 0; j < 8; j++)
            #pragma unroll
            for (int c = 0; c < 4; c++) acc[i][j][c] = 0.f;

    int stg = 0;
    #pragma unroll 2
    for (int kt = 0; kt < KT; kt++) {
        if (kt + 1 < KT) {
            asm volatile("cp.async.wait_group 1;\n");
        } else {
            asm volatile("cp.async.wait_group 0;\n");
        }
        __syncthreads();
        if (kt + 2 < KT) {
            int ns = stg + 2; if (ns >= 3) ns -= 3;
            load_body(kt + 2, ns);
            asm volatile("cp.async.commit_group;\n");
        }
        const uint32_t stb = sbase + (uint32_t)(stg * STG_W * 4);
        #pragma unroll
        for (int kk = 0; kk < 4; kk++) {
            const uint32_t kb = kk * 32;
            uint32_t af[2][4], bf[8][2];
            const uint32_t aa = stb + aoff + kb;
            ldm4(aa,             af[0][0], af[0][1], af[0][2], af[0][3]);
            ldm4(aa + 16*WSTR*4, af[1][0], af[1][1], af[1][2], af[1][3]);
            const uint32_t bb = stb + boff + kb;
            #pragma unroll
            for (int nt2 = 0; nt2 < 4; nt2++) {
                ldm4(bb + nt2*16*WSTR*4,
                     bf[2*nt2][0], bf[2*nt2+1][0], bf[2*nt2][1], bf[2*nt2+1][1]);
            }
            #pragma unroll
            for (int mt = 0; mt < 2; mt++)
                #pragma unroll
                for (int nt = 0; nt < 8; nt++)
                    MMA_BF16(acc[mt][nt], af[mt], bf[nt]);
        }
        if (++stg == 3) stg = 0;
    }

    if (MODE == 5) {
        const int gc0 = bn + col0;       // head-aligned 64-col span
        if (gc0 < 1024) {
            // ---- q or k: rmsnorm + rope, write g_qkb ----
            const bool isk = gc0 >= 512;
            const int head = (gc0 & 511) >> 6;
            const float* wn_ = isk ? knw : qnw;
            const float qs = isk ? 1.f : 0.125f;
            #pragma unroll
            for (int mt = 0; mt < 2; mt++) {
                const int row = bm + row0 + mt*16 + gid;
                const int n  = row & 1023;
                const int n8 = n + 8;            // row+8 token (same 128-block)
                float v0[8], v1[8], u0[8], u1[8];
                float ss0 = 0.f, ss1 = 0.f;
                #pragma unroll
                for (int nt = 0; nt < 8; nt++) {
                    const int col = gc0 + nt*8 + tig*2;
                    const float b0 = bias[col], b1 = bias[col+1];
                    v0[nt] = acc[mt][nt][0] + b0; v1[nt] = acc[mt][nt][1] + b1;
                    u0[nt] = acc[mt][nt][2] + b0; u1[nt] = acc[mt][nt][3] + b1;
                    ss0 += v0[nt]*v0[nt] + v1[nt]*v1[nt];
                    ss1 += u0[nt]*u0[nt] + u1[nt]*u1[nt];
                }
                #pragma unroll
                for (int o = 1; o <= 2; o <<= 1) {
                    ss0 += __shfl_xor_sync(0xffffffffu, ss0, o);
                    ss1 += __shfl_xor_sync(0xffffffffu, ss1, o);
                }
                const float r0 = rsqrtf(ss0 / 64.f + EPSV);
                const float r1 = rsqrtf(ss1 / 64.f + EPSV);
                #pragma unroll
                for (int nt = 0; nt < 8; nt++) {
                    const int j = nt*8 + tig*2;
                    const float w0 = wn_[j], w1 = wn_[j+1];
                    const float a0 = v0[nt]*r0*w0, a1 = v1[nt]*r0*w1;
                    const float c0 = u0[nt]*r1*w0, c1 = u1[nt]*r1*w1;
                    const int half = (j >= 32);
                    const int idx  = (half ? (j - 32) : j) >> 1;
                    const float freq = exp2f(-(float)idx * (13.287712379549449f / 16.f));
                    const float f0 = (half ? (float)(n  & 31) : (float)(n  >> 5)) * freq;
                    const float f1 = (half ? (float)(n8 & 31) : (float)(n8 >> 5)) * freq;
                    const float cf0 = cosf(f0), sf0 = sinf(f0);
                    const float cf1 = cosf(f1), sf1 = sinf(f1);
                    const float qa = (a0*cf0 - a1*sf0) * qs, qb = (a1*cf0 + a0*sf0) * qs;
                    const float ka = (c0*cf1 - c1*sf1) * qs, kb = (c1*cf1 + c0*sf1) * qs;
                    const size_t w_ = (size_t)row*512 + (isk ? 256 : 0) + head*32 + nt*4 + tig;
                    Cb[w_]       = pack2bf(qa, qb);
                    Cb[w_ + 8*512] = pack2bf(ka, kb);
                }
            }
        } else {
            // ---- v: stage bf16 tile in smem, write transposed to g_vtb ----
            __nv_bfloat16* vs = (__nv_bfloat16*)sm;       // 128 x 136
            __syncthreads();                               // all warps done reading stages
            #pragma unroll
            for (int mt = 0; mt < 2; mt++) {
                const int rl = row0 + mt*16 + gid;
                #pragma unroll
                for (int nt = 0; nt < 8; nt++) {
                    const int cl = col0 + nt*8 + tig*2;
                    const int col = bn + cl;
                    const float b0 = bias[col], b1 = bias[col+1];
                    *(uint32_t*)(vs + rl*136 + cl)     = pack2bf(acc[mt][nt][0]+b0, acc[mt][nt][1]+b1);
                    *(uint32_t*)(vs + (rl+8)*136 + cl) = pack2bf(acc[mt][nt][2]+b0, acc[mt][nt][3]+b1);
                }
            }
            __syncthreads();
            const int b  = bm >> 10;
            const int nb = bm & 1023;
            const int hbase = (bn - 1024) >> 6;
            #pragma unroll
            for (int i = 0; i < 8; i++) {
                const int lin = tid + i*256;     // 2048
                const int cl = lin >> 4;         // 0..127
                const int t8 = (lin & 15) * 8;
                const int head = hbase + (cl >> 6);
                const int d = cl & 63;
                uint16_t v[8];
                #pragma unroll
                for (int jx = 0; jx < 8; jx++)
                    v[jx] = *(const uint16_t*)(vs + (t8 + jx)*136 + cl);
                uint4 o;
                o.x = (uint32_t)v[0] | ((uint32_t)v[1] << 16);
                o.y = (uint32_t)v[2] | ((uint32_t)v[3] << 16);
                o.z = (uint32_t)v[4] | ((uint32_t)v[5] << 16);
                o.w = (uint32_t)v[6] | ((uint32_t)v[7] << 16);
                *(uint4*)(g_vtb + ((size_t)(b*8 + head)*64 + d)*NTOK + nb + t8) = o;
            }
        }
        return;
    }

    if (MODE == 4) {
        __syncthreads();
        float* hs = (float*)sm;
        #pragma unroll
        for (int mt = 0; mt < 2; mt++) {
            const int rl = row0 + mt*16 + gid;
            const int row = bm + rl;
            const int b = row >> 10;
            const float* gp = ada + b*6*CH + gch*CH;
            #pragma unroll
            for (int nt = 0; nt < 8; nt++) {
                const int cl = col0 + nt*8 + tig*2;
                const int col = bn + cl;
                const float b0 = bias[col], b1 = bias[col+1];
                float2 h0 = *(float2*)(Cf + (size_t)row*NN + col);
                float2 h1 = *(float2*)(Cf + (size_t)(row+8)*NN + col);
                hs[rl*132 + cl]       = h0.x + gp[col]  *(acc[mt][nt][0] + b0);
                hs[rl*132 + cl+1]     = h0.y + gp[col+1]*(acc[mt][nt][1] + b1);
                hs[(rl+8)*132 + cl]   = h1.x + gp[col]  *(acc[mt][nt][2] + b0);
                hs[(rl+8)*132 + cl+1] = h1.y + gp[col+1]*(acc[mt][nt][3] + b1);
            }
        }
        __syncthreads();
        const int b = bm >> 10;
        const int nbase = bm & 1023;
        #pragma unroll
        for (int i = 0; i < 16; i++) {
            const int lin = tid + i*256;
            const int cr = lin >> 5, g = lin & 31;
            const size_t oidx = ((size_t)b*CH + bn + cr)*NTOK + nbase + g*4;
            float4 xs = *(const float4*)(Xin + oidx);
            xs.x += hs[(g*4+0)*132 + cr];
            xs.y += hs[(g*4+1)*132 + cr];
            xs.z += hs[(g*4+2)*132 + cr];
            xs.w += hs[(g*4+3)*132 + cr];
            *(float4*)(Oout + oidx) = xs;
        }
        return;
    }

    #pragma unroll
    for (int mt = 0; mt < 2; mt++) {
        const int row = bm + row0 + mt*16 + gid;
        const int b   = row >> 10;
        const float* gp = ada + b*6*CH + gch*CH;
        #pragma unroll
        for (int nt = 0; nt < 8; nt++) {
            const int col = bn + col0 + nt*8 + tig*2;
            const float b0 = bias[col], b1 = bias[col+1];
            float v00 = acc[mt][nt][0] + b0, v01 = acc[mt][nt][1] + b1;
            float v10 = acc[mt][nt][2] + b0, v11 = acc[mt][nt][3] + b1;
            if (MODE == 2) {
                const float gg0 = gp[col], gg1 = gp[col+1];
                float2 h0 = *(float2*)(Cf + (size_t)row*NN + col);
                float2 h1 = *(float2*)(Cf + (size_t)(row+8)*NN + col);
                h0.x += gg0*v00; h0.y += gg1*v01;
                h1.x += gg0*v10; h1.y += gg1*v11;
                *(float2*)(Cf + (size_t)row*NN + col)     = h0;
                *(float2*)(Cf + (size_t)(row+8)*NN + col) = h1;
            } else {
                const int j = col >> 1;
                const float s0 = (v00 / (1.f + __expf(-v00))) * v01;
                const float s1 = (v10 / (1.f + __expf(-v10))) * v11;
                Gb[(size_t)row*(NN>>1) + j]     = __float2bfloat16(s0);
                Gb[(size_t)(row+8)*(NN>>1) + j] = __float2bfloat16(s1);
            }
        }
    }
}

// ---------------- flash attention: 3-stage K/V ring, one sync per chunk ----------------
#define QSTR 36
__global__ __launch_bounds__(256) void k_attn_mma() {
    extern __shared__ uint32_t smw[];
    const int bh = blockIdx.x;
    const int b = bh >> 3, hh = bh & 7;
    const int q0 = blockIdx.y * 128;
    const int tid = threadIdx.x, lane = tid & 31, warp = tid >> 5;
    const int lr = lane & 7, sel8 = (lane >> 3) & 1, sel4 = (lane >> 4) & 1;
    const int gid = lane >> 2, tig = lane & 3;
    const __nv_bfloat16* qk = g_qkb + (size_t)b * NTOK * 1024;
    const __nv_bfloat16* vt = g_vtb + (size_t)bh * 64 * NTOK;

    const uint32_t sbase = (uint32_t)__cvta_generic_to_shared(smw);
    const uint32_t qoff  = ((warp*16 + sel8*8 + lr)*QSTR + sel4*4) * 4;
    const uint32_t kvoff = ((sel8*8 + lr)*QSTR + sel4*4) * 4;

    #pragma unroll
    for (int i = 0; i < 4; i++) {
        const int lin = tid + i*256;
        const int r = lin >> 3, c4 = lin & 7;
        cpa16(smw + r*QSTR + c4*4, qk + (size_t)(q0 + r)*1024 + hh*64 + c4*8);
    }
    asm volatile("cp.async.commit_group;\n");
    asm volatile("cp.async.wait_group 0;\n");
    __syncthreads();
    uint32_t qf[4][4];
    #pragma unroll
    for (int kk = 0; kk < 4; kk++)
        ldm4(sbase + qoff + kk*32, qf[kk][0], qf[kk][1], qf[kk][2], qf[kk][3]);
    __syncthreads();

    auto load_kv = [&](int kc, int s) {
        uint32_t* Ks = smw + s*128*QSTR;
        uint32_t* Vs = Ks + 64*QSTR;
        #pragma unroll
        for (int i = 0; i < 2; i++) {
            const int lin = tid + i*256;
            const int r = lin >> 3, c4 = lin & 7;
            cpa16(Ks + r*QSTR + c4*4, qk + (size_t)(kc + r)*1024 + 512 + hh*64 + c4*8);
            cpa16(Vs + r*QSTR + c4*4, vt + (size_t)r*NTOK + kc + c4*8);
        }
    };

    float l0 = 0.f, l1 = 0.f;
    float oacc[8][4];
    #pragma unroll
    for (int nt = 0; nt < 8; nt++)
        #pragma unroll
        for (int c = 0; c < 4; c++) oacc[nt][c] = 0.f;

    load_kv(0, 0);
    asm volatile("cp.async.commit_group;\n");
    load_kv(64, 1);
    asm volatile("cp.async.commit_group;\n");

    int stg = 0;
    for (int it = 0; it < NTOK/64; it++) {
        if (it + 2 < NTOK/64) {
            asm volatile("cp.async.wait_group 1;\n");
        } else {
            asm volatile("cp.async.wait_group 0;\n");
        }
        __syncthreads();
        if (it + 2 < NTOK/64) {
            int ns = stg + 2; if (ns >= 3) ns -= 3;
            load_kv((it+2)*64, ns);
            asm volatile("cp.async.commit_group;\n");
        }
        const uint32_t kbase = sbase + (uint32_t)(stg*128*QSTR*4);
        const uint32_t vbase = kbase + 64*QSTR*4;

        float sacc[8][4];
        #pragma unroll
        for (int nt = 0; nt < 8; nt++)
            #pragma unroll
            for (int c = 0; c < 4; c++) sacc[nt][c] = 0.f;
        #pragma unroll
        for (int kk = 0; kk < 4; kk++) {
            uint32_t bf[8][2];
            const uint32_t kb = kbase + kvoff + kk*32;
            #pragma unroll
            for (int nt2 = 0; nt2 < 4; nt2++)
                ldm4(kb + nt2*16*QSTR*4,
                     bf[2*nt2][0], bf[2*nt2+1][0], bf[2*nt2][1], bf[2*nt2+1][1]);
            #pragma unroll
            for (int nt = 0; nt < 8; nt++)
                MMA_BF16(sacc[nt], qf[kk], bf[nt]);
        }

        uint32_t pa[8], pb[8];
        #pragma unroll
        for (int nt = 0; nt < 8; nt++) {
            const float p00 = __expf(sacc[nt][0] - 8.f);
            const float p01 = __expf(sacc[nt][1] - 8.f);
            const float p10 = __expf(sacc[nt][2] - 8.f);
            const float p11 = __expf(sacc[nt][3] - 8.f);
            l0 += p00 + p01;  l1 += p10 + p11;
            pa[nt] = pack2bf(p00, p01);
            pb[nt] = pack2bf(p10, p11);
        }

        #pragma unroll
        for (int kk = 0; kk < 4; kk++) {
            uint32_t af[4] = { pa[2*kk], pb[2*kk], pa[2*kk+1], pb[2*kk+1] };
            uint32_t bf[8][2];
            const uint32_t vb = vbase + kvoff + kk*32;
            #pragma unroll
            for (int nt2 = 0; nt2 < 4; nt2++)
                ldm4(vb + nt2*16*QSTR*4,
                     bf[2*nt2][0], bf[2*nt2+1][0], bf[2*nt2][1], bf[2*nt2+1][1]);
            #pragma unroll
            for (int nt = 0; nt < 8; nt++)
                MMA_BF16(oacc[nt], af, bf[nt]);
        }
        if (++stg == 3) stg = 0;
    }

    #pragma unroll
    for (int o = 1; o <= 2; o <<= 1) {
        l0 += __shfl_xor_sync(0xffffffffu, l0, o);
        l1 += __shfl_xor_sync(0xffffffffu, l1, o);
    }
    const float inv0 = 1.f / l0, inv1 = 1.f / l1;
    uint32_t* ow = (uint32_t*)g_attb;
    const size_t row = (size_t)b*NTOK + q0 + warp*16 + gid;
    #pragma unroll
    for (int nt = 0; nt < 8; nt++) {
        const int cw = hh*32 + nt*4 + tig;
        ow[row*256 + cw]     = pack2bf(oacc[nt][0]*inv0, oacc[nt][1]*inv0);
        ow[(row+8)*256 + cw] = pack2bf(oacc[nt][2]*inv1, oacc[nt][3]*inv1);
    }
}

// ---------------- launcher ----------------
extern "C" void kernel_launch(void* const* d_in, const int* in_sizes, int n_in,
                              void* d_out, int out_size) {
    const float* x      = (const float*)d_in[0];
    const float* temb   = (const float*)d_in[1];
    const float* gn_w   = (const float*)d_in[2];
    const float* gn_b   = (const float*)d_in[3];
    const float* ada_w  = (const float*)d_in[4];
    const float* ada_b  = (const float*)d_in[5];
    const float* n1_w   = (const float*)d_in[6];
    const float* n2_w   = (const float*)d_in[7];
    const float* qkv_w  = (const float*)d_in[8];
    const float* qkv_b  = (const float*)d_in[9];
    const float* qn_w   = (const float*)d_in[10];
    const float* kn_w   = (const float*)d_in[11];
    const float* proj_w = (const float*)d_in[12];
    const float* proj_b = (const float*)d_in[13];
    const float* w12    = (const float*)d_in[14];
    const float* b12    = (const float*)d_in[15];
    const float* w_out  = (const float*)d_in[16];
    const float* b_out  = (const float*)d_in[17];
    float* out = (float*)d_out;

    float *p_h, *p_ada, *p_b12p;
    __nv_bfloat16 *p_hnb, *p_qkb, *p_attb, *p_gateb;
    __nv_bfloat16 *p_wqkv, *p_wproj, *p_w12c, *p_woc;
    cudaGetSymbolAddress((void**)&p_h,     g_h);
    cudaGetSymbolAddress((void**)&p_ada,   g_ada);
    cudaGetSymbolAddress((void**)&p_b12p,  g_b12p);
    cudaGetSymbolAddress((void**)&p_hnb,   g_hnb);
    cudaGetSymbolAddress((void**)&p_qkb,   g_qkb);
    cudaGetSymbolAddress((void**)&p_attb,  g_attb);
    cudaGetSymbolAddress((void**)&p_gateb, g_gateb);
    cudaGetSymbolAddress((void**)&p_wqkv,  g_wqkv);
    cudaGetSymbolAddress((void**)&p_wproj, g_wproj);
    cudaGetSymbolAddress((void**)&p_w12c,  g_w12c);
    cudaGetSymbolAddress((void**)&p_woc,   g_woc);

    const int gemm_smem  = 3*STG_W*4;         // 110592 B
    const int attn_smem  = 3*128*QSTR*4;      // 55296 B
    const int gnrms_smem = (32*HSTR + 32)*4;  // 65792 B
    cudaFuncSetAttribute(k_gemm<5,1536,512>, cudaFuncAttributeMaxDynamicSharedMemorySize, gemm_smem);
    cudaFuncSetAttribute(k_gemm<2,512,512>,  cudaFuncAttributeMaxDynamicSharedMemorySize, gemm_smem);
    cudaFuncSetAttribute(k_gemm<3,4096,512>, cudaFuncAttributeMaxDynamicSharedMemorySize, gemm_smem);
    cudaFuncSetAttribute(k_gemm<4,512,2048>, cudaFuncAttributeMaxDynamicSharedMemorySize, gemm_smem);
    cudaFuncSetAttribute(k_attn_mma, cudaFuncAttributeMaxDynamicSharedMemorySize, attn_smem);
    cudaFuncSetAttribute(k_gnrms,    cudaFuncAttributeMaxDynamicSharedMemorySize, gnrms_smem);

    k_cvtall <<<(1048576 + FFN + 255)/256, 256>>>(qkv_w, proj_w, w_out, w12, b12);

    // adaLN + GroupNorm stats (merged) + fused gn-apply/rmsnorm/mod
    k_adagn  <<<192 + BDIM*32, 256>>>(temb, ada_w, ada_b, x);
    k_gnrms  <<<dim3(NTOK/32, BDIM), 512, gnrms_smem>>>(x, gn_w, gn_b, n1_w);

    // attention branch (QKV gemm with fused rope/rmsnorm/v-transpose epilogue)
    k_gemm<5,1536,512><<<dim3(1536/128, NT/128), 256, gemm_smem>>>(
        p_hnb, p_wqkv, qkv_b, nullptr, (uint32_t*)p_qkb, nullptr, p_ada,
        nullptr, nullptr, qn_w, kn_w, 0);
    k_attn_mma<<<dim3(BDIM*NHEADS, NTOK/128), 256, attn_smem>>>();
    k_gemm<2,512,512><<<dim3(512/128, NT/128), 256, gemm_smem>>>(
        p_attb, p_wproj, proj_b, p_h, nullptr, nullptr, p_ada,
        nullptr, nullptr, nullptr, nullptr, 2);

    // FFN branch
    k_rmsmod <<<NT, 128>>>(n2_w, 3, 4);
    k_gemm<3,4096,512><<<dim3(4096/128, NT/128), 256, gemm_smem>>>(
        p_hnb, p_w12c, p_b12p, nullptr, nullptr, p_gateb, p_ada,
        nullptr, nullptr, nullptr, nullptr, 0);
    k_gemm<4,512,2048><<<dim3(512/128, NT/128), 256, gemm_smem>>>(
        p_gateb, p_woc, b_out, p_h, nullptr, nullptr, p_ada,
        x, out, nullptr, nullptr, 5);
}

// round 15
// speedup vs baseline: 1.0636x; 1.0152x over previous
#include <cuda_runtime.h>
#include <cuda_bf16.h>
#include <cstdint>

// ---------------- problem constants ----------------
#define BDIM   16
#define CH     512
#define NTOK   1024
#define NT     (BDIM*NTOK)
#define NHEADS 8
#define HDIM   64
#define FFN    2048
#define EPSV   1e-6f

// ---------------- scratch ----------------
__device__ float g_ada [BDIM*6*CH];
__device__ float g_h   [NT*CH];
__device__ float g_stats[BDIM*32*2];
__device__ float g_b12p[2*FFN];
__device__ float2 g_rope[32*16];            // (cos,sin) for pos in 0..31, idx in 0..15
__device__ __nv_bfloat16 g_hnb [NT*CH];
__device__ __nv_bfloat16 g_qkb [NT*2*CH];
__device__ __nv_bfloat16 g_vtb [BDIM*NHEADS*HDIM*NTOK];
__device__ __nv_bfloat16 g_attb[NT*CH];
__device__ __nv_bfloat16 g_gateb[NT*FFN];
__device__ __nv_bfloat16 g_wqkv [3*CH*CH];
__device__ __nv_bfloat16 g_wproj[CH*CH];
__device__ __nv_bfloat16 g_w12c [2*FFN*CH];
__device__ __nv_bfloat16 g_woc  [CH*FFN];

// ---------------- helpers ----------------
__device__ __forceinline__ uint32_t pack2bf(float lo, float hi) {
    uint32_t r;
    asm("cvt.rn.bf16x2.f32 %0, %1, %2;" : "=r"(r) : "f"(hi), "f"(lo));
    return r;
}
__device__ __forceinline__ void cpa16(void* s, const void* g) {
    uint32_t sa = (uint32_t)__cvta_generic_to_shared(s);
    asm volatile("cp.async.cg.shared.global [%0], [%1], 16;\n" :: "r"(sa), "l"(g));
}
__device__ __forceinline__ void ldm4(uint32_t addr, uint32_t& r0, uint32_t& r1,
                                     uint32_t& r2, uint32_t& r3) {
    asm volatile("ldmatrix.sync.aligned.m8n8.x4.shared.b16 {%0,%1,%2,%3}, [%4];"
                 : "=r"(r0), "=r"(r1), "=r"(r2), "=r"(r3) : "r"(addr));
}
#define MMA_BF16(d, a, b) \
    asm volatile("mma.sync.aligned.m16n8k16.row.col.f32.bf16.bf16.f32 " \
                 "{%0,%1,%2,%3}, {%4,%5,%6,%7}, {%8,%9}, {%0,%1,%2,%3};" \
                 : "+f"(d[0]), "+f"(d[1]), "+f"(d[2]), "+f"(d[3]) \
                 : "r"(a[0]), "r"(a[1]), "r"(a[2]), "r"(a[3]), "r"(b[0]), "r"(b[1]))

// ---------------- merged weight conversion + rope table ----------------
__device__ __forceinline__ void cvt4(const float* __restrict__ s,
                                     __nv_bfloat16* __restrict__ d, int i) {
    float4 v = *(const float4*)(s + i);
    *(uint32_t*)(d + i)     = pack2bf(v.x, v.y);
    *(uint32_t*)(d + i + 2) = pack2bf(v.z, v.w);
}
__global__ void k_cvtall(const float* __restrict__ qkv_w, const float* __restrict__ proj_w,
                         const float* __restrict__ w_out, const float* __restrict__ w12,
                         const float* __restrict__ b12) {
    const int gi = blockIdx.x * blockDim.x + threadIdx.x;
    if (gi < 196608) {
        cvt4(qkv_w, g_wqkv, gi * 4);
    } else if (gi < 262144) {
        cvt4(proj_w, g_wproj, (gi - 196608) * 4);
    } else if (gi < 524288) {
        cvt4(w_out, g_woc, (gi - 262144) * 4);
    } else if (gi < 1048576) {
        const int i = (gi - 524288) * 4;
        const int r = i >> 9;
        const int k = i & (CH - 1);
        const int sr = (r & 1) ? (FFN + (r >> 1)) : (r >> 1);
        float4 v = *(const float4*)(w12 + (size_t)sr*CH + k);
        *(uint32_t*)(g_w12c + i)     = pack2bf(v.x, v.y);
        *(uint32_t*)(g_w12c + i + 2) = pack2bf(v.z, v.w);
    } else if (gi < 1048576 + FFN) {
        const int j = gi - 1048576;
        g_b12p[2*j]   = b12[j];
        g_b12p[2*j+1] = b12[FFN + j];
    } else if (gi < 1048576 + FFN + 512) {
        const int e = gi - 1048576 - FFN;       // pos*16 + idx
        const int pos = e >> 4, idx = e & 15;
        const float freq = exp2f(-(float)idx * (13.287712379549449f / 16.f));
        const float f = (float)pos * freq;
        g_rope[e] = make_float2(cosf(f), sinf(f));
    }
}

// ---------------- merged adaLN + GroupNorm stats ----------------
__global__ __launch_bounds__(256) void k_adagn(
    const float* __restrict__ temb, const float* __restrict__ ada_w,
    const float* __restrict__ ada_b, const float* __restrict__ x) {
    const int blk = blockIdx.x;
    __shared__ float sh[CH];
    if (blk < 192) {
        const int b = blk / 12;
        for (int i = threadIdx.x; i < CH; i += 256) {
            float v = temb[b*CH + i];
            sh[i] = v / (1.f + __expf(-v));
        }
        __syncthreads();
        const int n = (blk % 12) * 256 + threadIdx.x;
        const float* wr = ada_w + (size_t)n * CH;
        float acc = 0.f;
        #pragma unroll 8
        for (int k = 0; k < CH; k++) acc += wr[k] * sh[k];
        g_ada[b*6*CH + n] = acc + ada_b[n];
    } else {
        const int bg = blk - 192;
        const float* p = x + (size_t)bg * 16 * NTOK;
        float s = 0.f, s2 = 0.f;
        for (int i = threadIdx.x; i < 16*NTOK; i += 256) {
            float v = p[i]; s += v; s2 += v*v;
        }
        #pragma unroll
        for (int o = 16; o; o >>= 1) {
            s  += __shfl_xor_sync(0xffffffffu, s,  o);
            s2 += __shfl_xor_sync(0xffffffffu, s2, o);
        }
        const int w = threadIdx.x >> 5, l = threadIdx.x & 31;
        if (l == 0) { sh[w] = s; sh[32 + w] = s2; }
        __syncthreads();
        if (threadIdx.x < 32) {
            s  = (threadIdx.x < 8) ? sh[threadIdx.x]      : 0.f;
            s2 = (threadIdx.x < 8) ? sh[32 + threadIdx.x] : 0.f;
            #pragma unroll
            for (int o = 4; o; o >>= 1) {
                s  += __shfl_xor_sync(0xffffffffu, s,  o);
                s2 += __shfl_xor_sync(0xffffffffu, s2, o);
            }
            if (threadIdx.x == 0) {
                const float inv = 1.f / (16.f * NTOK);
                float mu  = s * inv;
                float var = s2 * inv - mu * mu;
                g_stats[bg*2]     = mu;
                g_stats[bg*2 + 1] = rsqrtf(var + EPSV);
            }
        }
    }
}

// ---------------- fused GroupNorm-apply + transpose + RMSNorm(n1) + mod ----------------
#define HSTR 513
__global__ __launch_bounds__(512) void k_gnrms(
    const float* __restrict__ x, const float* __restrict__ gw, const float* __restrict__ gb,
    const float* __restrict__ n1w) {
    extern __shared__ float hb[];
    float* rms = hb + 32*HSTR;
    const int b  = blockIdx.y;
    const int n0 = blockIdx.x * 32;
    const int t  = threadIdx.x;
    for (int c0 = 0; c0 < CH; c0 += 64) {
        #pragma unroll
        for (int i = 0; i < 4; i++) {
            const int cl = (t >> 5) + i*16;
            const int nl = t & 31;
            const int c  = c0 + cl;
            const float mu = g_stats[(b*32 + (c >> 4))*2];
            const float rs = g_stats[(b*32 + (c >> 4))*2 + 1];
            const float v  = x[((size_t)b*CH + c)*NTOK + n0 + nl];
            hb[nl*HSTR + c] = (v - mu) * rs * gw[c] + gb[c];
        }
    }
    __syncthreads();
    {
        const int tok = t >> 4, l16 = t & 15;
        float ss = 0.f;
        #pragma unroll 8
        for (int i = 0; i < 32; i++) {
            const float v = hb[tok*HSTR + l16 + i*16];
            ss += v*v;
        }
        #pragma unroll
        for (int o = 1; o <= 8; o <<= 1) ss += __shfl_xor_sync(0xffffffffu, ss, o);
        if (l16 == 0) rms[tok] = rsqrtf(ss / (float)CH + EPSV);
    }
    __syncthreads();
    const int rowb = b*NTOK + n0;
    const float* shf = g_ada + b*6*CH;
    const float* scl = g_ada + b*6*CH + CH;
    #pragma unroll 4
    for (int i = 0; i < 16; i++) {
        const int idx = (t + i*512) * 2;
        const int tk = idx >> 9, c = idx & 511;
        const float h0 = hb[tk*HSTR + c], h1 = hb[tk*HSTR + c + 1];
        const float r = rms[tk];
        *(float2*)(g_h + (size_t)(rowb + tk)*CH + c) = make_float2(h0, h1);
        const float o0 = h0 * r * n1w[c]   * (1.f + scl[c])   + shf[c];
        const float o1 = h1 * r * n1w[c+1] * (1.f + scl[c+1]) + shf[c+1];
        *(uint32_t*)(g_hnb + (size_t)(rowb + tk)*CH + c) = pack2bf(o0, o1);
    }
}

// ---------------- RMSNorm + modulation -> bf16 (n2 path) ----------------
__global__ void k_rmsmod(const float* __restrict__ w, int shift_ch, int scale_ch) {
    const int row = blockIdx.x;
    const int b = row >> 10;
    const float* hp = g_h + (size_t)row * CH;
    const int t = threadIdx.x;
    float4 v = *(const float4*)(hp + t*4);
    float ss = v.x*v.x + v.y*v.y + v.z*v.z + v.w*v.w;
    #pragma unroll
    for (int o = 16; o; o >>= 1) ss += __shfl_xor_sync(0xffffffffu, ss, o);
    __shared__ float sh[4];
    if ((t & 31) == 0) sh[t >> 5] = ss;
    __syncthreads();
    ss = sh[0] + sh[1] + sh[2] + sh[3];
    const float r = rsqrtf(ss / (float)CH + EPSV);
    const float* shf = g_ada + b*6*CH + shift_ch*CH;
    const float* scl = g_ada + b*6*CH + scale_ch*CH;
    const int c = t*4;
    float o0 = v.x * r * w[c+0] * (1.f + scl[c+0]) + shf[c+0];
    float o1 = v.y * r * w[c+1] * (1.f + scl[c+1]) + shf[c+1];
    float o2 = v.z * r * w[c+2] * (1.f + scl[c+2]) + shf[c+2];
    float o3 = v.w * r * w[c+3] * (1.f + scl[c+3]) + shf[c+3];
    uint32_t* dp = (uint32_t*)(g_hnb + (size_t)row*CH + c);
    dp[0] = pack2bf(o0, o1);
    dp[1] = pack2bf(o2, o3);
}

// ---------------- BF16 GEMM (templated): K-chunk 64, 3-stage, 1 barrier/chunk ----------------
// MODE: 2 = g_h += gate*(acc+bias); 3 = fused swiglu; 4 = final out = x + h^T;
//       5 = fused QKV post: q/k rmsnorm+rope(table) -> g_qkb, v -> transposed g_vtb
#define WSTR 36
#define STG_W (128*WSTR*2)
template<int MODE, int NN, int KK>
__global__ __launch_bounds__(256, 2) void k_gemm(
    const __nv_bfloat16* __restrict__ A, const __nv_bfloat16* __restrict__ W,
    const float* __restrict__ bias, float* __restrict__ Cf, uint32_t* __restrict__ Cb,
    __nv_bfloat16* __restrict__ Gb, const float* __restrict__ ada,
    const float* __restrict__ Xin, float* __restrict__ Oout,
    const float* __restrict__ qnw, const float* __restrict__ knw, int gch)
{
    extern __shared__ uint32_t sm[];
    const int tid  = threadIdx.x;
    const int lane = tid & 31;
    const int warp = tid >> 5;
    const int gid  = lane >> 2;
    const int tig  = lane & 3;
    const int row0 = (warp & 3) * 32;
    const int col0 = (warp >> 2) * 64;
    const int bm = blockIdx.y * 128, bn = blockIdx.x * 128;
    constexpr int KT = KK >> 6;
    const int lr   = lane & 7;
    const int sel8 = (lane >> 3) & 1;
    const int sel4 = (lane >> 4) & 1;

    const uint32_t sbase = (uint32_t)__cvta_generic_to_shared(sm);
    const uint32_t aoff  = ((row0 + sel8*8 + lr)*WSTR + sel4*4) * 4;
    const uint32_t boff  = ((col0 + sel8*8 + lr)*WSTR + sel4*4) * 4 + 128*WSTR*4;

    auto load_body = [&](int kt, int s) {
        uint32_t* As = sm + s * STG_W;
        uint32_t* Ws = As + 128*WSTR;
        const int k0 = kt << 6;
        #pragma unroll
        for (int i = 0; i < 4; i++) {
            const int lin = tid + i*256;
            const int r = lin >> 3, c = lin & 7;
            cpa16(As + r*WSTR + c*4, A + (size_t)(bm + r)*KK + k0 + c*8);
        }
        #pragma unroll
        for (int i = 0; i < 4; i++) {
            const int lin = tid + i*256;
            const int r = lin >> 3, c = lin & 7;
            cpa16(Ws + r*WSTR + c*4, W + (size_t)(bn + r)*KK + k0 + c*8);
        }
    };

    load_body(0, 0);
    asm volatile("cp.async.commit_group;\n");
    load_body(1, 1);
    asm volatile("cp.async.commit_group;\n");

    float acc[2][8][4];
    #pragma unroll
    for (int i = 0; i < 2; i++)
        #pragma unroll
        for (int j = 0; j < 8; j++)
            #pragma unroll
            for (int c = 0; c < 4; c++) acc[i][j][c] = 0.f;

    int stg = 0;
    #pragma unroll 2
    for (int kt = 0; kt < KT; kt++) {
        if (kt + 1 < KT) {
            asm volatile("cp.async.wait_group 1;\n");
        } else {
            asm volatile("cp.async.wait_group 0;\n");
        }
        __syncthreads();
        if (kt + 2 < KT) {
            int ns = stg + 2; if (ns >= 3) ns -= 3;
            load_body(kt + 2, ns);
            asm volatile("cp.async.commit_group;\n");
        }
        const uint32_t stb = sbase + (uint32_t)(stg * STG_W * 4);
        #pragma unroll
        for (int kk = 0; kk < 4; kk++) {
            const uint32_t kb = kk * 32;
            uint32_t af[2][4], bf[8][2];
            const uint32_t aa = stb + aoff + kb;
            ldm4(aa,             af[0][0], af[0][1], af[0][2], af[0][3]);
            ldm4(aa + 16*WSTR*4, af[1][0], af[1][1], af[1][2], af[1][3]);
            const uint32_t bb = stb + boff + kb;
            #pragma unroll
            for (int nt2 = 0; nt2 < 4; nt2++) {
                ldm4(bb + nt2*16*WSTR*4,
                     bf[2*nt2][0], bf[2*nt2+1][0], bf[2*nt2][1], bf[2*nt2+1][1]);
            }
            #pragma unroll
            for (int mt = 0; mt < 2; mt++)
                #pragma unroll
                for (int nt = 0; nt < 8; nt++)
                    MMA_BF16(acc[mt][nt], af[mt], bf[nt]);
        }
        if (++stg == 3) stg = 0;
    }

    if (MODE == 5) {
        const int gc0 = bn + col0;       // head-aligned 64-col span
        if (gc0 < 1024) {
            // ---- q or k: rmsnorm + rope (table), write g_qkb ----
            const bool isk = gc0 >= 512;
            const int head = (gc0 & 511) >> 6;
            const float* wn_ = isk ? knw : qnw;
            const float qs = isk ? 1.f : 0.125f;
            #pragma unroll
            for (int mt = 0; mt < 2; mt++) {
                const int row = bm + row0 + mt*16 + gid;
                const int n  = row & 1023;
                const int n8 = n + 8;
                float v0[8], v1[8], u0[8], u1[8];
                float ss0 = 0.f, ss1 = 0.f;
                #pragma unroll
                for (int nt = 0; nt < 8; nt++) {
                    const int col = gc0 + nt*8 + tig*2;
                    const float b0 = bias[col], b1 = bias[col+1];
                    v0[nt] = acc[mt][nt][0] + b0; v1[nt] = acc[mt][nt][1] + b1;
                    u0[nt] = acc[mt][nt][2] + b0; u1[nt] = acc[mt][nt][3] + b1;
                    ss0 += v0[nt]*v0[nt] + v1[nt]*v1[nt];
                    ss1 += u0[nt]*u0[nt] + u1[nt]*u1[nt];
                }
                #pragma unroll
                for (int o = 1; o <= 2; o <<= 1) {
                    ss0 += __shfl_xor_sync(0xffffffffu, ss0, o);
                    ss1 += __shfl_xor_sync(0xffffffffu, ss1, o);
                }
                const float r0 = rsqrtf(ss0 / 64.f + EPSV);
                const float r1 = rsqrtf(ss1 / 64.f + EPSV);
                #pragma unroll
                for (int nt = 0; nt < 8; nt++) {
                    const int j = nt*8 + tig*2;
                    const float w0 = wn_[j], w1 = wn_[j+1];
                    const float a0 = v0[nt]*r0*w0, a1 = v1[nt]*r0*w1;
                    const float c0 = u0[nt]*r1*w0, c1 = u1[nt]*r1*w1;
                    const int half = (j >= 32);
                    const int idx  = (half ? (j - 32) : j) >> 1;
                    const int pos0 = half ? (n  & 31) : (n  >> 5);
                    const int pos1 = half ? (n8 & 31) : (n8 >> 5);
                    const float2 cs0 = g_rope[pos0*16 + idx];
                    const float2 cs1 = g_rope[pos1*16 + idx];
                    const float qa = (a0*cs0.x - a1*cs0.y) * qs, qb = (a1*cs0.x + a0*cs0.y) * qs;
                    const float ka = (c0*cs1.x - c1*cs1.y) * qs, kb = (c1*cs1.x + c0*cs1.y) * qs;
                    const size_t w_ = (size_t)row*512 + (isk ? 256 : 0) + head*32 + nt*4 + tig;
                    Cb[w_]         = pack2bf(qa, qb);
                    Cb[w_ + 8*512] = pack2bf(ka, kb);
                }
            }
        } else {
            // ---- v: stage bf16 tile in smem, write transposed to g_vtb ----
            __nv_bfloat16* vs = (__nv_bfloat16*)sm;       // 128 x 136
            __syncthreads();
            #pragma unroll
            for (int mt = 0; mt < 2; mt++) {
                const int rl = row0 + mt*16 + gid;
                #pragma unroll
                for (int nt = 0; nt < 8; nt++) {
                    const int cl = col0 + nt*8 + tig*2;
                    const int col = bn + cl;
                    const float b0 = bias[col], b1 = bias[col+1];
                    *(uint32_t*)(vs + rl*136 + cl)     = pack2bf(acc[mt][nt][0]+b0, acc[mt][nt][1]+b1);
                    *(uint32_t*)(vs + (rl+8)*136 + cl) = pack2bf(acc[mt][nt][2]+b0, acc[mt][nt][3]+b1);
                }
            }
            __syncthreads();
            const int b  = bm >> 10;
            const int nb = bm & 1023;
            const int hbase = (bn - 1024) >> 6;
            #pragma unroll
            for (int i = 0; i < 8; i++) {
                const int lin = tid + i*256;
                const int cl = lin >> 4;
                const int t8 = (lin & 15) * 8;
                const int head = hbase + (cl >> 6);
                const int d = cl & 63;
                uint16_t v[8];
                #pragma unroll
                for (int jx = 0; jx < 8; jx++)
                    v[jx] = *(const uint16_t*)(vs + (t8 + jx)*136 + cl);
                uint4 o;
                o.x = (uint32_t)v[0] | ((uint32_t)v[1] << 16);
                o.y = (uint32_t)v[2] | ((uint32_t)v[3] << 16);
                o.z = (uint32_t)v[4] | ((uint32_t)v[5] << 16);
                o.w = (uint32_t)v[6] | ((uint32_t)v[7] << 16);
                *(uint4*)(g_vtb + ((size_t)(b*8 + head)*64 + d)*NTOK + nb + t8) = o;
            }
        }
        return;
    }

    if (MODE == 4) {
        __syncthreads();
        float* hs = (float*)sm;
        #pragma unroll
        for (int mt = 0; mt < 2; mt++) {
            const int rl = row0 + mt*16 + gid;
            const int row = bm + rl;
            const int b = row >> 10;
            const float* gp = ada + b*6*CH + gch*CH;
            #pragma unroll
            for (int nt = 0; nt < 8; nt++) {
                const int cl = col0 + nt*8 + tig*2;
                const int col = bn + cl;
                const float b0 = bias[col], b1 = bias[col+1];
                float2 h0 = *(float2*)(Cf + (size_t)row*NN + col);
                float2 h1 = *(float2*)(Cf + (size_t)(row+8)*NN + col);
                hs[rl*132 + cl]       = h0.x + gp[col]  *(acc[mt][nt][0] + b0);
                hs[rl*132 + cl+1]     = h0.y + gp[col+1]*(acc[mt][nt][1] + b1);
                hs[(rl+8)*132 + cl]   = h1.x + gp[col]  *(acc[mt][nt][2] + b0);
                hs[(rl+8)*132 + cl+1] = h1.y + gp[col+1]*(acc[mt][nt][3] + b1);
            }
        }
        __syncthreads();
        const int b = bm >> 10;
        const int nbase = bm & 1023;
        #pragma unroll
        for (int i = 0; i < 16; i++) {
            const int lin = tid + i*256;
            const int cr = lin >> 5, g = lin & 31;
            const size_t oidx = ((size_t)b*CH + bn + cr)*NTOK + nbase + g*4;
            float4 xs = *(const float4*)(Xin + oidx);
            xs.x += hs[(g*4+0)*132 + cr];
            xs.y += hs[(g*4+1)*132 + cr];
            xs.z += hs[(g*4+2)*132 + cr];
            xs.w += hs[(g*4+3)*132 + cr];
            *(float4*)(Oout + oidx) = xs;
        }
        return;
    }

    #pragma unroll
    for (int mt = 0; mt < 2; mt++) {
        const int row = bm + row0 + mt*16 + gid;
        const int b   = row >> 10;
        const float* gp = ada + b*6*CH + gch*CH;
        #pragma unroll
        for (int nt = 0; nt < 8; nt++) {
            const int col = bn + col0 + nt*8 + tig*2;
            const float b0 = bias[col], b1 = bias[col+1];
            float v00 = acc[mt][nt][0] + b0, v01 = acc[mt][nt][1] + b1;
            float v10 = acc[mt][nt][2] + b0, v11 = acc[mt][nt][3] + b1;
            if (MODE == 2) {
                const float gg0 = gp[col], gg1 = gp[col+1];
                float2 h0 = *(float2*)(Cf + (size_t)row*NN + col);
                float2 h1 = *(float2*)(Cf + (size_t)(row+8)*NN + col);
                h0.x += gg0*v00; h0.y += gg1*v01;
                h1.x += gg0*v10; h1.y += gg1*v11;
                *(float2*)(Cf + (size_t)row*NN + col)     = h0;
                *(float2*)(Cf + (size_t)(row+8)*NN + col) = h1;
            } else {
                const int j = col >> 1;
                const float s0 = (v00 / (1.f + __expf(-v00))) * v01;
                const float s1 = (v10 / (1.f + __expf(-v10))) * v11;
                Gb[(size_t)row*(NN>>1) + j]     = __float2bfloat16(s0);
                Gb[(size_t)(row+8)*(NN>>1) + j] = __float2bfloat16(s1);
            }
        }
    }
}

// ---------------- flash attention: 3-stage K/V ring, one sync per chunk ----------------
#define QSTR 36
__global__ __launch_bounds__(256) void k_attn_mma() {
    extern __shared__ uint32_t smw[];
    const int bh = blockIdx.x;
    const int b = bh >> 3, hh = bh & 7;
    const int q0 = blockIdx.y * 128;
    const int tid = threadIdx.x, lane = tid & 31, warp = tid >> 5;
    const int lr = lane & 7, sel8 = (lane >> 3) & 1, sel4 = (lane >> 4) & 1;
    const int gid = lane >> 2, tig = lane & 3;
    const __nv_bfloat16* qk = g_qkb + (size_t)b * NTOK * 1024;
    const __nv_bfloat16* vt = g_vtb + (size_t)bh * 64 * NTOK;

    const uint32_t sbase = (uint32_t)__cvta_generic_to_shared(smw);
    const uint32_t qoff  = ((warp*16 + sel8*8 + lr)*QSTR + sel4*4) * 4;
    const uint32_t kvoff = ((sel8*8 + lr)*QSTR + sel4*4) * 4;

    #pragma unroll
    for (int i = 0; i < 4; i++) {
        const int lin = tid + i*256;
        const int r = lin >> 3, c4 = lin & 7;
        cpa16(smw + r*QSTR + c4*4, qk + (size_t)(q0 + r)*1024 + hh*64 + c4*8);
    }
    asm volatile("cp.async.commit_group;\n");
    asm volatile("cp.async.wait_group 0;\n");
    __syncthreads();
    uint32_t qf[4][4];
    #pragma unroll
    for (int kk = 0; kk < 4; kk++)
        ldm4(sbase + qoff + kk*32, qf[kk][0], qf[kk][1], qf[kk][2], qf[kk][3]);
    __syncthreads();

    auto load_kv = [&](int kc, int s) {
        uint32_t* Ks = smw + s*128*QSTR;
        uint32_t* Vs = Ks + 64*QSTR;
        #pragma unroll
        for (int i = 0; i < 2; i++) {
            const int lin = tid + i*256;
            const int r = lin >> 3, c4 = lin & 7;
            cpa16(Ks + r*QSTR + c4*4, qk + (size_t)(kc + r)*1024 + 512 + hh*64 + c4*8);
            cpa16(Vs + r*QSTR + c4*4, vt + (size_t)r*NTOK + kc + c4*8);
        }
    };

    float l0 = 0.f, l1 = 0.f;
    float oacc[8][4];
    #pragma unroll
    for (int nt = 0; nt < 8; nt++)
        #pragma unroll
        for (int c = 0; c < 4; c++) oacc[nt][c] = 0.f;

    load_kv(0, 0);
    asm volatile("cp.async.commit_group;\n");
    load_kv(64, 1);
    asm volatile("cp.async.commit_group;\n");

    int stg = 0;
    for (int it = 0; it < NTOK/64; it++) {
        if (it + 2 < NTOK/64) {
            asm volatile("cp.async.wait_group 1;\n");
        } else {
            asm volatile("cp.async.wait_group 0;\n");
        }
        __syncthreads();
        if (it + 2 < NTOK/64) {
            int ns = stg + 2; if (ns >= 3) ns -= 3;
            load_kv((it+2)*64, ns);
            asm volatile("cp.async.commit_group;\n");
        }
        const uint32_t kbase = sbase + (uint32_t)(stg*128*QSTR*4);
        const uint32_t vbase = kbase + 64*QSTR*4;

        float sacc[8][4];
        #pragma unroll
        for (int nt = 0; nt < 8; nt++)
            #pragma unroll
            for (int c = 0; c < 4; c++) sacc[nt][c] = 0.f;
        #pragma unroll
        for (int kk = 0; kk < 4; kk++) {
            uint32_t bf[8][2];
            const uint32_t kb = kbase + kvoff + kk*32;
            #pragma unroll
            for (int nt2 = 0; nt2 < 4; nt2++)
                ldm4(kb + nt2*16*QSTR*4,
                     bf[2*nt2][0], bf[2*nt2+1][0], bf[2*nt2][1], bf[2*nt2+1][1]);
            #pragma unroll
            for (int nt = 0; nt < 8; nt++)
                MMA_BF16(sacc[nt], qf[kk], bf[nt]);
        }

        uint32_t pa[8], pb[8];
        #pragma unroll
        for (int nt = 0; nt < 8; nt++) {
            const float p00 = __expf(sacc[nt][0] - 8.f);
            const float p01 = __expf(sacc[nt][1] - 8.f);
            const float p10 = __expf(sacc[nt][2] - 8.f);
            const float p11 = __expf(sacc[nt][3] - 8.f);
            l0 += p00 + p01;  l1 += p10 + p11;
            pa[nt] = pack2bf(p00, p01);
            pb[nt] = pack2bf(p10, p11);
        }

        #pragma unroll
        for (int kk = 0; kk < 4; kk++) {
            uint32_t af[4] = { pa[2*kk], pb[2*kk], pa[2*kk+1], pb[2*kk+1] };
            uint32_t bf[8][2];
            const uint32_t vb = vbase + kvoff + kk*32;
            #pragma unroll
            for (int nt2 = 0; nt2 < 4; nt2++)
                ldm4(vb + nt2*16*QSTR*4,
                     bf[2*nt2][0], bf[2*nt2+1][0], bf[2*nt2][1], bf[2*nt2+1][1]);
            #pragma unroll
            for (int nt = 0; nt < 8; nt++)
                MMA_BF16(oacc[nt], af, bf[nt]);
        }
        if (++stg == 3) stg = 0;
    }

    #pragma unroll
    for (int o = 1; o <= 2; o <<= 1) {
        l0 += __shfl_xor_sync(0xffffffffu, l0, o);
        l1 += __shfl_xor_sync(0xffffffffu, l1, o);
    }
    const float inv0 = 1.f / l0, inv1 = 1.f / l1;
    uint32_t* ow = (uint32_t*)g_attb;
    const size_t row = (size_t)b*NTOK + q0 + warp*16 + gid;
    #pragma unroll
    for (int nt = 0; nt < 8; nt++) {
        const int cw = hh*32 + nt*4 + tig;
        ow[row*256 + cw]     = pack2bf(oacc[nt][0]*inv0, oacc[nt][1]*inv0);
        ow[(row+8)*256 + cw] = pack2bf(oacc[nt][2]*inv1, oacc[nt][3]*inv1);
    }
}

// ---------------- launcher ----------------
extern "C" void kernel_launch(void* const* d_in, const int* in_sizes, int n_in,
                              void* d_out, int out_size) {
    const float* x      = (const float*)d_in[0];
    const float* temb   = (const float*)d_in[1];
    const float* gn_w   = (const float*)d_in[2];
    const float* gn_b   = (const float*)d_in[3];
    const float* ada_w  = (const float*)d_in[4];
    const float* ada_b  = (const float*)d_in[5];
    const float* n1_w   = (const float*)d_in[6];
    const float* n2_w   = (const float*)d_in[7];
    const float* qkv_w  = (const float*)d_in[8];
    const float* qkv_b  = (const float*)d_in[9];
    const float* qn_w   = (const float*)d_in[10];
    const float* kn_w   = (const float*)d_in[11];
    const float* proj_w = (const float*)d_in[12];
    const float* proj_b = (const float*)d_in[13];
    const float* w12    = (const float*)d_in[14];
    const float* b12    = (const float*)d_in[15];
    const float* w_out  = (const float*)d_in[16];
    const float* b_out  = (const float*)d_in[17];
    float* out = (float*)d_out;

    float *p_h, *p_ada, *p_b12p;
    __nv_bfloat16 *p_hnb, *p_qkb, *p_attb, *p_gateb;
    __nv_bfloat16 *p_wqkv, *p_wproj, *p_w12c, *p_woc;
    cudaGetSymbolAddress((void**)&p_h,     g_h);
    cudaGetSymbolAddress((void**)&p_ada,   g_ada);
    cudaGetSymbolAddress((void**)&p_b12p,  g_b12p);
    cudaGetSymbolAddress((void**)&p_hnb,   g_hnb);
    cudaGetSymbolAddress((void**)&p_qkb,   g_qkb);
    cudaGetSymbolAddress((void**)&p_attb,  g_attb);
    cudaGetSymbolAddress((void**)&p_gateb, g_gateb);
    cudaGetSymbolAddress((void**)&p_wqkv,  g_wqkv);
    cudaGetSymbolAddress((void**)&p_wproj, g_wproj);
    cudaGetSymbolAddress((void**)&p_w12c,  g_w12c);
    cudaGetSymbolAddress((void**)&p_woc,   g_woc);

    const int gemm_smem  = 3*STG_W*4;         // 110592 B
    const int attn_smem  = 3*128*QSTR*4;      // 55296 B
    const int gnrms_smem = (32*HSTR + 32)*4;  // 65792 B
    cudaFuncSetAttribute(k_gemm<5,1536,512>, cudaFuncAttributeMaxDynamicSharedMemorySize, gemm_smem);
    cudaFuncSetAttribute(k_gemm<2,512,512>,  cudaFuncAttributeMaxDynamicSharedMemorySize, gemm_smem);
    cudaFuncSetAttribute(k_gemm<3,4096,512>, cudaFuncAttributeMaxDynamicSharedMemorySize, gemm_smem);
    cudaFuncSetAttribute(k_gemm<4,512,2048>, cudaFuncAttributeMaxDynamicSharedMemorySize, gemm_smem);
    cudaFuncSetAttribute(k_attn_mma, cudaFuncAttributeMaxDynamicSharedMemorySize, attn_smem);
    cudaFuncSetAttribute(k_gnrms,    cudaFuncAttributeMaxDynamicSharedMemorySize, gnrms_smem);

    k_cvtall <<<(1048576 + FFN + 512 + 255)/256, 256>>>(qkv_w, proj_w, w_out, w12, b12);

    // adaLN + GroupNorm stats (merged) + fused gn-apply/rmsnorm/mod
    k_adagn  <<<192 + BDIM*32, 256>>>(temb, ada_w, ada_b, x);
    k_gnrms  <<<dim3(NTOK/32, BDIM), 512, gnrms_smem>>>(x, gn_w, gn_b, n1_w);

    // attention branch (QKV gemm with fused rope/rmsnorm/v-transpose epilogue)
    k_gemm<5,1536,512><<<dim3(1536/128, NT/128), 256, gemm_smem>>>(
        p_hnb, p_wqkv, qkv_b, nullptr, (uint32_t*)p_qkb, nullptr, p_ada,
        nullptr, nullptr, qn_w, kn_w, 0);
    k_attn_mma<<<dim3(BDIM*NHEADS, NTOK/128), 256, attn_smem>>>();
    k_gemm<2,512,512><<<dim3(512/128, NT/128), 256, gemm_smem>>>(
        p_attb, p_wproj, proj_b, p_h, nullptr, nullptr, p_ada,
        nullptr, nullptr, nullptr, nullptr, 2);

    // FFN branch
    k_rmsmod <<<NT, 128>>>(n2_w, 3, 4);
    k_gemm<3,4096,512><<<dim3(4096/128, NT/128), 256, gemm_smem>>>(
        p_hnb, p_w12c, p_b12p, nullptr, nullptr, p_gateb, p_ada,
        nullptr, nullptr, nullptr, nullptr, 0);
    k_gemm<4,512,2048><<<dim3(512/128, NT/128), 256, gemm_smem>>>(
        p_gateb, p_woc, b_out, p_h, nullptr, nullptr, p_ada,
        x, out, nullptr, nullptr, 5);
}

// round 16
// speedup vs baseline: 1.0686x; 1.0048x over previous
#include <cuda_runtime.h>
#include <cuda_bf16.h>
#include <cstdint>

// ---------------- problem constants ----------------
#define BDIM   16
#define CH     512
#define NTOK   1024
#define NT     (BDIM*NTOK)
#define NHEADS 8
#define HDIM   64
#define FFN    2048
#define EPSV   1e-6f

// ---------------- scratch ----------------
__device__ float g_ada [BDIM*6*CH];
__device__ float g_h   [NT*CH];
__device__ float g_stats[BDIM*32*2];
__device__ float g_b12p[2*FFN];
__device__ float2 g_rope[32*16];
__device__ __nv_bfloat16 g_hnb [NT*CH];
__device__ __nv_bfloat16 g_qkb [NT*2*CH];
__device__ __nv_bfloat16 g_vtb [BDIM*NHEADS*HDIM*NTOK];
__device__ __nv_bfloat16 g_attb[NT*CH];
__device__ __nv_bfloat16 g_gateb[NT*FFN];
__device__ __nv_bfloat16 g_wqkv [3*CH*CH];
__device__ __nv_bfloat16 g_wproj[CH*CH];
__device__ __nv_bfloat16 g_w12c [2*FFN*CH];
__device__ __nv_bfloat16 g_woc  [CH*FFN];

// ---------------- helpers ----------------
__device__ __forceinline__ uint32_t pack2bf(float lo, float hi) {
    uint32_t r;
    asm("cvt.rn.bf16x2.f32 %0, %1, %2;" : "=r"(r) : "f"(hi), "f"(lo));
    return r;
}
__device__ __forceinline__ void cpa16(void* s, const void* g) {
    uint32_t sa = (uint32_t)__cvta_generic_to_shared(s);
    asm volatile("cp.async.cg.shared.global [%0], [%1], 16;\n" :: "r"(sa), "l"(g));
}
__device__ __forceinline__ void ldm4(uint32_t addr, uint32_t& r0, uint32_t& r1,
                                     uint32_t& r2, uint32_t& r3) {
    asm volatile("ldmatrix.sync.aligned.m8n8.x4.shared.b16 {%0,%1,%2,%3}, [%4];"
                 : "=r"(r0), "=r"(r1), "=r"(r2), "=r"(r3) : "r"(addr));
}
#define MMA_BF16(d, a, b) \
    asm volatile("mma.sync.aligned.m16n8k16.row.col.f32.bf16.bf16.f32 " \
                 "{%0,%1,%2,%3}, {%4,%5,%6,%7}, {%8,%9}, {%0,%1,%2,%3};" \
                 : "+f"(d[0]), "+f"(d[1]), "+f"(d[2]), "+f"(d[3]) \
                 : "r"(a[0]), "r"(a[1]), "r"(a[2]), "r"(a[3]), "r"(b[0]), "r"(b[1]))

// ---------------- merged prologue: adaLN + GN stats + weight cvt + rope table ----------------
__device__ __forceinline__ void cvt4(const float* __restrict__ s,
                                     __nv_bfloat16* __restrict__ d, int i) {
    float4 v = *(const float4*)(s + i);
    *(uint32_t*)(d + i)     = pack2bf(v.x, v.y);
    *(uint32_t*)(d + i + 2) = pack2bf(v.z, v.w);
}
__global__ __launch_bounds__(256) void k_prolog(
    const float* __restrict__ temb, const float* __restrict__ ada_w,
    const float* __restrict__ ada_b, const float* __restrict__ x,
    const float* __restrict__ qkv_w, const float* __restrict__ proj_w,
    const float* __restrict__ w_out, const float* __restrict__ w12,
    const float* __restrict__ b12) {
    const int blk = blockIdx.x;
    __shared__ float sh[CH];
    if (blk < 192) {
        // ---- adaLN: b = blk/12, n-chunk = blk%12 ----
        const int b = blk / 12;
        for (int i = threadIdx.x; i < CH; i += 256) {
            float v = temb[b*CH + i];
            sh[i] = v / (1.f + __expf(-v));
        }
        __syncthreads();
        const int n = (blk % 12) * 256 + threadIdx.x;
        const float* wr = ada_w + (size_t)n * CH;
        float acc = 0.f;
        #pragma unroll 8
        for (int k = 0; k < CH; k++) acc += wr[k] * sh[k];
        g_ada[b*6*CH + n] = acc + ada_b[n];
    } else if (blk < 704) {
        // ---- GroupNorm stats ----
        const int bg = blk - 192;
        const float* p = x + (size_t)bg * 16 * NTOK;
        float s = 0.f, s2 = 0.f;
        for (int i = threadIdx.x; i < 16*NTOK; i += 256) {
            float v = p[i]; s += v; s2 += v*v;
        }
        #pragma unroll
        for (int o = 16; o; o >>= 1) {
            s  += __shfl_xor_sync(0xffffffffu, s,  o);
            s2 += __shfl_xor_sync(0xffffffffu, s2, o);
        }
        const int w = threadIdx.x >> 5, l = threadIdx.x & 31;
        if (l == 0) { sh[w] = s; sh[32 + w] = s2; }
        __syncthreads();
        if (threadIdx.x < 32) {
            s  = (threadIdx.x < 8) ? sh[threadIdx.x]      : 0.f;
            s2 = (threadIdx.x < 8) ? sh[32 + threadIdx.x] : 0.f;
            #pragma unroll
            for (int o = 4; o; o >>= 1) {
                s  += __shfl_xor_sync(0xffffffffu, s,  o);
                s2 += __shfl_xor_sync(0xffffffffu, s2, o);
            }
            if (threadIdx.x == 0) {
                const float inv = 1.f / (16.f * NTOK);
                float mu  = s * inv;
                float var = s2 * inv - mu * mu;
                g_stats[bg*2]     = mu;
                g_stats[bg*2 + 1] = rsqrtf(var + EPSV);
            }
        }
    } else {
        // ---- weight conversion + permutes + rope table ----
        const int gi = (blk - 704) * 256 + threadIdx.x;
        if (gi < 196608) {
            cvt4(qkv_w, g_wqkv, gi * 4);
        } else if (gi < 262144) {
            cvt4(proj_w, g_wproj, (gi - 196608) * 4);
        } else if (gi < 524288) {
            cvt4(w_out, g_woc, (gi - 262144) * 4);
        } else if (gi < 1048576) {
            const int i = (gi - 524288) * 4;
            const int r = i >> 9;
            const int k = i & (CH - 1);
            const int sr = (r & 1) ? (FFN + (r >> 1)) : (r >> 1);
            float4 v = *(const float4*)(w12 + (size_t)sr*CH + k);
            *(uint32_t*)(g_w12c + i)     = pack2bf(v.x, v.y);
            *(uint32_t*)(g_w12c + i + 2) = pack2bf(v.z, v.w);
        } else if (gi < 1048576 + FFN) {
            const int j = gi - 1048576;
            g_b12p[2*j]   = b12[j];
            g_b12p[2*j+1] = b12[FFN + j];
        } else if (gi < 1048576 + FFN + 512) {
            const int e = gi - 1048576 - FFN;
            const int pos = e >> 4, idx = e & 15;
            const float freq = exp2f(-(float)idx * (13.287712379549449f / 16.f));
            const float f = (float)pos * freq;
            g_rope[e] = make_float2(cosf(f), sinf(f));
        }
    }
}

// ---------------- fused GroupNorm-apply + transpose + RMSNorm(n1) + mod ----------------
#define HSTR 513
__global__ __launch_bounds__(512) void k_gnrms(
    const float* __restrict__ x, const float* __restrict__ gw, const float* __restrict__ gb,
    const float* __restrict__ n1w) {
    extern __shared__ float hb[];
    float* rms = hb + 32*HSTR;
    const int b  = blockIdx.y;
    const int n0 = blockIdx.x * 32;
    const int t  = threadIdx.x;
    for (int c0 = 0; c0 < CH; c0 += 64) {
        #pragma unroll
        for (int i = 0; i < 4; i++) {
            const int cl = (t >> 5) + i*16;
            const int nl = t & 31;
            const int c  = c0 + cl;
            const float mu = g_stats[(b*32 + (c >> 4))*2];
            const float rs = g_stats[(b*32 + (c >> 4))*2 + 1];
            const float v  = x[((size_t)b*CH + c)*NTOK + n0 + nl];
            hb[nl*HSTR + c] = (v - mu) * rs * gw[c] + gb[c];
        }
    }
    __syncthreads();
    {
        const int tok = t >> 4, l16 = t & 15;
        float ss = 0.f;
        #pragma unroll 8
        for (int i = 0; i < 32; i++) {
            const float v = hb[tok*HSTR + l16 + i*16];
            ss += v*v;
        }
        #pragma unroll
        for (int o = 1; o <= 8; o <<= 1) ss += __shfl_xor_sync(0xffffffffu, ss, o);
        if (l16 == 0) rms[tok] = rsqrtf(ss / (float)CH + EPSV);
    }
    __syncthreads();
    const int rowb = b*NTOK + n0;
    const float* shf = g_ada + b*6*CH;
    const float* scl = g_ada + b*6*CH + CH;
    #pragma unroll 4
    for (int i = 0; i < 16; i++) {
        const int idx = (t + i*512) * 2;
        const int tk = idx >> 9, c = idx & 511;
        const float h0 = hb[tk*HSTR + c], h1 = hb[tk*HSTR + c + 1];
        const float r = rms[tk];
        *(float2*)(g_h + (size_t)(rowb + tk)*CH + c) = make_float2(h0, h1);
        const float o0 = h0 * r * n1w[c]   * (1.f + scl[c])   + shf[c];
        const float o1 = h1 * r * n1w[c+1] * (1.f + scl[c+1]) + shf[c+1];
        *(uint32_t*)(g_hnb + (size_t)(rowb + tk)*CH + c) = pack2bf(o0, o1);
    }
}

// ---------------- RMSNorm + modulation -> bf16 (n2 path) ----------------
__global__ void k_rmsmod(const float* __restrict__ w, int shift_ch, int scale_ch) {
    const int row = blockIdx.x;
    const int b = row >> 10;
    const float* hp = g_h + (size_t)row * CH;
    const int t = threadIdx.x;
    float4 v = *(const float4*)(hp + t*4);
    float ss = v.x*v.x + v.y*v.y + v.z*v.z + v.w*v.w;
    #pragma unroll
    for (int o = 16; o; o >>= 1) ss += __shfl_xor_sync(0xffffffffu, ss, o);
    __shared__ float sh[4];
    if ((t & 31) == 0) sh[t >> 5] = ss;
    __syncthreads();
    ss = sh[0] + sh[1] + sh[2] + sh[3];
    const float r = rsqrtf(ss / (float)CH + EPSV);
    const float* shf = g_ada + b*6*CH + shift_ch*CH;
    const float* scl = g_ada + b*6*CH + scale_ch*CH;
    const int c = t*4;
    float o0 = v.x * r * w[c+0] * (1.f + scl[c+0]) + shf[c+0];
    float o1 = v.y * r * w[c+1] * (1.f + scl[c+1]) + shf[c+1];
    float o2 = v.z * r * w[c+2] * (1.f + scl[c+2]) + shf[c+2];
    float o3 = v.w * r * w[c+3] * (1.f + scl[c+3]) + shf[c+3];
    uint32_t* dp = (uint32_t*)(g_hnb + (size_t)row*CH + c);
    dp[0] = pack2bf(o0, o1);
    dp[1] = pack2bf(o2, o3);
}

// ---------------- BF16 GEMM (templated): K-chunk 64, 3-stage, 1 barrier/chunk ----------------
// MODE: 2 = g_h += gate*(acc+bias); 3 = fused swiglu; 4 = final out = x + h^T;
//       5 = fused QKV post: q/k rmsnorm+rope(table) -> g_qkb, v -> transposed g_vtb
#define WSTR 36
#define STG_W (128*WSTR*2)
template<int MODE, int NN, int KK>
__global__ __launch_bounds__(256, 2) void k_gemm(
    const __nv_bfloat16* __restrict__ A, const __nv_bfloat16* __restrict__ W,
    const float* __restrict__ bias, float* __restrict__ Cf, uint32_t* __restrict__ Cb,
    __nv_bfloat16* __restrict__ Gb, const float* __restrict__ ada,
    const float* __restrict__ Xin, float* __restrict__ Oout,
    const float* __restrict__ qnw, const float* __restrict__ knw, int gch)
{
    extern __shared__ uint32_t sm[];
    const int tid  = threadIdx.x;
    const int lane = tid & 31;
    const int warp = tid >> 5;
    const int gid  = lane >> 2;
    const int tig  = lane & 3;
    const int row0 = (warp & 3) * 32;
    const int col0 = (warp >> 2) * 64;
    const int bm = blockIdx.y * 128, bn = blockIdx.x * 128;
    constexpr int KT = KK >> 6;
    const int lr   = lane & 7;
    const int sel8 = (lane >> 3) & 1;
    const int sel4 = (lane >> 4) & 1;

    const uint32_t sbase = (uint32_t)__cvta_generic_to_shared(sm);
    const uint32_t aoff  = ((row0 + sel8*8 + lr)*WSTR + sel4*4) * 4;
    const uint32_t boff  = ((col0 + sel8*8 + lr)*WSTR + sel4*4) * 4 + 128*WSTR*4;

    auto load_body = [&](int kt, int s) {
        uint32_t* As = sm + s * STG_W;
        uint32_t* Ws = As + 128*WSTR;
        const int k0 = kt << 6;
        #pragma unroll
        for (int i = 0; i < 4; i++) {
            const int lin = tid + i*256;
            const int r = lin >> 3, c = lin & 7;
            cpa16(As + r*WSTR + c*4, A + (size_t)(bm + r)*KK + k0 + c*8);
        }
        #pragma unroll
        for (int i = 0; i < 4; i++) {
            const int lin = tid + i*256;
            const int r = lin >> 3, c = lin & 7;
            cpa16(Ws + r*WSTR + c*4, W + (size_t)(bn + r)*KK + k0 + c*8);
        }
    };

    load_body(0, 0);
    asm volatile("cp.async.commit_group;\n");
    load_body(1, 1);
    asm volatile("cp.async.commit_group;\n");

    float acc[2][8][4];
    #pragma unroll
    for (int i = 0; i < 2; i++)
        #pragma unroll
        for (int j = 0; j < 8; j++)
            #pragma unroll
            for (int c = 0; c < 4; c++) acc[i][j][c] = 0.f;

    int stg = 0;
    #pragma unroll 2
    for (int kt = 0; kt < KT; kt++) {
        if (kt + 1 < KT) {
            asm volatile("cp.async.wait_group 1;\n");
        } else {
            asm volatile("cp.async.wait_group 0;\n");
        }
        __syncthreads();
        if (kt + 2 < KT) {
            int ns = stg + 2; if (ns >= 3) ns -= 3;
            load_body(kt + 2, ns);
            asm volatile("cp.async.commit_group;\n");
        }
        const uint32_t stb = sbase + (uint32_t)(stg * STG_W * 4);
        #pragma unroll
        for (int kk = 0; kk < 4; kk++) {
            const uint32_t kb = kk * 32;
            uint32_t af[2][4], bf[8][2];
            const uint32_t aa = stb + aoff + kb;
            ldm4(aa,             af[0][0], af[0][1], af[0][2], af[0][3]);
            ldm4(aa + 16*WSTR*4, af[1][0], af[1][1], af[1][2], af[1][3]);
            const uint32_t bb = stb + boff + kb;
            #pragma unroll
            for (int nt2 = 0; nt2 < 4; nt2++) {
                ldm4(bb + nt2*16*WSTR*4,
                     bf[2*nt2][0], bf[2*nt2+1][0], bf[2*nt2][1], bf[2*nt2+1][1]);
            }
            #pragma unroll
            for (int mt = 0; mt < 2; mt++)
                #pragma unroll
                for (int nt = 0; nt < 8; nt++)
                    MMA_BF16(acc[mt][nt], af[mt], bf[nt]);
        }
        if (++stg == 3) stg = 0;
    }

    if (MODE == 5) {
        const int gc0 = bn + col0;
        if (gc0 < 1024) {
            const bool isk = gc0 >= 512;
            const int head = (gc0 & 511) >> 6;
            const float* wn_ = isk ? knw : qnw;
            const float qs = isk ? 1.f : 0.125f;
            #pragma unroll
            for (int mt = 0; mt < 2; mt++) {
                const int row = bm + row0 + mt*16 + gid;
                const int n  = row & 1023;
                const int n8 = n + 8;
                float v0[8], v1[8], u0[8], u1[8];
                float ss0 = 0.f, ss1 = 0.f;
                #pragma unroll
                for (int nt = 0; nt < 8; nt++) {
                    const int col = gc0 + nt*8 + tig*2;
                    const float b0 = bias[col], b1 = bias[col+1];
                    v0[nt] = acc[mt][nt][0] + b0; v1[nt] = acc[mt][nt][1] + b1;
                    u0[nt] = acc[mt][nt][2] + b0; u1[nt] = acc[mt][nt][3] + b1;
                    ss0 += v0[nt]*v0[nt] + v1[nt]*v1[nt];
                    ss1 += u0[nt]*u0[nt] + u1[nt]*u1[nt];
                }
                #pragma unroll
                for (int o = 1; o <= 2; o <<= 1) {
                    ss0 += __shfl_xor_sync(0xffffffffu, ss0, o);
                    ss1 += __shfl_xor_sync(0xffffffffu, ss1, o);
                }
                const float r0 = rsqrtf(ss0 / 64.f + EPSV);
                const float r1 = rsqrtf(ss1 / 64.f + EPSV);
                #pragma unroll
                for (int nt = 0; nt < 8; nt++) {
                    const int j = nt*8 + tig*2;
                    const float w0 = wn_[j], w1 = wn_[j+1];
                    const float a0 = v0[nt]*r0*w0, a1 = v1[nt]*r0*w1;
                    const float c0 = u0[nt]*r1*w0, c1 = u1[nt]*r1*w1;
                    const int half = (j >= 32);
                    const int idx  = (half ? (j - 32) : j) >> 1;
                    const int pos0 = half ? (n  & 31) : (n  >> 5);
                    const int pos1 = half ? (n8 & 31) : (n8 >> 5);
                    const float2 cs0 = g_rope[pos0*16 + idx];
                    const float2 cs1 = g_rope[pos1*16 + idx];
                    const float qa = (a0*cs0.x - a1*cs0.y) * qs, qb = (a1*cs0.x + a0*cs0.y) * qs;
                    const float ka = (c0*cs1.x - c1*cs1.y) * qs, kb = (c1*cs1.x + c0*cs1.y) * qs;
                    const size_t w_ = (size_t)row*512 + (isk ? 256 : 0) + head*32 + nt*4 + tig;
                    Cb[w_]         = pack2bf(qa, qb);
                    Cb[w_ + 8*512] = pack2bf(ka, kb);
                }
            }
        } else {
            __nv_bfloat16* vs = (__nv_bfloat16*)sm;
            __syncthreads();
            #pragma unroll
            for (int mt = 0; mt < 2; mt++) {
                const int rl = row0 + mt*16 + gid;
                #pragma unroll
                for (int nt = 0; nt < 8; nt++) {
                    const int cl = col0 + nt*8 + tig*2;
                    const int col = bn + cl;
                    const float b0 = bias[col], b1 = bias[col+1];
                    *(uint32_t*)(vs + rl*136 + cl)     = pack2bf(acc[mt][nt][0]+b0, acc[mt][nt][1]+b1);
                    *(uint32_t*)(vs + (rl+8)*136 + cl) = pack2bf(acc[mt][nt][2]+b0, acc[mt][nt][3]+b1);
                }
            }
            __syncthreads();
            const int b  = bm >> 10;
            const int nb = bm & 1023;
            const int hbase = (bn - 1024) >> 6;
            #pragma unroll
            for (int i = 0; i < 8; i++) {
                const int lin = tid + i*256;
                const int cl = lin >> 4;
                const int t8 = (lin & 15) * 8;
                const int head = hbase + (cl >> 6);
                const int d = cl & 63;
                uint16_t v[8];
                #pragma unroll
                for (int jx = 0; jx < 8; jx++)
                    v[jx] = *(const uint16_t*)(vs + (t8 + jx)*136 + cl);
                uint4 o;
                o.x = (uint32_t)v[0] | ((uint32_t)v[1] << 16);
                o.y = (uint32_t)v[2] | ((uint32_t)v[3] << 16);
                o.z = (uint32_t)v[4] | ((uint32_t)v[5] << 16);
                o.w = (uint32_t)v[6] | ((uint32_t)v[7] << 16);
                *(uint4*)(g_vtb + ((size_t)(b*8 + head)*64 + d)*NTOK + nb + t8) = o;
            }
        }
        return;
    }

    if (MODE == 4) {
        __syncthreads();
        float* hs = (float*)sm;
        #pragma unroll
        for (int mt = 0; mt < 2; mt++) {
            const int rl = row0 + mt*16 + gid;
            const int row = bm + rl;
            const int b = row >> 10;
            const float* gp = ada + b*6*CH + gch*CH;
            #pragma unroll
            for (int nt = 0; nt < 8; nt++) {
                const int cl = col0 + nt*8 + tig*2;
                const int col = bn + cl;
                const float b0 = bias[col], b1 = bias[col+1];
                float2 h0 = *(float2*)(Cf + (size_t)row*NN + col);
                float2 h1 = *(float2*)(Cf + (size_t)(row+8)*NN + col);
                hs[rl*132 + cl]       = h0.x + gp[col]  *(acc[mt][nt][0] + b0);
                hs[rl*132 + cl+1]     = h0.y + gp[col+1]*(acc[mt][nt][1] + b1);
                hs[(rl+8)*132 + cl]   = h1.x + gp[col]  *(acc[mt][nt][2] + b0);
                hs[(rl+8)*132 + cl+1] = h1.y + gp[col+1]*(acc[mt][nt][3] + b1);
            }
        }
        __syncthreads();
        const int b = bm >> 10;
        const int nbase = bm & 1023;
        #pragma unroll
        for (int i = 0; i < 16; i++) {
            const int lin = tid + i*256;
            const int cr = lin >> 5, g = lin & 31;
            const size_t oidx = ((size_t)b*CH + bn + cr)*NTOK + nbase + g*4;
            float4 xs = *(const float4*)(Xin + oidx);
            xs.x += hs[(g*4+0)*132 + cr];
            xs.y += hs[(g*4+1)*132 + cr];
            xs.z += hs[(g*4+2)*132 + cr];
            xs.w += hs[(g*4+3)*132 + cr];
            *(float4*)(Oout + oidx) = xs;
        }
        return;
    }

    #pragma unroll
    for (int mt = 0; mt < 2; mt++) {
        const int row = bm + row0 + mt*16 + gid;
        const int b   = row >> 10;
        const float* gp = ada + b*6*CH + gch*CH;
        #pragma unroll
        for (int nt = 0; nt < 8; nt++) {
            const int col = bn + col0 + nt*8 + tig*2;
            const float b0 = bias[col], b1 = bias[col+1];
            float v00 = acc[mt][nt][0] + b0, v01 = acc[mt][nt][1] + b1;
            float v10 = acc[mt][nt][2] + b0, v11 = acc[mt][nt][3] + b1;
            if (MODE == 2) {
                const float gg0 = gp[col], gg1 = gp[col+1];
                float2 h0 = *(float2*)(Cf + (size_t)row*NN + col);
                float2 h1 = *(float2*)(Cf + (size_t)(row+8)*NN + col);
                h0.x += gg0*v00; h0.y += gg1*v01;
                h1.x += gg0*v10; h1.y += gg1*v11;
                *(float2*)(Cf + (size_t)row*NN + col)     = h0;
                *(float2*)(Cf + (size_t)(row+8)*NN + col) = h1;
            } else {
                const int j = col >> 1;
                const float s0 = (v00 / (1.f + __expf(-v00))) * v01;
                const float s1 = (v10 / (1.f + __expf(-v10))) * v11;
                Gb[(size_t)row*(NN>>1) + j]     = __float2bfloat16(s0);
                Gb[(size_t)(row+8)*(NN>>1) + j] = __float2bfloat16(s1);
            }
        }
    }
}

// ---------------- flash attention: 3-stage K/V ring, one sync per chunk ----------------
#define QSTR 36
__global__ __launch_bounds__(256) void k_attn_mma() {
    extern __shared__ uint32_t smw[];
    const int bh = blockIdx.x;
    const int b = bh >> 3, hh = bh & 7;
    const int q0 = blockIdx.y * 128;
    const int tid = threadIdx.x, lane = tid & 31, warp = tid >> 5;
    const int lr = lane & 7, sel8 = (lane >> 3) & 1, sel4 = (lane >> 4) & 1;
    const int gid = lane >> 2, tig = lane & 3;
    const __nv_bfloat16* qk = g_qkb + (size_t)b * NTOK * 1024;
    const __nv_bfloat16* vt = g_vtb + (size_t)bh * 64 * NTOK;

    const uint32_t sbase = (uint32_t)__cvta_generic_to_shared(smw);
    const uint32_t qoff  = ((warp*16 + sel8*8 + lr)*QSTR + sel4*4) * 4;
    const uint32_t kvoff = ((sel8*8 + lr)*QSTR + sel4*4) * 4;

    #pragma unroll
    for (int i = 0; i < 4; i++) {
        const int lin = tid + i*256;
        const int r = lin >> 3, c4 = lin & 7;
        cpa16(smw + r*QSTR + c4*4, qk + (size_t)(q0 + r)*1024 + hh*64 + c4*8);
    }
    asm volatile("cp.async.commit_group;\n");
    asm volatile("cp.async.wait_group 0;\n");
    __syncthreads();
    uint32_t qf[4][4];
    #pragma unroll
    for (int kk = 0; kk < 4; kk++)
        ldm4(sbase + qoff + kk*32, qf[kk][0], qf[kk][1], qf[kk][2], qf[kk][3]);
    __syncthreads();

    auto load_kv = [&](int kc, int s) {
        uint32_t* Ks = smw + s*128*QSTR;
        uint32_t* Vs = Ks + 64*QSTR;
        #pragma unroll
        for (int i = 0; i < 2; i++) {
            const int lin = tid + i*256;
            const int r = lin >> 3, c4 = lin & 7;
            cpa16(Ks + r*QSTR + c4*4, qk + (size_t)(kc + r)*1024 + 512 + hh*64 + c4*8);
            cpa16(Vs + r*QSTR + c4*4, vt + (size_t)r*NTOK + kc + c4*8);
        }
    };

    float l0 = 0.f, l1 = 0.f;
    float oacc[8][4];
    #pragma unroll
    for (int nt = 0; nt < 8; nt++)
        #pragma unroll
        for (int c = 0; c < 4; c++) oacc[nt][c] = 0.f;

    load_kv(0, 0);
    asm volatile("cp.async.commit_group;\n");
    load_kv(64, 1);
    asm volatile("cp.async.commit_group;\n");

    int stg = 0;
    for (int it = 0; it < NTOK/64; it++) {
        if (it + 2 < NTOK/64) {
            asm volatile("cp.async.wait_group 1;\n");
        } else {
            asm volatile("cp.async.wait_group 0;\n");
        }
        __syncthreads();
        if (it + 2 < NTOK/64) {
            int ns = stg + 2; if (ns >= 3) ns -= 3;
            load_kv((it+2)*64, ns);
            asm volatile("cp.async.commit_group;\n");
        }
        const uint32_t kbase = sbase + (uint32_t)(stg*128*QSTR*4);
        const uint32_t vbase = kbase + 64*QSTR*4;

        float sacc[8][4];
        #pragma unroll
        for (int nt = 0; nt < 8; nt++)
            #pragma unroll
            for (int c = 0; c < 4; c++) sacc[nt][c] = 0.f;
        #pragma unroll
        for (int kk = 0; kk < 4; kk++) {
            uint32_t bf[8][2];
            const uint32_t kb = kbase + kvoff + kk*32;
            #pragma unroll
            for (int nt2 = 0; nt2 < 4; nt2++)
                ldm4(kb + nt2*16*QSTR*4,
                     bf[2*nt2][0], bf[2*nt2+1][0], bf[2*nt2][1], bf[2*nt2+1][1]);
            #pragma unroll
            for (int nt = 0; nt < 8; nt++)
                MMA_BF16(sacc[nt], qf[kk], bf[nt]);
        }

        uint32_t pa[8], pb[8];
        #pragma unroll
        for (int nt = 0; nt < 8; nt++) {
            const float p00 = __expf(sacc[nt][0] - 8.f);
            const float p01 = __expf(sacc[nt][1] - 8.f);
            const float p10 = __expf(sacc[nt][2] - 8.f);
            const float p11 = __expf(sacc[nt][3] - 8.f);
            l0 += p00 + p01;  l1 += p10 + p11;
            pa[nt] = pack2bf(p00, p01);
            pb[nt] = pack2bf(p10, p11);
        }

        #pragma unroll
        for (int kk = 0; kk < 4; kk++) {
            uint32_t af[4] = { pa[2*kk], pb[2*kk], pa[2*kk+1], pb[2*kk+1] };
            uint32_t bf[8][2];
            const uint32_t vb = vbase + kvoff + kk*32;
            #pragma unroll
            for (int nt2 = 0; nt2 < 4; nt2++)
                ldm4(vb + nt2*16*QSTR*4,
                     bf[2*nt2][0], bf[2*nt2+1][0], bf[2*nt2][1], bf[2*nt2+1][1]);
            #pragma unroll
            for (int nt = 0; nt < 8; nt++)
                MMA_BF16(oacc[nt], af, bf[nt]);
        }
        if (++stg == 3) stg = 0;
    }

    #pragma unroll
    for (int o = 1; o <= 2; o <<= 1) {
        l0 += __shfl_xor_sync(0xffffffffu, l0, o);
        l1 += __shfl_xor_sync(0xffffffffu, l1, o);
    }
    const float inv0 = 1.f / l0, inv1 = 1.f / l1;
    uint32_t* ow = (uint32_t*)g_attb;
    const size_t row = (size_t)b*NTOK + q0 + warp*16 + gid;
    #pragma unroll
    for (int nt = 0; nt < 8; nt++) {
        const int cw = hh*32 + nt*4 + tig;
        ow[row*256 + cw]     = pack2bf(oacc[nt][0]*inv0, oacc[nt][1]*inv0);
        ow[(row+8)*256 + cw] = pack2bf(oacc[nt][2]*inv1, oacc[nt][3]*inv1);
    }
}

// ---------------- launcher ----------------
extern "C" void kernel_launch(void* const* d_in, const int* in_sizes, int n_in,
                              void* d_out, int out_size) {
    const float* x      = (const float*)d_in[0];
    const float* temb   = (const float*)d_in[1];
    const float* gn_w   = (const float*)d_in[2];
    const float* gn_b   = (const float*)d_in[3];
    const float* ada_w  = (const float*)d_in[4];
    const float* ada_b  = (const float*)d_in[5];
    const float* n1_w   = (const float*)d_in[6];
    const float* n2_w   = (const float*)d_in[7];
    const float* qkv_w  = (const float*)d_in[8];
    const float* qkv_b  = (const float*)d_in[9];
    const float* qn_w   = (const float*)d_in[10];
    const float* kn_w   = (const float*)d_in[11];
    const float* proj_w = (const float*)d_in[12];
    const float* proj_b = (const float*)d_in[13];
    const float* w12    = (const float*)d_in[14];
    const float* b12    = (const float*)d_in[15];
    const float* w_out  = (const float*)d_in[16];
    const float* b_out  = (const float*)d_in[17];
    float* out = (float*)d_out;

    float *p_h, *p_ada, *p_b12p;
    __nv_bfloat16 *p_hnb, *p_qkb, *p_attb, *p_gateb;
    __nv_bfloat16 *p_wqkv, *p_wproj, *p_w12c, *p_woc;
    cudaGetSymbolAddress((void**)&p_h,     g_h);
    cudaGetSymbolAddress((void**)&p_ada,   g_ada);
    cudaGetSymbolAddress((void**)&p_b12p,  g_b12p);
    cudaGetSymbolAddress((void**)&p_hnb,   g_hnb);
    cudaGetSymbolAddress((void**)&p_qkb,   g_qkb);
    cudaGetSymbolAddress((void**)&p_attb,  g_attb);
    cudaGetSymbolAddress((void**)&p_gateb, g_gateb);
    cudaGetSymbolAddress((void**)&p_wqkv,  g_wqkv);
    cudaGetSymbolAddress((void**)&p_wproj, g_wproj);
    cudaGetSymbolAddress((void**)&p_w12c,  g_w12c);
    cudaGetSymbolAddress((void**)&p_woc,   g_woc);

    const int gemm_smem  = 3*STG_W*4;         // 110592 B
    const int attn_smem  = 3*128*QSTR*4;      // 55296 B
    const int gnrms_smem = (32*HSTR + 32)*4;  // 65792 B
    cudaFuncSetAttribute(k_gemm<5,1536,512>, cudaFuncAttributeMaxDynamicSharedMemorySize, gemm_smem);
    cudaFuncSetAttribute(k_gemm<2,512,512>,  cudaFuncAttributeMaxDynamicSharedMemorySize, gemm_smem);
    cudaFuncSetAttribute(k_gemm<3,4096,512>, cudaFuncAttributeMaxDynamicSharedMemorySize, gemm_smem);
    cudaFuncSetAttribute(k_gemm<4,512,2048>, cudaFuncAttributeMaxDynamicSharedMemorySize, gemm_smem);
    cudaFuncSetAttribute(k_attn_mma, cudaFuncAttributeMaxDynamicSharedMemorySize, attn_smem);
    cudaFuncSetAttribute(k_gnrms,    cudaFuncAttributeMaxDynamicSharedMemorySize, gnrms_smem);

    // single merged prologue: adaLN + GN stats + all weight conversion + rope table
    const int cvt_blocks = (1048576 + FFN + 512 + 255)/256;   // 4106
    k_prolog <<<704 + cvt_blocks, 256>>>(temb, ada_w, ada_b, x,
                                         qkv_w, proj_w, w_out, w12, b12);
    k_gnrms  <<<dim3(NTOK/32, BDIM), 512, gnrms_smem>>>(x, gn_w, gn_b, n1_w);

    // attention branch (QKV gemm with fused rope/rmsnorm/v-transpose epilogue)
    k_gemm<5,1536,512><<<dim3(1536/128, NT/128), 256, gemm_smem>>>(
        p_hnb, p_wqkv, qkv_b, nullptr, (uint32_t*)p_qkb, nullptr, p_ada,
        nullptr, nullptr, qn_w, kn_w, 0);
    k_attn_mma<<<dim3(BDIM*NHEADS, NTOK/128), 256, attn_smem>>>();
    k_gemm<2,512,512><<<dim3(512/128, NT/128), 256, gemm_smem>>>(
        p_attb, p_wproj, proj_b, p_h, nullptr, nullptr, p_ada,
        nullptr, nullptr, nullptr, nullptr, 2);

    // FFN branch
    k_rmsmod <<<NT, 128>>>(n2_w, 3, 4);
    k_gemm<3,4096,512><<<dim3(4096/128, NT/128), 256, gemm_smem>>>(
        p_hnb, p_w12c, p_b12p, nullptr, nullptr, p_gateb, p_ada,
        nullptr, nullptr, nullptr, nullptr, 0);
    k_gemm<4,512,2048><<<dim3(512/128, NT/128), 256, gemm_smem>>>(
        p_gateb, p_woc, b_out, p_h, nullptr, nullptr, p_ada,
        x, out, nullptr, nullptr, 5);
}